// round 3
// baseline (speedup 1.0000x reference)
#include <cuda_runtime.h>
#include <math.h>

// ---------------- problem constants ----------------
#define Bx   2
#define Sx   2048
#define Dx   2048
#define Hx   16
#define HDx  128
#define Ex   4
#define Ix   2048
#define Tx   (Bx * Sx)          // 4096 tokens

// ---------------- scratch (static device globals; no runtime alloc) ----------------
__device__ float g_x1  [(size_t)Tx * Dx];   // LN1 output
__device__ float g_q   [(size_t)Tx * Dx];
__device__ float g_k   [(size_t)Tx * Dx];
__device__ float g_v   [(size_t)Tx * Dx];
__device__ float g_attn[(size_t)Tx * Dx];
__device__ float g_x2  [(size_t)Tx * Dx];   // LN2 output
__device__ float g_hmid[(size_t)Tx * Ix];   // expert mid activations (reused per expert)
__device__ float g_comb[Tx * Ex];           // dense combine weights

// ---------------- LayerNorm: one block (256 thr) per row of 2048 ----------------
__global__ __launch_bounds__(256) void ln_kernel(
    const float* __restrict__ x, const float* __restrict__ w,
    const float* __restrict__ b, float* __restrict__ y)
{
    __shared__ float red[8];
    int row = blockIdx.x;
    int t = threadIdx.x;
    const float* xr = x + (size_t)row * Dx;

    float v[8];
    float s = 0.f;
#pragma unroll
    for (int i = 0; i < 8; i++) { v[i] = xr[t + i * 256]; s += v[i]; }
#pragma unroll
    for (int off = 16; off >= 1; off >>= 1) s += __shfl_xor_sync(0xffffffffu, s, off);
    if ((t & 31) == 0) red[t >> 5] = s;
    __syncthreads();
    float tot = red[0] + red[1] + red[2] + red[3] + red[4] + red[5] + red[6] + red[7];
    float mu = tot * (1.0f / (float)Dx);

    float s2 = 0.f;
#pragma unroll
    for (int i = 0; i < 8; i++) { float d = v[i] - mu; s2 += d * d; }
    __syncthreads();
#pragma unroll
    for (int off = 16; off >= 1; off >>= 1) s2 += __shfl_xor_sync(0xffffffffu, s2, off);
    if ((t & 31) == 0) red[t >> 5] = s2;
    __syncthreads();
    float tot2 = red[0] + red[1] + red[2] + red[3] + red[4] + red[5] + red[6] + red[7];
    float var = tot2 * (1.0f / (float)Dx);
    float r = rsqrtf(var + 1e-5f);

    float* yr = y + (size_t)row * Dx;
#pragma unroll
    for (int i = 0; i < 8; i++) {
        int c = t + i * 256;
        yr[c] = (v[i] - mu) * r * w[c] + b[c];
    }
}

// ---------------- tiled fp32 GEMM: C[M,N] = A[M,K] @ B[K,N] (+epilogue) ----------------
// MODE 0: C = AB + bias
// MODE 1: C = AB + bias + extra   (extra is [M,N] residual)
// MODE 2: C = gelu_exact(AB + bias)
// MODE 3: C += extra[m*4] * (AB + bias)   (extra = comb + e, row stride Ex=4)
#define BM 128
#define BN 128
#define BK 16

template <int MODE>
__global__ __launch_bounds__(256, 2) void gemm_k(
    const float* __restrict__ A, const float* __restrict__ B,
    const float* __restrict__ bias, float* __restrict__ C,
    const float* __restrict__ extra, int M, int N, int K)
{
    __shared__ float As[BK][BM];
    __shared__ float Bs[BK][BN];

    const int tid = threadIdx.x;
    const int tx = tid & 15;
    const int ty = tid >> 4;
    const int m0 = blockIdx.y * BM;
    const int n0 = blockIdx.x * BN;

    float acc[8][8];
#pragma unroll
    for (int i = 0; i < 8; i++)
#pragma unroll
        for (int j = 0; j < 8; j++) acc[i][j] = 0.f;

    // A loader: 512 float4 per tile; thread handles f = tid, tid+256
    const int arow = tid >> 2;            // 0..63
    const int akq  = (tid & 3) * 4;       // k offset within tile
    // B loader: krow = f>>5, nc = (f&31)*4
    const int bkr = tid >> 5;             // 0..7
    const int bnc = (tid & 31) * 4;

    const float* Ap = A + (size_t)m0 * K;
    const float* Bp = B + n0;

    for (int k0 = 0; k0 < K; k0 += BK) {
#pragma unroll
        for (int u = 0; u < 2; u++) {
            int row = arow + u * 64;
            float4 av = *(const float4*)(Ap + (size_t)row * K + k0 + akq);
            As[akq + 0][row] = av.x;
            As[akq + 1][row] = av.y;
            As[akq + 2][row] = av.z;
            As[akq + 3][row] = av.w;
        }
#pragma unroll
        for (int u = 0; u < 2; u++) {
            int kr = bkr + u * 8;
            float4 bv = *(const float4*)(Bp + (size_t)(k0 + kr) * N + bnc);
            *(float4*)&Bs[kr][bnc] = bv;
        }
        __syncthreads();

#pragma unroll
        for (int kk = 0; kk < BK; kk++) {
            float4 a0 = *(const float4*)&As[kk][ty * 8];
            float4 a1 = *(const float4*)&As[kk][ty * 8 + 4];
            float4 b0 = *(const float4*)&Bs[kk][tx * 8];
            float4 b1 = *(const float4*)&Bs[kk][tx * 8 + 4];
            float a[8] = {a0.x, a0.y, a0.z, a0.w, a1.x, a1.y, a1.z, a1.w};
            float b[8] = {b0.x, b0.y, b0.z, b0.w, b1.x, b1.y, b1.z, b1.w};
#pragma unroll
            for (int i = 0; i < 8; i++)
#pragma unroll
                for (int j = 0; j < 8; j++)
                    acc[i][j] = fmaf(a[i], b[j], acc[i][j]);
        }
        __syncthreads();
    }

#pragma unroll
    for (int i = 0; i < 8; i++) {
        int gm = m0 + ty * 8 + i;
        float* crow = C + (size_t)gm * N + n0 + tx * 8;
        float scale = 0.f;
        if (MODE == 3) scale = extra[(size_t)gm * Ex];
#pragma unroll
        for (int j = 0; j < 8; j++) {
            int gn = n0 + tx * 8 + j;
            float val = acc[i][j] + bias[gn];
            if (MODE == 1) val += extra[(size_t)gm * N + gn];
            if (MODE == 2) val = 0.5f * val * (1.0f + erff(val * 0.70710678118654752f));
            if (MODE == 3) crow[j] += scale * val;
            else           crow[j] = val;
        }
    }
}

// ---------------- RoPE over q and k in-place ----------------
__global__ __launch_bounds__(256) void rope_kernel(float* __restrict__ q, float* __restrict__ k)
{
    int idx = blockIdx.x * 256 + threadIdx.x;          // Tx*Hx*64
    int d = idx & 63;
    int rest = idx >> 6;
    int h = rest & (Hx - 1);
    int tok = rest >> 4;
    int s = tok & (Sx - 1);

    // inv_freq = 10000^(-d/64)
    float freq = expf(-(float)d * (9.21034037197618f / 64.0f));
    float ang = (float)s * freq;
    float c, sn;
    sincosf(ang, &sn, &c);

    size_t base = (size_t)tok * Dx + h * HDx;
    float q1 = q[base + d], q2 = q[base + d + 64];
    q[base + d]      = q1 * c - q2 * sn;
    q[base + d + 64] = q2 * c + q1 * sn;
    float k1 = k[base + d], k2 = k[base + d + 64];
    k[base + d]      = k1 * c - k2 * sn;
    k[base + d + 64] = k2 * c + k1 * sn;
}

// ---------------- causal attention: one warp per query row, online softmax ----------------
__global__ __launch_bounds__(256) void attn_kernel(
    const float* __restrict__ q, const float* __restrict__ k,
    const float* __restrict__ v, float* __restrict__ o)
{
    int bh = blockIdx.x;                 // b*H + h
    int b = bh >> 4;
    int h = bh & (Hx - 1);
    int warp = threadIdx.x >> 5;
    int lane = threadIdx.x & 31;
    int qi = blockIdx.y * 8 + warp;

    size_t qoff = ((size_t)(b * Sx + qi)) * Dx + h * HDx + lane * 4;
    float4 q4 = *(const float4*)(q + qoff);
    const float scale = 0.0883883476483184f;   // 1/sqrt(128)
    q4.x *= scale; q4.y *= scale; q4.z *= scale; q4.w *= scale;

    const float* kb = k + ((size_t)b * Sx) * Dx + h * HDx + lane * 4;
    const float* vb = v + ((size_t)b * Sx) * Dx + h * HDx + lane * 4;

    float m = -1e30f, l = 0.f;
    float4 acc = make_float4(0.f, 0.f, 0.f, 0.f);

    for (int j = 0; j <= qi; j++) {
        float4 k4 = *(const float4*)(kb + (size_t)j * Dx);
        float s = q4.x * k4.x + q4.y * k4.y + q4.z * k4.z + q4.w * k4.w;
        s += __shfl_xor_sync(0xffffffffu, s, 16);
        s += __shfl_xor_sync(0xffffffffu, s, 8);
        s += __shfl_xor_sync(0xffffffffu, s, 4);
        s += __shfl_xor_sync(0xffffffffu, s, 2);
        s += __shfl_xor_sync(0xffffffffu, s, 1);
        float4 v4 = *(const float4*)(vb + (size_t)j * Dx);
        float nm = fmaxf(m, s);
        float corr = __expf(m - nm);
        float p = __expf(s - nm);
        l = l * corr + p;
        acc.x = fmaf(acc.x, corr, p * v4.x);
        acc.y = fmaf(acc.y, corr, p * v4.y);
        acc.z = fmaf(acc.z, corr, p * v4.z);
        acc.w = fmaf(acc.w, corr, p * v4.w);
        m = nm;
    }
    float inv = __fdividef(1.0f, l);
    float4 outv = make_float4(acc.x * inv, acc.y * inv, acc.z * inv, acc.w * inv);
    *(float4*)(o + qoff) = outv;
}

// ---------------- MoE gate: softmax -> top-2 -> softmax(top vals) -> dense comb ----------------
__global__ __launch_bounds__(256) void gate_kernel(
    const float* __restrict__ x, const float* __restrict__ wg, float* __restrict__ comb)
{
    int warp = threadIdx.x >> 5;
    int lane = threadIdx.x & 31;
    int t = blockIdx.x * 8 + warp;
    const float* xr = x + (size_t)t * Dx;

    float a0 = 0.f, a1 = 0.f, a2 = 0.f, a3 = 0.f;
    for (int d = lane; d < Dx; d += 32) {
        float xv = xr[d];
        float4 w4 = ((const float4*)wg)[d];   // wg is [D,4] row-major
        a0 = fmaf(xv, w4.x, a0);
        a1 = fmaf(xv, w4.y, a1);
        a2 = fmaf(xv, w4.z, a2);
        a3 = fmaf(xv, w4.w, a3);
    }
#pragma unroll
    for (int off = 16; off >= 1; off >>= 1) {
        a0 += __shfl_xor_sync(0xffffffffu, a0, off);
        a1 += __shfl_xor_sync(0xffffffffu, a1, off);
        a2 += __shfl_xor_sync(0xffffffffu, a2, off);
        a3 += __shfl_xor_sync(0xffffffffu, a3, off);
    }
    if (lane == 0) {
        float lg[4] = {a0, a1, a2, a3};
        float mx = fmaxf(fmaxf(lg[0], lg[1]), fmaxf(lg[2], lg[3]));
        float e[4], sum = 0.f;
#pragma unroll
        for (int i = 0; i < 4; i++) { e[i] = expf(lg[i] - mx); sum += e[i]; }
        float p[4];
#pragma unroll
        for (int i = 0; i < 4; i++) p[i] = e[i] / sum;

        int i0 = 0;
#pragma unroll
        for (int i = 1; i < 4; i++) if (p[i] > p[i0]) i0 = i;
        int i1 = (i0 == 0) ? 1 : 0;
#pragma unroll
        for (int i = 0; i < 4; i++) if (i != i0 && p[i] > p[i1]) i1 = i;

        // renormalize: softmax over the two top probabilities
        float hi = fmaxf(p[i0], p[i1]);
        float ea = expf(p[i0] - hi), eb = expf(p[i1] - hi);
        float inv = 1.0f / (ea + eb);
        float w0 = ea * inv, w1 = eb * inv;
#pragma unroll
        for (int i = 0; i < 4; i++)
            comb[t * 4 + i] = (i == i0) ? w0 : ((i == i1) ? w1 : 0.f);
    }
}

// ---------------- host launcher ----------------
extern "C" void kernel_launch(void* const* d_in, const int* in_sizes, int n_in,
                              void* d_out, int out_size)
{
    const float* hidden = (const float*)d_in[0];
    const float* wq   = (const float*)d_in[1];
    const float* bq   = (const float*)d_in[2];
    const float* wk   = (const float*)d_in[3];
    const float* bk   = (const float*)d_in[4];
    const float* wv   = (const float*)d_in[5];
    const float* bv   = (const float*)d_in[6];
    const float* wo   = (const float*)d_in[7];
    const float* bo   = (const float*)d_in[8];
    const float* ln1w = (const float*)d_in[9];
    const float* ln1b = (const float*)d_in[10];
    const float* ln2w = (const float*)d_in[11];
    const float* ln2b = (const float*)d_in[12];
    const float* wgate= (const float*)d_in[13];
    const float* we1  = (const float*)d_in[14];
    const float* be1  = (const float*)d_in[15];
    const float* we2  = (const float*)d_in[16];
    const float* be2  = (const float*)d_in[17];
    float* out = (float*)d_out;

    float *x1, *q, *k, *v, *attn, *x2, *hmid, *comb;
    cudaGetSymbolAddress((void**)&x1,   g_x1);
    cudaGetSymbolAddress((void**)&q,    g_q);
    cudaGetSymbolAddress((void**)&k,    g_k);
    cudaGetSymbolAddress((void**)&v,    g_v);
    cudaGetSymbolAddress((void**)&attn, g_attn);
    cudaGetSymbolAddress((void**)&x2,   g_x2);
    cudaGetSymbolAddress((void**)&hmid, g_hmid);
    cudaGetSymbolAddress((void**)&comb, g_comb);

    dim3 gg(Dx / BN, Tx / BM);          // (16, 32)

    // 1) LN1
    ln_kernel<<<Tx, 256>>>(hidden, ln1w, ln1b, x1);
    // 2) QKV projections
    gemm_k<0><<<gg, 256>>>(x1, wq, bq, q, nullptr, Tx, Dx, Dx);
    gemm_k<0><<<gg, 256>>>(x1, wk, bk, k, nullptr, Tx, Dx, Dx);
    gemm_k<0><<<gg, 256>>>(x1, wv, bv, v, nullptr, Tx, Dx, Dx);
    // 3) RoPE in-place on q, k
    rope_kernel<<<(Tx * Hx * 64) / 256, 256>>>(q, k);
    // 4) causal attention
    attn_kernel<<<dim3(Bx * Hx, Sx / 8), 256>>>(q, k, v, attn);
    // 5) O-projection + residual  ->  d_out holds h = x + Attn(LN1(x))
    gemm_k<1><<<gg, 256>>>(attn, wo, bo, out, hidden, Tx, Dx, Dx);
    // 6) LN2
    ln_kernel<<<Tx, 256>>>(out, ln2w, ln2b, x2);
    // 7) gate -> dense combine weights
    gate_kernel<<<Tx / 8, 256>>>(x2, wgate, comb);
    // 8) dense per-expert MLPs, comb-weighted accumulate into d_out
    for (int e = 0; e < Ex; e++) {
        gemm_k<2><<<dim3(Ix / BN, Tx / BM), 256>>>(
            x2, we1 + (size_t)e * Dx * Ix, be1 + (size_t)e * Ix,
            hmid, nullptr, Tx, Ix, Dx);
        gemm_k<3><<<gg, 256>>>(
            hmid, we2 + (size_t)e * Ix * Dx, be2 + (size_t)e * Dx,
            out, comb + e, Tx, Dx, Ix);
    }
}

// round 4
// speedup vs baseline: 1.9921x; 1.9921x over previous
#include <cuda_runtime.h>
#include <math.h>
#include <stdint.h>

// ---------------- problem constants ----------------
#define Bx   2
#define Sx   2048
#define Dx   2048
#define Hx   16
#define HDx  128
#define Ex   4
#define Ix   2048
#define Tx   (Bx * Sx)          // 4096 tokens

// ---------------- scratch (static device globals; no runtime alloc) ----------------
__device__ float g_x1  [(size_t)Tx * Dx];   // LN1 output
__device__ float g_q   [(size_t)Tx * Dx];
__device__ float g_k   [(size_t)Tx * Dx];
__device__ float g_v   [(size_t)Tx * Dx];
__device__ float g_attn[(size_t)Tx * Dx];
__device__ float g_x2  [(size_t)Tx * Dx];   // LN2 output
__device__ float g_hmid[(size_t)Tx * Ix];   // expert mid activations (reused per expert)
__device__ float g_comb[Tx * Ex];           // dense combine weights

// ---------------- LayerNorm: one block (256 thr) per row of 2048 ----------------
__global__ __launch_bounds__(256) void ln_kernel(
    const float* __restrict__ x, const float* __restrict__ w,
    const float* __restrict__ b, float* __restrict__ y)
{
    __shared__ float red[8];
    int row = blockIdx.x;
    int t = threadIdx.x;
    const float* xr = x + (size_t)row * Dx;

    float v[8];
    float s = 0.f;
#pragma unroll
    for (int i = 0; i < 8; i++) { v[i] = xr[t + i * 256]; s += v[i]; }
#pragma unroll
    for (int off = 16; off >= 1; off >>= 1) s += __shfl_xor_sync(0xffffffffu, s, off);
    if ((t & 31) == 0) red[t >> 5] = s;
    __syncthreads();
    float tot = red[0] + red[1] + red[2] + red[3] + red[4] + red[5] + red[6] + red[7];
    float mu = tot * (1.0f / (float)Dx);

    float s2 = 0.f;
#pragma unroll
    for (int i = 0; i < 8; i++) { float d = v[i] - mu; s2 += d * d; }
    __syncthreads();
#pragma unroll
    for (int off = 16; off >= 1; off >>= 1) s2 += __shfl_xor_sync(0xffffffffu, s2, off);
    if ((t & 31) == 0) red[t >> 5] = s2;
    __syncthreads();
    float tot2 = red[0] + red[1] + red[2] + red[3] + red[4] + red[5] + red[6] + red[7];
    float var = tot2 * (1.0f / (float)Dx);
    float r = rsqrtf(var + 1e-5f);

    float* yr = y + (size_t)row * Dx;
#pragma unroll
    for (int i = 0; i < 8; i++) {
        int c = t + i * 256;
        yr[c] = (v[i] - mu) * r * w[c] + b[c];
    }
}

// ================= tensor-core tf32 GEMM =================
// C[M,N] = A[M,K] @ B[K,N] (+epilogue), both row-major fp32 in gmem.
// MODE 0: C = AB + bias
// MODE 1: C = AB + bias + extra   (extra is [M,N] residual)
// MODE 2: C = gelu_exact(AB + bias)
// MODE 3: C += extra[m*Ex] * (AB + bias)
#define BM 128
#define BN 128
#define BK 32
#define APAD 4      // A row stride 36 floats -> 4g+t lane pattern, conflict-free
#define BPAD 8      // B row stride 136 floats -> 8t+g lane pattern, conflict-free
#define ASZ (BM * (BK + APAD))   // floats per A buffer
#define BSZ (BK * (BN + BPAD))   // floats per B buffer
#define GEMM_SMEM_BYTES ((2 * ASZ + 2 * BSZ) * 4)   // 71680

__device__ __forceinline__ uint32_t f2tf32(float x) {
    uint32_t u;
    asm volatile("cvt.rna.tf32.f32 %0, %1;\n" : "=r"(u) : "f"(x));
    return u;
}

__device__ __forceinline__ void mma_tf32(float* d, const uint32_t* a, const uint32_t* b) {
    asm volatile(
        "mma.sync.aligned.m16n8k8.row.col.f32.tf32.tf32.f32 "
        "{%0,%1,%2,%3}, {%4,%5,%6,%7}, {%8,%9}, {%0,%1,%2,%3};\n"
        : "+f"(d[0]), "+f"(d[1]), "+f"(d[2]), "+f"(d[3])
        : "r"(a[0]), "r"(a[1]), "r"(a[2]), "r"(a[3]), "r"(b[0]), "r"(b[1]));
}

__device__ __forceinline__ void cp16(float* dst, const float* src) {
    uint32_t d = (uint32_t)__cvta_generic_to_shared(dst);
    asm volatile("cp.async.cg.shared.global [%0], [%1], 16;\n" :: "r"(d), "l"(src));
}

template <int MODE>
__global__ __launch_bounds__(256) void gemm_tc(
    const float* __restrict__ A, const float* __restrict__ B,
    const float* __restrict__ bias, float* __restrict__ C,
    const float* __restrict__ extra, int M, int N, int K)
{
    extern __shared__ float sm[];
    float* As0 = sm;                 // [2][BM][BK+APAD]
    float* Bs0 = sm + 2 * ASZ;       // [2][BK][BN+BPAD]

    const int tid  = threadIdx.x;
    const int lane = tid & 31;
    const int wid  = tid >> 5;
    const int g = lane >> 2;         // group id (0..7)
    const int t = lane & 3;          // thread-in-group (0..3)
    const int wm = wid >> 2;         // warp row (0..1), 64 rows each
    const int wn = wid & 3;          // warp col (0..3), 32 cols each
    const int m0 = blockIdx.y * BM;
    const int n0 = blockIdx.x * BN;

    float acc[4][4][4];
#pragma unroll
    for (int i = 0; i < 4; i++)
#pragma unroll
        for (int j = 0; j < 4; j++)
#pragma unroll
            for (int c = 0; c < 4; c++) acc[i][j][c] = 0.f;

    auto loadTile = [&](int k0, int buf) {
        float* Ad = As0 + buf * ASZ;
        float* Bd = Bs0 + buf * BSZ;
#pragma unroll
        for (int i = 0; i < 4; i++) {              // 1024 float4 for A
            int f = tid + i * 256;
            int row = f >> 3;
            int kq  = (f & 7) * 4;
            cp16(Ad + row * (BK + APAD) + kq,
                 A + (size_t)(m0 + row) * K + k0 + kq);
        }
#pragma unroll
        for (int i = 0; i < 4; i++) {              // 1024 float4 for B
            int f = tid + i * 256;
            int kr = f >> 5;
            int nc = (f & 31) * 4;
            cp16(Bd + kr * (BN + BPAD) + nc,
                 B + (size_t)(k0 + kr) * N + n0 + nc);
        }
        asm volatile("cp.async.commit_group;\n");
    };

    const int ntiles = K / BK;
    loadTile(0, 0);

    for (int tile = 0; tile < ntiles; tile++) {
        int buf = tile & 1;
        if (tile + 1 < ntiles) {
            loadTile((tile + 1) * BK, buf ^ 1);
            asm volatile("cp.async.wait_group 1;\n");
        } else {
            asm volatile("cp.async.wait_group 0;\n");
        }
        __syncthreads();

        const float* Ab = As0 + buf * ASZ;
        const float* Bb = Bs0 + buf * BSZ;

#pragma unroll
        for (int kk = 0; kk < BK / 8; kk++) {
            const int k = kk * 8;
            uint32_t af[4][4];
            uint32_t bf[4][2];
#pragma unroll
            for (int mi = 0; mi < 4; mi++) {
                int r = wm * 64 + mi * 16 + g;
                const float* ar0 = Ab + (size_t)r * (BK + APAD) + k;
                const float* ar1 = ar0 + 8 * (BK + APAD);
                af[mi][0] = f2tf32(ar0[t]);
                af[mi][1] = f2tf32(ar1[t]);
                af[mi][2] = f2tf32(ar0[t + 4]);
                af[mi][3] = f2tf32(ar1[t + 4]);
            }
#pragma unroll
            for (int ni = 0; ni < 4; ni++) {
                int c = wn * 32 + ni * 8 + g;
                bf[ni][0] = f2tf32(Bb[(size_t)(k + t) * (BN + BPAD) + c]);
                bf[ni][1] = f2tf32(Bb[(size_t)(k + t + 4) * (BN + BPAD) + c]);
            }
#pragma unroll
            for (int mi = 0; mi < 4; mi++)
#pragma unroll
                for (int ni = 0; ni < 4; ni++)
                    mma_tf32(acc[mi][ni], af[mi], bf[ni]);
        }
        __syncthreads();
    }

    // ---------------- epilogue ----------------
#pragma unroll
    for (int mi = 0; mi < 4; mi++) {
        int r0 = m0 + wm * 64 + mi * 16 + g;
        int r1 = r0 + 8;
        float s0 = 0.f, s1 = 0.f;
        if (MODE == 3) {
            s0 = extra[(size_t)r0 * Ex];
            s1 = extra[(size_t)r1 * Ex];
        }
#pragma unroll
        for (int ni = 0; ni < 4; ni++) {
            int c = n0 + wn * 32 + ni * 8 + t * 2;
            float v00 = acc[mi][ni][0] + bias[c];
            float v01 = acc[mi][ni][1] + bias[c + 1];
            float v10 = acc[mi][ni][2] + bias[c];
            float v11 = acc[mi][ni][3] + bias[c + 1];
            if (MODE == 1) {
                v00 += extra[(size_t)r0 * N + c];
                v01 += extra[(size_t)r0 * N + c + 1];
                v10 += extra[(size_t)r1 * N + c];
                v11 += extra[(size_t)r1 * N + c + 1];
            }
            if (MODE == 2) {
                v00 = 0.5f * v00 * (1.0f + erff(v00 * 0.70710678118654752f));
                v01 = 0.5f * v01 * (1.0f + erff(v01 * 0.70710678118654752f));
                v10 = 0.5f * v10 * (1.0f + erff(v10 * 0.70710678118654752f));
                v11 = 0.5f * v11 * (1.0f + erff(v11 * 0.70710678118654752f));
            }
            if (MODE == 3) {
                C[(size_t)r0 * N + c]     += s0 * v00;
                C[(size_t)r0 * N + c + 1] += s0 * v01;
                C[(size_t)r1 * N + c]     += s1 * v10;
                C[(size_t)r1 * N + c + 1] += s1 * v11;
            } else {
                C[(size_t)r0 * N + c]     = v00;
                C[(size_t)r0 * N + c + 1] = v01;
                C[(size_t)r1 * N + c]     = v10;
                C[(size_t)r1 * N + c + 1] = v11;
            }
        }
    }
}

// ---------------- RoPE over q and k in-place ----------------
__global__ __launch_bounds__(256) void rope_kernel(float* __restrict__ q, float* __restrict__ k)
{
    int idx = blockIdx.x * 256 + threadIdx.x;          // Tx*Hx*64
    int d = idx & 63;
    int rest = idx >> 6;
    int h = rest & (Hx - 1);
    int tok = rest >> 4;
    int s = tok & (Sx - 1);

    float freq = expf(-(float)d * (9.21034037197618f / 64.0f));
    float ang = (float)s * freq;
    float c, sn;
    sincosf(ang, &sn, &c);

    size_t base = (size_t)tok * Dx + h * HDx;
    float q1 = q[base + d], q2 = q[base + d + 64];
    q[base + d]      = q1 * c - q2 * sn;
    q[base + d + 64] = q2 * c + q1 * sn;
    float k1 = k[base + d], k2 = k[base + d + 64];
    k[base + d]      = k1 * c - k2 * sn;
    k[base + d + 64] = k2 * c + k1 * sn;
}

// ---------------- causal attention: one warp per query row, online softmax ----------------
__global__ __launch_bounds__(256) void attn_kernel(
    const float* __restrict__ q, const float* __restrict__ k,
    const float* __restrict__ v, float* __restrict__ o)
{
    int bh = blockIdx.x;                 // b*H + h
    int b = bh >> 4;
    int h = bh & (Hx - 1);
    int warp = threadIdx.x >> 5;
    int lane = threadIdx.x & 31;
    int qi = blockIdx.y * 8 + warp;

    size_t qoff = ((size_t)(b * Sx + qi)) * Dx + h * HDx + lane * 4;
    float4 q4 = *(const float4*)(q + qoff);
    const float scale = 0.0883883476483184f;   // 1/sqrt(128)
    q4.x *= scale; q4.y *= scale; q4.z *= scale; q4.w *= scale;

    const float* kb = k + ((size_t)b * Sx) * Dx + h * HDx + lane * 4;
    const float* vb = v + ((size_t)b * Sx) * Dx + h * HDx + lane * 4;

    float m = -1e30f, l = 0.f;
    float4 acc = make_float4(0.f, 0.f, 0.f, 0.f);

    for (int j = 0; j <= qi; j++) {
        float4 k4 = *(const float4*)(kb + (size_t)j * Dx);
        float s = q4.x * k4.x + q4.y * k4.y + q4.z * k4.z + q4.w * k4.w;
        s += __shfl_xor_sync(0xffffffffu, s, 16);
        s += __shfl_xor_sync(0xffffffffu, s, 8);
        s += __shfl_xor_sync(0xffffffffu, s, 4);
        s += __shfl_xor_sync(0xffffffffu, s, 2);
        s += __shfl_xor_sync(0xffffffffu, s, 1);
        float4 v4 = *(const float4*)(vb + (size_t)j * Dx);
        float nm = fmaxf(m, s);
        float corr = __expf(m - nm);
        float p = __expf(s - nm);
        l = l * corr + p;
        acc.x = fmaf(acc.x, corr, p * v4.x);
        acc.y = fmaf(acc.y, corr, p * v4.y);
        acc.z = fmaf(acc.z, corr, p * v4.z);
        acc.w = fmaf(acc.w, corr, p * v4.w);
        m = nm;
    }
    float inv = __fdividef(1.0f, l);
    float4 outv = make_float4(acc.x * inv, acc.y * inv, acc.z * inv, acc.w * inv);
    *(float4*)(o + qoff) = outv;
}

// ---------------- MoE gate: softmax -> top-2 -> softmax(top vals) -> dense comb ----------------
__global__ __launch_bounds__(256) void gate_kernel(
    const float* __restrict__ x, const float* __restrict__ wg, float* __restrict__ comb)
{
    int warp = threadIdx.x >> 5;
    int lane = threadIdx.x & 31;
    int t = blockIdx.x * 8 + warp;
    const float* xr = x + (size_t)t * Dx;

    float a0 = 0.f, a1 = 0.f, a2 = 0.f, a3 = 0.f;
    for (int d = lane; d < Dx; d += 32) {
        float xv = xr[d];
        float4 w4 = ((const float4*)wg)[d];   // wg is [D,4] row-major
        a0 = fmaf(xv, w4.x, a0);
        a1 = fmaf(xv, w4.y, a1);
        a2 = fmaf(xv, w4.z, a2);
        a3 = fmaf(xv, w4.w, a3);
    }
#pragma unroll
    for (int off = 16; off >= 1; off >>= 1) {
        a0 += __shfl_xor_sync(0xffffffffu, a0, off);
        a1 += __shfl_xor_sync(0xffffffffu, a1, off);
        a2 += __shfl_xor_sync(0xffffffffu, a2, off);
        a3 += __shfl_xor_sync(0xffffffffu, a3, off);
    }
    if (lane == 0) {
        float lg[4] = {a0, a1, a2, a3};
        float mx = fmaxf(fmaxf(lg[0], lg[1]), fmaxf(lg[2], lg[3]));
        float e[4], sum = 0.f;
#pragma unroll
        for (int i = 0; i < 4; i++) { e[i] = expf(lg[i] - mx); sum += e[i]; }
        float p[4];
#pragma unroll
        for (int i = 0; i < 4; i++) p[i] = e[i] / sum;

        int i0 = 0;
#pragma unroll
        for (int i = 1; i < 4; i++) if (p[i] > p[i0]) i0 = i;
        int i1 = (i0 == 0) ? 1 : 0;
#pragma unroll
        for (int i = 0; i < 4; i++) if (i != i0 && p[i] > p[i1]) i1 = i;

        float hi = fmaxf(p[i0], p[i1]);
        float ea = expf(p[i0] - hi), eb = expf(p[i1] - hi);
        float inv = 1.0f / (ea + eb);
        float w0 = ea * inv, w1 = eb * inv;
#pragma unroll
        for (int i = 0; i < 4; i++)
            comb[t * 4 + i] = (i == i0) ? w0 : ((i == i1) ? w1 : 0.f);
    }
}

// ---------------- host launcher ----------------
extern "C" void kernel_launch(void* const* d_in, const int* in_sizes, int n_in,
                              void* d_out, int out_size)
{
    const float* hidden = (const float*)d_in[0];
    const float* wq   = (const float*)d_in[1];
    const float* bq   = (const float*)d_in[2];
    const float* wk   = (const float*)d_in[3];
    const float* bk   = (const float*)d_in[4];
    const float* wv   = (const float*)d_in[5];
    const float* bv   = (const float*)d_in[6];
    const float* wo   = (const float*)d_in[7];
    const float* bo   = (const float*)d_in[8];
    const float* ln1w = (const float*)d_in[9];
    const float* ln1b = (const float*)d_in[10];
    const float* ln2w = (const float*)d_in[11];
    const float* ln2b = (const float*)d_in[12];
    const float* wgate= (const float*)d_in[13];
    const float* we1  = (const float*)d_in[14];
    const float* be1  = (const float*)d_in[15];
    const float* we2  = (const float*)d_in[16];
    const float* be2  = (const float*)d_in[17];
    float* out = (float*)d_out;

    float *x1, *q, *k, *v, *attn, *x2, *hmid, *comb;
    cudaGetSymbolAddress((void**)&x1,   g_x1);
    cudaGetSymbolAddress((void**)&q,    g_q);
    cudaGetSymbolAddress((void**)&k,    g_k);
    cudaGetSymbolAddress((void**)&v,    g_v);
    cudaGetSymbolAddress((void**)&attn, g_attn);
    cudaGetSymbolAddress((void**)&x2,   g_x2);
    cudaGetSymbolAddress((void**)&hmid, g_hmid);
    cudaGetSymbolAddress((void**)&comb, g_comb);

    cudaFuncSetAttribute(gemm_tc<0>, cudaFuncAttributeMaxDynamicSharedMemorySize, GEMM_SMEM_BYTES);
    cudaFuncSetAttribute(gemm_tc<1>, cudaFuncAttributeMaxDynamicSharedMemorySize, GEMM_SMEM_BYTES);
    cudaFuncSetAttribute(gemm_tc<2>, cudaFuncAttributeMaxDynamicSharedMemorySize, GEMM_SMEM_BYTES);
    cudaFuncSetAttribute(gemm_tc<3>, cudaFuncAttributeMaxDynamicSharedMemorySize, GEMM_SMEM_BYTES);

    dim3 gg(Dx / BN, Tx / BM);          // (16, 32)

    // 1) LN1
    ln_kernel<<<Tx, 256>>>(hidden, ln1w, ln1b, x1);
    // 2) QKV projections (tensor cores, tf32)
    gemm_tc<0><<<gg, 256, GEMM_SMEM_BYTES>>>(x1, wq, bq, q, nullptr, Tx, Dx, Dx);
    gemm_tc<0><<<gg, 256, GEMM_SMEM_BYTES>>>(x1, wk, bk, k, nullptr, Tx, Dx, Dx);
    gemm_tc<0><<<gg, 256, GEMM_SMEM_BYTES>>>(x1, wv, bv, v, nullptr, Tx, Dx, Dx);
    // 3) RoPE in-place on q, k
    rope_kernel<<<(Tx * Hx * 64) / 256, 256>>>(q, k);
    // 4) causal attention
    attn_kernel<<<dim3(Bx * Hx, Sx / 8), 256>>>(q, k, v, attn);
    // 5) O-projection + residual  ->  d_out holds h = x + Attn(LN1(x))
    gemm_tc<1><<<gg, 256, GEMM_SMEM_BYTES>>>(attn, wo, bo, out, hidden, Tx, Dx, Dx);
    // 6) LN2
    ln_kernel<<<Tx, 256>>>(out, ln2w, ln2b, x2);
    // 7) gate -> dense combine weights
    gate_kernel<<<Tx / 8, 256>>>(x2, wgate, comb);
    // 8) dense per-expert MLPs, comb-weighted accumulate into d_out
    for (int e = 0; e < Ex; e++) {
        gemm_tc<2><<<dim3(Ix / BN, Tx / BM), 256, GEMM_SMEM_BYTES>>>(
            x2, we1 + (size_t)e * Dx * Ix, be1 + (size_t)e * Ix,
            hmid, nullptr, Tx, Ix, Dx);
        gemm_tc<3><<<gg, 256, GEMM_SMEM_BYTES>>>(
            hmid, we2 + (size_t)e * Ix * Dx, be2 + (size_t)e * Dx,
            out, comb + e, Tx, Dx, Ix);
    }
}

// round 5
// speedup vs baseline: 4.0994x; 2.0578x over previous
#include <cuda_runtime.h>
#include <math.h>
#include <stdint.h>

// ---------------- problem constants ----------------
#define Bx   2
#define Sx   2048
#define Dx   2048
#define Hx   16
#define HDx  128
#define Ex   4
#define Ix   2048
#define Tx   (Bx * Sx)          // 4096 tokens

// ---------------- scratch (static device globals; no runtime alloc) ----------------
__device__ float g_x1  [(size_t)Tx * Dx];   // LN1 output
__device__ float g_q   [(size_t)Tx * Dx];
__device__ float g_k   [(size_t)Tx * Dx];
__device__ float g_v   [(size_t)Tx * Dx];
__device__ float g_attn[(size_t)Tx * Dx];
__device__ float g_x2  [(size_t)Tx * Dx];   // LN2 output
__device__ float g_hmid[(size_t)Tx * Ix];   // expert mid activations (reused per expert)
__device__ float g_comb[Tx * Ex];           // dense combine weights

__device__ __forceinline__ uint32_t f2tf32(float x) {
    uint32_t u;
    asm volatile("cvt.rna.tf32.f32 %0, %1;\n" : "=r"(u) : "f"(x));
    return u;
}

__device__ __forceinline__ void mma_tf32(float* d, const uint32_t* a, const uint32_t* b) {
    asm volatile(
        "mma.sync.aligned.m16n8k8.row.col.f32.tf32.tf32.f32 "
        "{%0,%1,%2,%3}, {%4,%5,%6,%7}, {%8,%9}, {%0,%1,%2,%3};\n"
        : "+f"(d[0]), "+f"(d[1]), "+f"(d[2]), "+f"(d[3])
        : "r"(a[0]), "r"(a[1]), "r"(a[2]), "r"(a[3]), "r"(b[0]), "r"(b[1]));
}

__device__ __forceinline__ void cp16(float* dst, const float* src) {
    uint32_t d = (uint32_t)__cvta_generic_to_shared(dst);
    asm volatile("cp.async.cg.shared.global [%0], [%1], 16;\n" :: "r"(d), "l"(src));
}

// ---------------- LayerNorm: one block (256 thr) per row of 2048 ----------------
__global__ __launch_bounds__(256) void ln_kernel(
    const float* __restrict__ x, const float* __restrict__ w,
    const float* __restrict__ b, float* __restrict__ y)
{
    __shared__ float red[8];
    int row = blockIdx.x;
    int t = threadIdx.x;
    const float* xr = x + (size_t)row * Dx;

    float v[8];
    float s = 0.f;
#pragma unroll
    for (int i = 0; i < 8; i++) { v[i] = xr[t + i * 256]; s += v[i]; }
#pragma unroll
    for (int off = 16; off >= 1; off >>= 1) s += __shfl_xor_sync(0xffffffffu, s, off);
    if ((t & 31) == 0) red[t >> 5] = s;
    __syncthreads();
    float tot = red[0] + red[1] + red[2] + red[3] + red[4] + red[5] + red[6] + red[7];
    float mu = tot * (1.0f / (float)Dx);

    float s2 = 0.f;
#pragma unroll
    for (int i = 0; i < 8; i++) { float d = v[i] - mu; s2 += d * d; }
    __syncthreads();
#pragma unroll
    for (int off = 16; off >= 1; off >>= 1) s2 += __shfl_xor_sync(0xffffffffu, s2, off);
    if ((t & 31) == 0) red[t >> 5] = s2;
    __syncthreads();
    float tot2 = red[0] + red[1] + red[2] + red[3] + red[4] + red[5] + red[6] + red[7];
    float var = tot2 * (1.0f / (float)Dx);
    float r = rsqrtf(var + 1e-5f);

    float* yr = y + (size_t)row * Dx;
#pragma unroll
    for (int i = 0; i < 8; i++) {
        int c = t + i * 256;
        yr[c] = (v[i] - mu) * r * w[c] + b[c];
    }
}

// ================= tensor-core tf32 GEMM =================
#define BM 128
#define BN 128
#define BK 32
#define APAD 4
#define BPAD 8
#define ASZ (BM * (BK + APAD))
#define BSZ (BK * (BN + BPAD))
#define GEMM_SMEM_BYTES ((2 * ASZ + 2 * BSZ) * 4)   // 71680

template <int MODE>
__global__ __launch_bounds__(256) void gemm_tc(
    const float* __restrict__ A, const float* __restrict__ B,
    const float* __restrict__ bias, float* __restrict__ C,
    const float* __restrict__ extra, int M, int N, int K)
{
    extern __shared__ float sm[];
    float* As0 = sm;
    float* Bs0 = sm + 2 * ASZ;

    const int tid  = threadIdx.x;
    const int lane = tid & 31;
    const int wid  = tid >> 5;
    const int g = lane >> 2;
    const int t = lane & 3;
    const int wm = wid >> 2;
    const int wn = wid & 3;
    const int m0 = blockIdx.y * BM;
    const int n0 = blockIdx.x * BN;

    float acc[4][4][4];
#pragma unroll
    for (int i = 0; i < 4; i++)
#pragma unroll
        for (int j = 0; j < 4; j++)
#pragma unroll
            for (int c = 0; c < 4; c++) acc[i][j][c] = 0.f;

    auto loadTile = [&](int k0, int buf) {
        float* Ad = As0 + buf * ASZ;
        float* Bd = Bs0 + buf * BSZ;
#pragma unroll
        for (int i = 0; i < 4; i++) {
            int f = tid + i * 256;
            int row = f >> 3;
            int kq  = (f & 7) * 4;
            cp16(Ad + row * (BK + APAD) + kq,
                 A + (size_t)(m0 + row) * K + k0 + kq);
        }
#pragma unroll
        for (int i = 0; i < 4; i++) {
            int f = tid + i * 256;
            int kr = f >> 5;
            int nc = (f & 31) * 4;
            cp16(Bd + kr * (BN + BPAD) + nc,
                 B + (size_t)(k0 + kr) * N + n0 + nc);
        }
        asm volatile("cp.async.commit_group;\n");
    };

    const int ntiles = K / BK;
    loadTile(0, 0);

    for (int tile = 0; tile < ntiles; tile++) {
        int buf = tile & 1;
        if (tile + 1 < ntiles) {
            loadTile((tile + 1) * BK, buf ^ 1);
            asm volatile("cp.async.wait_group 1;\n");
        } else {
            asm volatile("cp.async.wait_group 0;\n");
        }
        __syncthreads();

        const float* Ab = As0 + buf * ASZ;
        const float* Bb = Bs0 + buf * BSZ;

#pragma unroll
        for (int kk = 0; kk < BK / 8; kk++) {
            const int k = kk * 8;
            uint32_t af[4][4];
            uint32_t bf[4][2];
#pragma unroll
            for (int mi = 0; mi < 4; mi++) {
                int r = wm * 64 + mi * 16 + g;
                const float* ar0 = Ab + (size_t)r * (BK + APAD) + k;
                const float* ar1 = ar0 + 8 * (BK + APAD);
                af[mi][0] = f2tf32(ar0[t]);
                af[mi][1] = f2tf32(ar1[t]);
                af[mi][2] = f2tf32(ar0[t + 4]);
                af[mi][3] = f2tf32(ar1[t + 4]);
            }
#pragma unroll
            for (int ni = 0; ni < 4; ni++) {
                int c = wn * 32 + ni * 8 + g;
                bf[ni][0] = f2tf32(Bb[(size_t)(k + t) * (BN + BPAD) + c]);
                bf[ni][1] = f2tf32(Bb[(size_t)(k + t + 4) * (BN + BPAD) + c]);
            }
#pragma unroll
            for (int mi = 0; mi < 4; mi++)
#pragma unroll
                for (int ni = 0; ni < 4; ni++)
                    mma_tf32(acc[mi][ni], af[mi], bf[ni]);
        }
        __syncthreads();
    }

#pragma unroll
    for (int mi = 0; mi < 4; mi++) {
        int r0 = m0 + wm * 64 + mi * 16 + g;
        int r1 = r0 + 8;
        float s0 = 0.f, s1 = 0.f;
        if (MODE == 3) {
            s0 = extra[(size_t)r0 * Ex];
            s1 = extra[(size_t)r1 * Ex];
        }
#pragma unroll
        for (int ni = 0; ni < 4; ni++) {
            int c = n0 + wn * 32 + ni * 8 + t * 2;
            float v00 = acc[mi][ni][0] + bias[c];
            float v01 = acc[mi][ni][1] + bias[c + 1];
            float v10 = acc[mi][ni][2] + bias[c];
            float v11 = acc[mi][ni][3] + bias[c + 1];
            if (MODE == 1) {
                v00 += extra[(size_t)r0 * N + c];
                v01 += extra[(size_t)r0 * N + c + 1];
                v10 += extra[(size_t)r1 * N + c];
                v11 += extra[(size_t)r1 * N + c + 1];
            }
            if (MODE == 2) {
                v00 = 0.5f * v00 * (1.0f + erff(v00 * 0.70710678118654752f));
                v01 = 0.5f * v01 * (1.0f + erff(v01 * 0.70710678118654752f));
                v10 = 0.5f * v10 * (1.0f + erff(v10 * 0.70710678118654752f));
                v11 = 0.5f * v11 * (1.0f + erff(v11 * 0.70710678118654752f));
            }
            if (MODE == 3) {
                C[(size_t)r0 * N + c]     += s0 * v00;
                C[(size_t)r0 * N + c + 1] += s0 * v01;
                C[(size_t)r1 * N + c]     += s1 * v10;
                C[(size_t)r1 * N + c + 1] += s1 * v11;
            } else {
                C[(size_t)r0 * N + c]     = v00;
                C[(size_t)r0 * N + c + 1] = v01;
                C[(size_t)r1 * N + c]     = v10;
                C[(size_t)r1 * N + c + 1] = v11;
            }
        }
    }
}

// ---------------- RoPE over q and k in-place ----------------
__global__ __launch_bounds__(256) void rope_kernel(float* __restrict__ q, float* __restrict__ k)
{
    int idx = blockIdx.x * 256 + threadIdx.x;
    int d = idx & 63;
    int rest = idx >> 6;
    int h = rest & (Hx - 1);
    int tok = rest >> 4;
    int s = tok & (Sx - 1);

    float freq = expf(-(float)d * (9.21034037197618f / 64.0f));
    float ang = (float)s * freq;
    float c, sn;
    sincosf(ang, &sn, &c);

    size_t base = (size_t)tok * Dx + h * HDx;
    float q1 = q[base + d], q2 = q[base + d + 64];
    q[base + d]      = q1 * c - q2 * sn;
    q[base + d + 64] = q2 * c + q1 * sn;
    float k1 = k[base + d], k2 = k[base + d + 64];
    k[base + d]      = k1 * c - k2 * sn;
    k[base + d + 64] = k2 * c + k1 * sn;
}

// ================= tensor-core flash attention =================
// CTA: 4 warps, 64 queries x HD=128. Loop over 64-key tiles (causal).
#define KSTR 132      // K smem row stride (floats): B-frag bank pattern 4g+t
#define VSTR 136      // V smem row stride: pattern 8t+g
#define PSTR 68       // P smem row stride: A-frag pattern 4g+t
#define FA_SMEM_BYTES ((64 * KSTR + 64 * VSTR + 4 * 16 * PSTR) * 4)   // 86016

__global__ __launch_bounds__(128) void fattn_kernel(
    const float* __restrict__ q, const float* __restrict__ k,
    const float* __restrict__ v, float* __restrict__ o)
{
    extern __shared__ float fs[];
    float* Ks = fs;                          // [64][KSTR]
    float* Vs = fs + 64 * KSTR;              // [64][VSTR]
    uint32_t* Ps = (uint32_t*)(fs + 64 * KSTR + 64 * VSTR);  // [4][16][PSTR] tf32 bits

    const int bh = blockIdx.x;               // b*H + h
    const int b = bh >> 4;
    const int h = bh & (Hx - 1);
    const int qt = blockIdx.y;               // query tile (64 rows)
    const int tid = threadIdx.x;
    const int lane = tid & 31;
    const int w = tid >> 5;
    const int g = lane >> 2;
    const int t = lane & 3;

    const float* Qg = q + ((size_t)(b * Sx + qt * 64)) * Dx + h * HDx;
    const float* Kg = k + ((size_t)b * Sx) * Dx + h * HDx;
    const float* Vg = v + ((size_t)b * Sx) * Dx + h * HDx;

    // ---- stage Q tile through Ks, pull fragments into registers (scaled) ----
    for (int i = tid; i < 64 * 32; i += 128) {
        int r = i >> 5, c4 = (i & 31) * 4;
        *(float4*)&Ks[r * KSTR + c4] = *(const float4*)(Qg + (size_t)r * Dx + c4);
    }
    __syncthreads();

    const float qscale = 0.08838834764831843f;   // 1/sqrt(128)
    uint32_t qf[16][4];
#pragma unroll
    for (int s = 0; s < 16; s++) {
        const float* r0 = &Ks[(w * 16 + g) * KSTR + s * 8];
        const float* r1 = r0 + 8 * KSTR;
        qf[s][0] = f2tf32(r0[t] * qscale);
        qf[s][1] = f2tf32(r1[t] * qscale);
        qf[s][2] = f2tf32(r0[t + 4] * qscale);
        qf[s][3] = f2tf32(r1[t + 4] * qscale);
    }
    __syncthreads();

    float acc_o[16][4];
#pragma unroll
    for (int n = 0; n < 16; n++)
#pragma unroll
        for (int c = 0; c < 4; c++) acc_o[n][c] = 0.f;

    float m0 = -1e30f, m1 = -1e30f, l0 = 0.f, l1 = 0.f;
    const int q0 = qt * 64 + w * 16;         // warp's first query row (within seq)

    for (int kt = 0; kt <= qt; kt++) {
        // ---- async load K tile (group 0), V tile (group 1) ----
#pragma unroll
        for (int i = 0; i < 16; i++) {
            int f = tid + i * 128;
            int r = f >> 5, c4 = (f & 31) * 4;
            cp16(&Ks[r * KSTR + c4], Kg + (size_t)(kt * 64 + r) * Dx + c4);
        }
        asm volatile("cp.async.commit_group;\n");
#pragma unroll
        for (int i = 0; i < 16; i++) {
            int f = tid + i * 128;
            int r = f >> 5, c4 = (f & 31) * 4;
            cp16(&Vs[r * VSTR + c4], Vg + (size_t)(kt * 64 + r) * Dx + c4);
        }
        asm volatile("cp.async.commit_group;\n");
        asm volatile("cp.async.wait_group 1;\n");   // K ready; V still in flight
        __syncthreads();

        // ---- S = Q @ K^T (16x64 per warp) ----
        float sacc[8][4];
#pragma unroll
        for (int n = 0; n < 8; n++)
#pragma unroll
            for (int c = 0; c < 4; c++) sacc[n][c] = 0.f;

#pragma unroll
        for (int s = 0; s < 16; s++) {
#pragma unroll
            for (int n = 0; n < 8; n++) {
                uint32_t bf[2];
                const float* kr = &Ks[(n * 8 + g) * KSTR + s * 8];
                bf[0] = f2tf32(kr[t]);
                bf[1] = f2tf32(kr[t + 4]);
                mma_tf32(sacc[n], qf[s], bf);
            }
        }

        // ---- causal mask (diagonal tile only) ----
        if (kt == qt) {
#pragma unroll
            for (int n = 0; n < 8; n++) {
                int key = kt * 64 + n * 8 + 2 * t;
                if (key     > q0 + g)     sacc[n][0] = -1e30f;
                if (key + 1 > q0 + g)     sacc[n][1] = -1e30f;
                if (key     > q0 + g + 8) sacc[n][2] = -1e30f;
                if (key + 1 > q0 + g + 8) sacc[n][3] = -1e30f;
            }
        }

        // ---- online softmax (rows g and g+8) ----
        float rm0 = -1e30f, rm1 = -1e30f;
#pragma unroll
        for (int n = 0; n < 8; n++) {
            rm0 = fmaxf(rm0, fmaxf(sacc[n][0], sacc[n][1]));
            rm1 = fmaxf(rm1, fmaxf(sacc[n][2], sacc[n][3]));
        }
        rm0 = fmaxf(rm0, __shfl_xor_sync(0xffffffffu, rm0, 1));
        rm0 = fmaxf(rm0, __shfl_xor_sync(0xffffffffu, rm0, 2));
        rm1 = fmaxf(rm1, __shfl_xor_sync(0xffffffffu, rm1, 1));
        rm1 = fmaxf(rm1, __shfl_xor_sync(0xffffffffu, rm1, 2));

        float nm0 = fmaxf(m0, rm0), nm1 = fmaxf(m1, rm1);
        float c0 = __expf(m0 - nm0), c1 = __expf(m1 - nm1);

        uint32_t* pw = Ps + (w * 16 + g) * PSTR;
        float rs0 = 0.f, rs1 = 0.f;
#pragma unroll
        for (int n = 0; n < 8; n++) {
            float p00 = __expf(sacc[n][0] - nm0);
            float p01 = __expf(sacc[n][1] - nm0);
            float p10 = __expf(sacc[n][2] - nm1);
            float p11 = __expf(sacc[n][3] - nm1);
            rs0 += p00 + p01;
            rs1 += p10 + p11;
            uint2 u0 = make_uint2(f2tf32(p00), f2tf32(p01));
            uint2 u1 = make_uint2(f2tf32(p10), f2tf32(p11));
            *(uint2*)&pw[n * 8 + 2 * t]            = u0;
            *(uint2*)&pw[8 * PSTR + n * 8 + 2 * t] = u1;
        }
        rs0 += __shfl_xor_sync(0xffffffffu, rs0, 1);
        rs0 += __shfl_xor_sync(0xffffffffu, rs0, 2);
        rs1 += __shfl_xor_sync(0xffffffffu, rs1, 1);
        rs1 += __shfl_xor_sync(0xffffffffu, rs1, 2);

        l0 = l0 * c0 + rs0;
        l1 = l1 * c1 + rs1;
        m0 = nm0; m1 = nm1;

#pragma unroll
        for (int n = 0; n < 16; n++) {
            acc_o[n][0] *= c0; acc_o[n][1] *= c0;
            acc_o[n][2] *= c1; acc_o[n][3] *= c1;
        }
        __syncwarp();   // P visible within warp

        // ---- pull P fragments (warp-private region) ----
        uint32_t pf[8][4];
#pragma unroll
        for (int s = 0; s < 8; s++) {
            const uint32_t* pr0 = Ps + (w * 16 + g) * PSTR + s * 8;
            const uint32_t* pr1 = pr0 + 8 * PSTR;
            pf[s][0] = pr0[t];
            pf[s][1] = pr1[t];
            pf[s][2] = pr0[t + 4];
            pf[s][3] = pr1[t + 4];
        }

        asm volatile("cp.async.wait_group 0;\n");   // V ready
        __syncthreads();

        // ---- O += P @ V ----
#pragma unroll
        for (int s = 0; s < 8; s++) {
#pragma unroll
            for (int n = 0; n < 16; n++) {
                uint32_t bf[2];
                bf[0] = f2tf32(Vs[(s * 8 + t) * VSTR + n * 8 + g]);
                bf[1] = f2tf32(Vs[(s * 8 + t + 4) * VSTR + n * 8 + g]);
                mma_tf32(acc_o[n], pf[s], bf);
            }
        }
        __syncthreads();   // all reads of Ks/Vs done before next iter's loads
    }

    // ---- epilogue: divide by l, store ----
    float inv0 = __fdividef(1.0f, l0);
    float inv1 = __fdividef(1.0f, l1);
    size_t tok0 = (size_t)(b * Sx + q0 + g);
    size_t tok1 = tok0 + 8;
    float* o0 = o + tok0 * Dx + h * HDx;
    float* o1 = o + tok1 * Dx + h * HDx;
#pragma unroll
    for (int n = 0; n < 16; n++) {
        int col = n * 8 + 2 * t;
        *(float2*)&o0[col] = make_float2(acc_o[n][0] * inv0, acc_o[n][1] * inv0);
        *(float2*)&o1[col] = make_float2(acc_o[n][2] * inv1, acc_o[n][3] * inv1);
    }
}

// ---------------- MoE gate ----------------
__global__ __launch_bounds__(256) void gate_kernel(
    const float* __restrict__ x, const float* __restrict__ wg, float* __restrict__ comb)
{
    int warp = threadIdx.x >> 5;
    int lane = threadIdx.x & 31;
    int t = blockIdx.x * 8 + warp;
    const float* xr = x + (size_t)t * Dx;

    float a0 = 0.f, a1 = 0.f, a2 = 0.f, a3 = 0.f;
    for (int d = lane; d < Dx; d += 32) {
        float xv = xr[d];
        float4 w4 = ((const float4*)wg)[d];
        a0 = fmaf(xv, w4.x, a0);
        a1 = fmaf(xv, w4.y, a1);
        a2 = fmaf(xv, w4.z, a2);
        a3 = fmaf(xv, w4.w, a3);
    }
#pragma unroll
    for (int off = 16; off >= 1; off >>= 1) {
        a0 += __shfl_xor_sync(0xffffffffu, a0, off);
        a1 += __shfl_xor_sync(0xffffffffu, a1, off);
        a2 += __shfl_xor_sync(0xffffffffu, a2, off);
        a3 += __shfl_xor_sync(0xffffffffu, a3, off);
    }
    if (lane == 0) {
        float lg[4] = {a0, a1, a2, a3};
        float mx = fmaxf(fmaxf(lg[0], lg[1]), fmaxf(lg[2], lg[3]));
        float e[4], sum = 0.f;
#pragma unroll
        for (int i = 0; i < 4; i++) { e[i] = expf(lg[i] - mx); sum += e[i]; }
        float p[4];
#pragma unroll
        for (int i = 0; i < 4; i++) p[i] = e[i] / sum;

        int i0 = 0;
#pragma unroll
        for (int i = 1; i < 4; i++) if (p[i] > p[i0]) i0 = i;
        int i1 = (i0 == 0) ? 1 : 0;
#pragma unroll
        for (int i = 0; i < 4; i++) if (i != i0 && p[i] > p[i1]) i1 = i;

        float hi = fmaxf(p[i0], p[i1]);
        float ea = expf(p[i0] - hi), eb = expf(p[i1] - hi);
        float inv = 1.0f / (ea + eb);
        float w0 = ea * inv, w1 = eb * inv;
#pragma unroll
        for (int i = 0; i < 4; i++)
            comb[t * 4 + i] = (i == i0) ? w0 : ((i == i1) ? w1 : 0.f);
    }
}

// ---------------- host launcher ----------------
extern "C" void kernel_launch(void* const* d_in, const int* in_sizes, int n_in,
                              void* d_out, int out_size)
{
    const float* hidden = (const float*)d_in[0];
    const float* wq   = (const float*)d_in[1];
    const float* bq   = (const float*)d_in[2];
    const float* wk   = (const float*)d_in[3];
    const float* bk   = (const float*)d_in[4];
    const float* wv   = (const float*)d_in[5];
    const float* bv   = (const float*)d_in[6];
    const float* wo   = (const float*)d_in[7];
    const float* bo   = (const float*)d_in[8];
    const float* ln1w = (const float*)d_in[9];
    const float* ln1b = (const float*)d_in[10];
    const float* ln2w = (const float*)d_in[11];
    const float* ln2b = (const float*)d_in[12];
    const float* wgate= (const float*)d_in[13];
    const float* we1  = (const float*)d_in[14];
    const float* be1  = (const float*)d_in[15];
    const float* we2  = (const float*)d_in[16];
    const float* be2  = (const float*)d_in[17];
    float* out = (float*)d_out;

    float *x1, *q, *k, *v, *attn, *x2, *hmid, *comb;
    cudaGetSymbolAddress((void**)&x1,   g_x1);
    cudaGetSymbolAddress((void**)&q,    g_q);
    cudaGetSymbolAddress((void**)&k,    g_k);
    cudaGetSymbolAddress((void**)&v,    g_v);
    cudaGetSymbolAddress((void**)&attn, g_attn);
    cudaGetSymbolAddress((void**)&x2,   g_x2);
    cudaGetSymbolAddress((void**)&hmid, g_hmid);
    cudaGetSymbolAddress((void**)&comb, g_comb);

    cudaFuncSetAttribute(gemm_tc<0>, cudaFuncAttributeMaxDynamicSharedMemorySize, GEMM_SMEM_BYTES);
    cudaFuncSetAttribute(gemm_tc<1>, cudaFuncAttributeMaxDynamicSharedMemorySize, GEMM_SMEM_BYTES);
    cudaFuncSetAttribute(gemm_tc<2>, cudaFuncAttributeMaxDynamicSharedMemorySize, GEMM_SMEM_BYTES);
    cudaFuncSetAttribute(gemm_tc<3>, cudaFuncAttributeMaxDynamicSharedMemorySize, GEMM_SMEM_BYTES);
    cudaFuncSetAttribute(fattn_kernel, cudaFuncAttributeMaxDynamicSharedMemorySize, FA_SMEM_BYTES);

    dim3 gg(Dx / BN, Tx / BM);          // (16, 32)

    // 1) LN1
    ln_kernel<<<Tx, 256>>>(hidden, ln1w, ln1b, x1);
    // 2) QKV projections (tensor cores, tf32)
    gemm_tc<0><<<gg, 256, GEMM_SMEM_BYTES>>>(x1, wq, bq, q, nullptr, Tx, Dx, Dx);
    gemm_tc<0><<<gg, 256, GEMM_SMEM_BYTES>>>(x1, wk, bk, k, nullptr, Tx, Dx, Dx);
    gemm_tc<0><<<gg, 256, GEMM_SMEM_BYTES>>>(x1, wv, bv, v, nullptr, Tx, Dx, Dx);
    // 3) RoPE in-place on q, k
    rope_kernel<<<(Tx * Hx * 64) / 256, 256>>>(q, k);
    // 4) flash attention (tensor cores)
    fattn_kernel<<<dim3(Bx * Hx, Sx / 64), 128, FA_SMEM_BYTES>>>(q, k, v, attn);
    // 5) O-projection + residual
    gemm_tc<1><<<gg, 256, GEMM_SMEM_BYTES>>>(attn, wo, bo, out, hidden, Tx, Dx, Dx);
    // 6) LN2
    ln_kernel<<<Tx, 256>>>(out, ln2w, ln2b, x2);
    // 7) gate -> dense combine weights
    gate_kernel<<<Tx / 8, 256>>>(x2, wgate, comb);
    // 8) dense per-expert MLPs, comb-weighted accumulate into d_out
    for (int e = 0; e < Ex; e++) {
        gemm_tc<2><<<dim3(Ix / BN, Tx / BM), 256, GEMM_SMEM_BYTES>>>(
            x2, we1 + (size_t)e * Dx * Ix, be1 + (size_t)e * Ix,
            hmid, nullptr, Tx, Ix, Dx);
        gemm_tc<3><<<gg, 256, GEMM_SMEM_BYTES>>>(
            hmid, we2 + (size_t)e * Ix * Dx, be2 + (size_t)e * Dx,
            out, comb + e, Tx, Dx, Ix);
    }
}

// round 8
// speedup vs baseline: 5.4848x; 1.3379x over previous
#include <cuda_runtime.h>
#include <math.h>
#include <stdint.h>

// ---------------- problem constants ----------------
#define Bx   2
#define Sx   2048
#define Dx   2048
#define Hx   16
#define HDx  128
#define Ex   4
#define Ix   2048
#define Tx   (Bx * Sx)          // 4096 tokens

// ---------------- scratch (static device globals; no runtime alloc) ----------------
__device__ float g_x1  [(size_t)Tx * Dx];
__device__ float g_q   [(size_t)Tx * Dx];
__device__ float g_k   [(size_t)Tx * Dx];
__device__ float g_v   [(size_t)Tx * Dx];
__device__ float g_attn[(size_t)Tx * Dx];
__device__ float g_x2  [(size_t)Tx * Dx];
__device__ float g_hmid[(size_t)Tx * Ix];
__device__ int   g_cnt [Ex];
__device__ int   g_list[Ex * Tx];
__device__ float g_wgt [Ex * Tx];

__device__ __forceinline__ uint32_t f2tf32(float x) {
    uint32_t u;
    asm volatile("cvt.rna.tf32.f32 %0, %1;\n" : "=r"(u) : "f"(x));
    return u;
}

__device__ __forceinline__ void mma_tf32(float* d, const uint32_t* a, const uint32_t* b) {
    asm volatile(
        "mma.sync.aligned.m16n8k8.row.col.f32.tf32.tf32.f32 "
        "{%0,%1,%2,%3}, {%4,%5,%6,%7}, {%8,%9}, {%0,%1,%2,%3};\n"
        : "+f"(d[0]), "+f"(d[1]), "+f"(d[2]), "+f"(d[3])
        : "r"(a[0]), "r"(a[1]), "r"(a[2]), "r"(a[3]), "r"(b[0]), "r"(b[1]));
}

__device__ __forceinline__ void cp16(float* dst, const float* src) {
    uint32_t d = (uint32_t)__cvta_generic_to_shared(dst);
    asm volatile("cp.async.cg.shared.global [%0], [%1], 16;\n" :: "r"(d), "l"(src));
}

// ---------------- LayerNorm ----------------
__global__ __launch_bounds__(256) void ln_kernel(
    const float* __restrict__ x, const float* __restrict__ w,
    const float* __restrict__ b, float* __restrict__ y)
{
    __shared__ float red[8];
    int row = blockIdx.x;
    int t = threadIdx.x;
    const float* xr = x + (size_t)row * Dx;

    float v[8];
    float s = 0.f;
#pragma unroll
    for (int i = 0; i < 8; i++) { v[i] = xr[t + i * 256]; s += v[i]; }
#pragma unroll
    for (int off = 16; off >= 1; off >>= 1) s += __shfl_xor_sync(0xffffffffu, s, off);
    if ((t & 31) == 0) red[t >> 5] = s;
    __syncthreads();
    float tot = red[0] + red[1] + red[2] + red[3] + red[4] + red[5] + red[6] + red[7];
    float mu = tot * (1.0f / (float)Dx);

    float s2 = 0.f;
#pragma unroll
    for (int i = 0; i < 8; i++) { float d = v[i] - mu; s2 += d * d; }
    __syncthreads();
#pragma unroll
    for (int off = 16; off >= 1; off >>= 1) s2 += __shfl_xor_sync(0xffffffffu, s2, off);
    if ((t & 31) == 0) red[t >> 5] = s2;
    __syncthreads();
    float tot2 = red[0] + red[1] + red[2] + red[3] + red[4] + red[5] + red[6] + red[7];
    float var = tot2 * (1.0f / (float)Dx);
    float r = rsqrtf(var + 1e-5f);

    float* yr = y + (size_t)row * Dx;
#pragma unroll
    for (int i = 0; i < 8; i++) {
        int c = t + i * 256;
        yr[c] = (v[i] - mu) * r * w[c] + b[c];
    }
}

// ================= tensor-core tf32 GEMM (dense) =================
// MODE 0: C = AB + bias
// MODE 1: C = AB + bias + extra (residual)
#define BM 128
#define BN 128
#define BK 32
#define APAD 4
#define BPAD 8
#define ASZ (BM * (BK + APAD))
#define BSZ (BK * (BN + BPAD))
#define GEMM_SMEM_BYTES ((2 * ASZ + 2 * BSZ) * 4)   // 71680

template <int MODE>
__global__ __launch_bounds__(256) void gemm_tc(
    const float* __restrict__ A, const float* __restrict__ B,
    const float* __restrict__ bias, float* __restrict__ C,
    const float* __restrict__ extra, int M, int N, int K)
{
    extern __shared__ float sm[];
    float* As0 = sm;
    float* Bs0 = sm + 2 * ASZ;

    const int tid  = threadIdx.x;
    const int lane = tid & 31;
    const int wid  = tid >> 5;
    const int g = lane >> 2;
    const int t = lane & 3;
    const int wm = wid >> 2;
    const int wn = wid & 3;
    const int m0 = blockIdx.y * BM;
    const int n0 = blockIdx.x * BN;

    float acc[4][4][4];
#pragma unroll
    for (int i = 0; i < 4; i++)
#pragma unroll
        for (int j = 0; j < 4; j++)
#pragma unroll
            for (int c = 0; c < 4; c++) acc[i][j][c] = 0.f;

    auto loadTile = [&](int k0, int buf) {
        float* Ad = As0 + buf * ASZ;
        float* Bd = Bs0 + buf * BSZ;
#pragma unroll
        for (int i = 0; i < 4; i++) {
            int f = tid + i * 256;
            int row = f >> 3;
            int kq  = (f & 7) * 4;
            cp16(Ad + row * (BK + APAD) + kq,
                 A + (size_t)(m0 + row) * K + k0 + kq);
        }
#pragma unroll
        for (int i = 0; i < 4; i++) {
            int f = tid + i * 256;
            int kr = f >> 5;
            int nc = (f & 31) * 4;
            cp16(Bd + kr * (BN + BPAD) + nc,
                 B + (size_t)(k0 + kr) * N + n0 + nc);
        }
        asm volatile("cp.async.commit_group;\n");
    };

    const int ntiles = K / BK;
    loadTile(0, 0);

    for (int tile = 0; tile < ntiles; tile++) {
        int buf = tile & 1;
        if (tile + 1 < ntiles) {
            loadTile((tile + 1) * BK, buf ^ 1);
            asm volatile("cp.async.wait_group 1;\n");
        } else {
            asm volatile("cp.async.wait_group 0;\n");
        }
        __syncthreads();

        const float* Ab = As0 + buf * ASZ;
        const float* Bb = Bs0 + buf * BSZ;

#pragma unroll
        for (int kk = 0; kk < BK / 8; kk++) {
            const int k = kk * 8;
            uint32_t af[4][4];
            uint32_t bf[4][2];
#pragma unroll
            for (int mi = 0; mi < 4; mi++) {
                int r = wm * 64 + mi * 16 + g;
                const float* ar0 = Ab + (size_t)r * (BK + APAD) + k;
                const float* ar1 = ar0 + 8 * (BK + APAD);
                af[mi][0] = __float_as_uint(ar0[t]);
                af[mi][1] = __float_as_uint(ar1[t]);
                af[mi][2] = __float_as_uint(ar0[t + 4]);
                af[mi][3] = __float_as_uint(ar1[t + 4]);
            }
#pragma unroll
            for (int ni = 0; ni < 4; ni++) {
                int c = wn * 32 + ni * 8 + g;
                bf[ni][0] = __float_as_uint(Bb[(size_t)(k + t) * (BN + BPAD) + c]);
                bf[ni][1] = __float_as_uint(Bb[(size_t)(k + t + 4) * (BN + BPAD) + c]);
            }
#pragma unroll
            for (int mi = 0; mi < 4; mi++)
#pragma unroll
                for (int ni = 0; ni < 4; ni++)
                    mma_tf32(acc[mi][ni], af[mi], bf[ni]);
        }
        __syncthreads();
    }

#pragma unroll
    for (int mi = 0; mi < 4; mi++) {
        int r0 = m0 + wm * 64 + mi * 16 + g;
        int r1 = r0 + 8;
#pragma unroll
        for (int ni = 0; ni < 4; ni++) {
            int c = n0 + wn * 32 + ni * 8 + t * 2;
            float v00 = acc[mi][ni][0] + bias[c];
            float v01 = acc[mi][ni][1] + bias[c + 1];
            float v10 = acc[mi][ni][2] + bias[c];
            float v11 = acc[mi][ni][3] + bias[c + 1];
            if (MODE == 1) {
                v00 += extra[(size_t)r0 * N + c];
                v01 += extra[(size_t)r0 * N + c + 1];
                v10 += extra[(size_t)r1 * N + c];
                v11 += extra[(size_t)r1 * N + c + 1];
            }
            C[(size_t)r0 * N + c]     = v00;
            C[(size_t)r0 * N + c + 1] = v01;
            C[(size_t)r1 * N + c]     = v10;
            C[(size_t)r1 * N + c + 1] = v11;
        }
    }
}

// ================= sparse MoE expert GEMMs =================
// PHASE 0 (up):   A rows gathered from X via gidx; C = gelu(AB+bias) compact into hmid
// PHASE 1 (down): A compact (hmid); C[gidx[m]] += gw[m] * (AB + bias)
template <int PHASE>
__global__ __launch_bounds__(256) void gemm_moe(
    const float* __restrict__ A, const float* __restrict__ B,
    const float* __restrict__ bias, float* __restrict__ C,
    const int* __restrict__ gidx, const float* __restrict__ gw,
    const int* __restrict__ gcnt, int N, int K)
{
    const int cnt = *gcnt;
    const int m0 = blockIdx.y * BM;
    if (m0 >= cnt) return;

    extern __shared__ float sm[];
    float* As0 = sm;
    float* Bs0 = sm + 2 * ASZ;

    const int tid  = threadIdx.x;
    const int lane = tid & 31;
    const int wid  = tid >> 5;
    const int g = lane >> 2;
    const int t = lane & 3;
    const int wm = wid >> 2;
    const int wn = wid & 3;
    const int n0 = blockIdx.x * BN;

    float acc[4][4][4];
#pragma unroll
    for (int i = 0; i < 4; i++)
#pragma unroll
        for (int j = 0; j < 4; j++)
#pragma unroll
            for (int c = 0; c < 4; c++) acc[i][j][c] = 0.f;

    // per-thread A source rows: loader iteration i touches row (tid>>3) + 32*i
    int asrc[4];
#pragma unroll
    for (int u = 0; u < 4; u++) {
        int gr = m0 + (tid >> 3) + 32 * u;
        if (gr >= cnt) gr = cnt - 1;
        asrc[u] = (PHASE == 0) ? gidx[gr] : gr;
    }

    auto loadTile = [&](int k0, int buf) {
        float* Ad = As0 + buf * ASZ;
        float* Bd = Bs0 + buf * BSZ;
#pragma unroll
        for (int i = 0; i < 4; i++) {
            int row = (tid >> 3) + 32 * i;
            int kq  = (tid & 7) * 4;
            cp16(Ad + row * (BK + APAD) + kq,
                 A + (size_t)asrc[i] * K + k0 + kq);
        }
#pragma unroll
        for (int i = 0; i < 4; i++) {
            int f = tid + i * 256;
            int kr = f >> 5;
            int nc = (f & 31) * 4;
            cp16(Bd + kr * (BN + BPAD) + nc,
                 B + (size_t)(k0 + kr) * N + n0 + nc);
        }
        asm volatile("cp.async.commit_group;\n");
    };

    const int ntiles = K / BK;
    loadTile(0, 0);

    for (int tile = 0; tile < ntiles; tile++) {
        int buf = tile & 1;
        if (tile + 1 < ntiles) {
            loadTile((tile + 1) * BK, buf ^ 1);
            asm volatile("cp.async.wait_group 1;\n");
        } else {
            asm volatile("cp.async.wait_group 0;\n");
        }
        __syncthreads();

        const float* Ab = As0 + buf * ASZ;
        const float* Bb = Bs0 + buf * BSZ;

#pragma unroll
        for (int kk = 0; kk < BK / 8; kk++) {
            const int k = kk * 8;
            uint32_t af[4][4];
            uint32_t bf[4][2];
#pragma unroll
            for (int mi = 0; mi < 4; mi++) {
                int r = wm * 64 + mi * 16 + g;
                const float* ar0 = Ab + (size_t)r * (BK + APAD) + k;
                const float* ar1 = ar0 + 8 * (BK + APAD);
                af[mi][0] = __float_as_uint(ar0[t]);
                af[mi][1] = __float_as_uint(ar1[t]);
                af[mi][2] = __float_as_uint(ar0[t + 4]);
                af[mi][3] = __float_as_uint(ar1[t + 4]);
            }
#pragma unroll
            for (int ni = 0; ni < 4; ni++) {
                int c = wn * 32 + ni * 8 + g;
                bf[ni][0] = __float_as_uint(Bb[(size_t)(k + t) * (BN + BPAD) + c]);
                bf[ni][1] = __float_as_uint(Bb[(size_t)(k + t + 4) * (BN + BPAD) + c]);
            }
#pragma unroll
            for (int mi = 0; mi < 4; mi++)
#pragma unroll
                for (int ni = 0; ni < 4; ni++)
                    mma_tf32(acc[mi][ni], af[mi], bf[ni]);
        }
        __syncthreads();
    }

#pragma unroll
    for (int mi = 0; mi < 4; mi++) {
        int r0 = m0 + wm * 64 + mi * 16 + g;
        int r1 = r0 + 8;
        bool v0 = r0 < cnt, v1 = r1 < cnt;
        int d0 = 0, d1 = 0;
        float s0 = 0.f, s1 = 0.f;
        if (PHASE == 1) {
            if (v0) { d0 = gidx[r0]; s0 = gw[r0]; }
            if (v1) { d1 = gidx[r1]; s1 = gw[r1]; }
        }
#pragma unroll
        for (int ni = 0; ni < 4; ni++) {
            int c = n0 + wn * 32 + ni * 8 + t * 2;
            float v00 = acc[mi][ni][0] + bias[c];
            float v01 = acc[mi][ni][1] + bias[c + 1];
            float v10 = acc[mi][ni][2] + bias[c];
            float v11 = acc[mi][ni][3] + bias[c + 1];
            if (PHASE == 0) {
                v00 = 0.5f * v00 * (1.0f + erff(v00 * 0.70710678118654752f));
                v01 = 0.5f * v01 * (1.0f + erff(v01 * 0.70710678118654752f));
                v10 = 0.5f * v10 * (1.0f + erff(v10 * 0.70710678118654752f));
                v11 = 0.5f * v11 * (1.0f + erff(v11 * 0.70710678118654752f));
                if (v0) {
                    C[(size_t)r0 * N + c]     = v00;
                    C[(size_t)r0 * N + c + 1] = v01;
                }
                if (v1) {
                    C[(size_t)r1 * N + c]     = v10;
                    C[(size_t)r1 * N + c + 1] = v11;
                }
            } else {
                if (v0) {
                    C[(size_t)d0 * N + c]     += s0 * v00;
                    C[(size_t)d0 * N + c + 1] += s0 * v01;
                }
                if (v1) {
                    C[(size_t)d1 * N + c]     += s1 * v10;
                    C[(size_t)d1 * N + c + 1] += s1 * v11;
                }
            }
        }
    }
}

// ---------------- RoPE ----------------
__global__ __launch_bounds__(256) void rope_kernel(float* __restrict__ q, float* __restrict__ k)
{
    int idx = blockIdx.x * 256 + threadIdx.x;
    int d = idx & 63;
    int rest = idx >> 6;
    int h = rest & (Hx - 1);
    int tok = rest >> 4;
    int s = tok & (Sx - 1);

    float freq = expf(-(float)d * (9.21034037197618f / 64.0f));
    float ang = (float)s * freq;
    float c, sn;
    sincosf(ang, &sn, &c);

    size_t base = (size_t)tok * Dx + h * HDx;
    float q1 = q[base + d], q2 = q[base + d + 64];
    q[base + d]      = q1 * c - q2 * sn;
    q[base + d + 64] = q2 * c + q1 * sn;
    float k1 = k[base + d], k2 = k[base + d + 64];
    k[base + d]      = k1 * c - k2 * sn;
    k[base + d + 64] = k2 * c + k1 * sn;
}

// ================= tensor-core flash attention =================
#define KSTR 132
#define VSTR 136
#define PSTR 68
#define FA_SMEM_BYTES ((64 * KSTR + 64 * VSTR + 4 * 16 * PSTR) * 4)   // 86016

__global__ __launch_bounds__(128) void fattn_kernel(
    const float* __restrict__ q, const float* __restrict__ k,
    const float* __restrict__ v, float* __restrict__ o)
{
    extern __shared__ float fs[];
    float* Ks = fs;
    float* Vs = fs + 64 * KSTR;
    uint32_t* Ps = (uint32_t*)(fs + 64 * KSTR + 64 * VSTR);

    const int bh = blockIdx.x;
    const int b = bh >> 4;
    const int h = bh & (Hx - 1);
    const int qt = blockIdx.y;
    const int tid = threadIdx.x;
    const int lane = tid & 31;
    const int w = tid >> 5;
    const int g = lane >> 2;
    const int t = lane & 3;

    const float* Qg = q + ((size_t)(b * Sx + qt * 64)) * Dx + h * HDx;
    const float* Kg = k + ((size_t)b * Sx) * Dx + h * HDx;
    const float* Vg = v + ((size_t)b * Sx) * Dx + h * HDx;

    for (int i = tid; i < 64 * 32; i += 128) {
        int r = i >> 5, c4 = (i & 31) * 4;
        *(float4*)&Ks[r * KSTR + c4] = *(const float4*)(Qg + (size_t)r * Dx + c4);
    }
    __syncthreads();

    const float qscale = 0.08838834764831843f;
    uint32_t qf[16][4];
#pragma unroll
    for (int s = 0; s < 16; s++) {
        const float* r0 = &Ks[(w * 16 + g) * KSTR + s * 8];
        const float* r1 = r0 + 8 * KSTR;
        qf[s][0] = f2tf32(r0[t] * qscale);
        qf[s][1] = f2tf32(r1[t] * qscale);
        qf[s][2] = f2tf32(r0[t + 4] * qscale);
        qf[s][3] = f2tf32(r1[t + 4] * qscale);
    }
    __syncthreads();

    float acc_o[16][4];
#pragma unroll
    for (int n = 0; n < 16; n++)
#pragma unroll
        for (int c = 0; c < 4; c++) acc_o[n][c] = 0.f;

    float m0 = -1e30f, m1 = -1e30f, l0 = 0.f, l1 = 0.f;
    const int q0 = qt * 64 + w * 16;

    for (int kt = 0; kt <= qt; kt++) {
#pragma unroll
        for (int i = 0; i < 16; i++) {
            int f = tid + i * 128;
            int r = f >> 5, c4 = (f & 31) * 4;
            cp16(&Ks[r * KSTR + c4], Kg + (size_t)(kt * 64 + r) * Dx + c4);
        }
        asm volatile("cp.async.commit_group;\n");
#pragma unroll
        for (int i = 0; i < 16; i++) {
            int f = tid + i * 128;
            int r = f >> 5, c4 = (f & 31) * 4;
            cp16(&Vs[r * VSTR + c4], Vg + (size_t)(kt * 64 + r) * Dx + c4);
        }
        asm volatile("cp.async.commit_group;\n");
        asm volatile("cp.async.wait_group 1;\n");
        __syncthreads();

        float sacc[8][4];
#pragma unroll
        for (int n = 0; n < 8; n++)
#pragma unroll
            for (int c = 0; c < 4; c++) sacc[n][c] = 0.f;

#pragma unroll
        for (int s = 0; s < 16; s++) {
#pragma unroll
            for (int n = 0; n < 8; n++) {
                uint32_t bf[2];
                const float* kr = &Ks[(n * 8 + g) * KSTR + s * 8];
                bf[0] = __float_as_uint(kr[t]);
                bf[1] = __float_as_uint(kr[t + 4]);
                mma_tf32(sacc[n], qf[s], bf);
            }
        }

        if (kt == qt) {
#pragma unroll
            for (int n = 0; n < 8; n++) {
                int key = kt * 64 + n * 8 + 2 * t;
                if (key     > q0 + g)     sacc[n][0] = -1e30f;
                if (key + 1 > q0 + g)     sacc[n][1] = -1e30f;
                if (key     > q0 + g + 8) sacc[n][2] = -1e30f;
                if (key + 1 > q0 + g + 8) sacc[n][3] = -1e30f;
            }
        }

        float rm0 = -1e30f, rm1 = -1e30f;
#pragma unroll
        for (int n = 0; n < 8; n++) {
            rm0 = fmaxf(rm0, fmaxf(sacc[n][0], sacc[n][1]));
            rm1 = fmaxf(rm1, fmaxf(sacc[n][2], sacc[n][3]));
        }
        rm0 = fmaxf(rm0, __shfl_xor_sync(0xffffffffu, rm0, 1));
        rm0 = fmaxf(rm0, __shfl_xor_sync(0xffffffffu, rm0, 2));
        rm1 = fmaxf(rm1, __shfl_xor_sync(0xffffffffu, rm1, 1));
        rm1 = fmaxf(rm1, __shfl_xor_sync(0xffffffffu, rm1, 2));

        float nm0 = fmaxf(m0, rm0), nm1 = fmaxf(m1, rm1);
        float c0 = __expf(m0 - nm0), c1 = __expf(m1 - nm1);

        uint32_t* pw = Ps + (w * 16 + g) * PSTR;
        float rs0 = 0.f, rs1 = 0.f;
#pragma unroll
        for (int n = 0; n < 8; n++) {
            float p00 = __expf(sacc[n][0] - nm0);
            float p01 = __expf(sacc[n][1] - nm0);
            float p10 = __expf(sacc[n][2] - nm1);
            float p11 = __expf(sacc[n][3] - nm1);
            rs0 += p00 + p01;
            rs1 += p10 + p11;
            uint2 u0 = make_uint2(__float_as_uint(p00), __float_as_uint(p01));
            uint2 u1 = make_uint2(__float_as_uint(p10), __float_as_uint(p11));
            *(uint2*)&pw[n * 8 + 2 * t]            = u0;
            *(uint2*)&pw[8 * PSTR + n * 8 + 2 * t] = u1;
        }
        rs0 += __shfl_xor_sync(0xffffffffu, rs0, 1);
        rs0 += __shfl_xor_sync(0xffffffffu, rs0, 2);
        rs1 += __shfl_xor_sync(0xffffffffu, rs1, 1);
        rs1 += __shfl_xor_sync(0xffffffffu, rs1, 2);

        l0 = l0 * c0 + rs0;
        l1 = l1 * c1 + rs1;
        m0 = nm0; m1 = nm1;

#pragma unroll
        for (int n = 0; n < 16; n++) {
            acc_o[n][0] *= c0; acc_o[n][1] *= c0;
            acc_o[n][2] *= c1; acc_o[n][3] *= c1;
        }
        __syncwarp();

        uint32_t pf[8][4];
#pragma unroll
        for (int s = 0; s < 8; s++) {
            const uint32_t* pr0 = Ps + (w * 16 + g) * PSTR + s * 8;
            const uint32_t* pr1 = pr0 + 8 * PSTR;
            pf[s][0] = pr0[t];
            pf[s][1] = pr1[t];
            pf[s][2] = pr0[t + 4];
            pf[s][3] = pr1[t + 4];
        }

        asm volatile("cp.async.wait_group 0;\n");
        __syncthreads();

#pragma unroll
        for (int s = 0; s < 8; s++) {
#pragma unroll
            for (int n = 0; n < 16; n++) {
                uint32_t bf[2];
                bf[0] = __float_as_uint(Vs[(s * 8 + t) * VSTR + n * 8 + g]);
                bf[1] = __float_as_uint(Vs[(s * 8 + t + 4) * VSTR + n * 8 + g]);
                mma_tf32(acc_o[n], pf[s], bf);
            }
        }
        __syncthreads();
    }

    float inv0 = __fdividef(1.0f, l0);
    float inv1 = __fdividef(1.0f, l1);
    size_t tok0 = (size_t)(b * Sx + q0 + g);
    size_t tok1 = tok0 + 8;
    float* o0 = o + tok0 * Dx + h * HDx;
    float* o1 = o + tok1 * Dx + h * HDx;
#pragma unroll
    for (int n = 0; n < 16; n++) {
        int col = n * 8 + 2 * t;
        *(float2*)&o0[col] = make_float2(acc_o[n][0] * inv0, acc_o[n][1] * inv0);
        *(float2*)&o1[col] = make_float2(acc_o[n][2] * inv1, acc_o[n][3] * inv1);
    }
}

// ---------------- zero expert counters ----------------
__global__ void zero_cnt_kernel(int* cnt)
{
    if (threadIdx.x < Ex) cnt[threadIdx.x] = 0;
}

// ---------------- MoE gate: top-2 scatter into per-expert lists ----------------
__global__ __launch_bounds__(256) void gate_kernel(
    const float* __restrict__ x, const float* __restrict__ wg,
    int* __restrict__ cnt, int* __restrict__ list, float* __restrict__ wgt)
{
    int warp = threadIdx.x >> 5;
    int lane = threadIdx.x & 31;
    int t = blockIdx.x * 8 + warp;
    const float* xr = x + (size_t)t * Dx;

    float a0 = 0.f, a1 = 0.f, a2 = 0.f, a3 = 0.f;
    for (int d = lane; d < Dx; d += 32) {
        float xv = xr[d];
        float4 w4 = ((const float4*)wg)[d];
        a0 = fmaf(xv, w4.x, a0);
        a1 = fmaf(xv, w4.y, a1);
        a2 = fmaf(xv, w4.z, a2);
        a3 = fmaf(xv, w4.w, a3);
    }
#pragma unroll
    for (int off = 16; off >= 1; off >>= 1) {
        a0 += __shfl_xor_sync(0xffffffffu, a0, off);
        a1 += __shfl_xor_sync(0xffffffffu, a1, off);
        a2 += __shfl_xor_sync(0xffffffffu, a2, off);
        a3 += __shfl_xor_sync(0xffffffffu, a3, off);
    }
    if (lane == 0) {
        float lg[4] = {a0, a1, a2, a3};
        float mx = fmaxf(fmaxf(lg[0], lg[1]), fmaxf(lg[2], lg[3]));
        float e[4], sum = 0.f;
#pragma unroll
        for (int i = 0; i < 4; i++) { e[i] = expf(lg[i] - mx); sum += e[i]; }
        float p[4];
#pragma unroll
        for (int i = 0; i < 4; i++) p[i] = e[i] / sum;

        int i0 = 0;
#pragma unroll
        for (int i = 1; i < 4; i++) if (p[i] > p[i0]) i0 = i;
        int i1 = (i0 == 0) ? 1 : 0;
#pragma unroll
        for (int i = 0; i < 4; i++) if (i != i0 && p[i] > p[i1]) i1 = i;

        float hi = fmaxf(p[i0], p[i1]);
        float ea = expf(p[i0] - hi), eb = expf(p[i1] - hi);
        float inv = 1.0f / (ea + eb);
        float w0 = ea * inv, w1 = eb * inv;

        int s0 = atomicAdd(&cnt[i0], 1);
        list[i0 * Tx + s0] = t;
        wgt [i0 * Tx + s0] = w0;
        int s1 = atomicAdd(&cnt[i1], 1);
        list[i1 * Tx + s1] = t;
        wgt [i1 * Tx + s1] = w1;
    }
}

// ---------------- host launcher ----------------
extern "C" void kernel_launch(void* const* d_in, const int* in_sizes, int n_in,
                              void* d_out, int out_size)
{
    const float* hidden = (const float*)d_in[0];
    const float* wq   = (const float*)d_in[1];
    const float* bq   = (const float*)d_in[2];
    const float* wk   = (const float*)d_in[3];
    const float* bk   = (const float*)d_in[4];
    const float* wv   = (const float*)d_in[5];
    const float* bv   = (const float*)d_in[6];
    const float* wo   = (const float*)d_in[7];
    const float* bo   = (const float*)d_in[8];
    const float* ln1w = (const float*)d_in[9];
    const float* ln1b = (const float*)d_in[10];
    const float* ln2w = (const float*)d_in[11];
    const float* ln2b = (const float*)d_in[12];
    const float* wgate= (const float*)d_in[13];
    const float* we1  = (const float*)d_in[14];
    const float* be1  = (const float*)d_in[15];
    const float* we2  = (const float*)d_in[16];
    const float* be2  = (const float*)d_in[17];
    float* out = (float*)d_out;

    float *x1, *q, *k, *v, *attn, *x2, *hmid, *wgt;
    int *cnt, *list;
    cudaGetSymbolAddress((void**)&x1,   g_x1);
    cudaGetSymbolAddress((void**)&q,    g_q);
    cudaGetSymbolAddress((void**)&k,    g_k);
    cudaGetSymbolAddress((void**)&v,    g_v);
    cudaGetSymbolAddress((void**)&attn, g_attn);
    cudaGetSymbolAddress((void**)&x2,   g_x2);
    cudaGetSymbolAddress((void**)&hmid, g_hmid);
    cudaGetSymbolAddress((void**)&cnt,  g_cnt);
    cudaGetSymbolAddress((void**)&list, g_list);
    cudaGetSymbolAddress((void**)&wgt,  g_wgt);

    cudaFuncSetAttribute(gemm_tc<0>, cudaFuncAttributeMaxDynamicSharedMemorySize, GEMM_SMEM_BYTES);
    cudaFuncSetAttribute(gemm_tc<1>, cudaFuncAttributeMaxDynamicSharedMemorySize, GEMM_SMEM_BYTES);
    cudaFuncSetAttribute(gemm_moe<0>, cudaFuncAttributeMaxDynamicSharedMemorySize, GEMM_SMEM_BYTES);
    cudaFuncSetAttribute(gemm_moe<1>, cudaFuncAttributeMaxDynamicSharedMemorySize, GEMM_SMEM_BYTES);
    cudaFuncSetAttribute(fattn_kernel, cudaFuncAttributeMaxDynamicSharedMemorySize, FA_SMEM_BYTES);

    dim3 gg(Dx / BN, Tx / BM);          // (16, 32)

    // 1) LN1
    ln_kernel<<<Tx, 256>>>(hidden, ln1w, ln1b, x1);
    // 2) QKV projections
    gemm_tc<0><<<gg, 256, GEMM_SMEM_BYTES>>>(x1, wq, bq, q, nullptr, Tx, Dx, Dx);
    gemm_tc<0><<<gg, 256, GEMM_SMEM_BYTES>>>(x1, wk, bk, k, nullptr, Tx, Dx, Dx);
    gemm_tc<0><<<gg, 256, GEMM_SMEM_BYTES>>>(x1, wv, bv, v, nullptr, Tx, Dx, Dx);
    // 3) RoPE
    rope_kernel<<<(Tx * Hx * 64) / 256, 256>>>(q, k);
    // 4) flash attention
    fattn_kernel<<<dim3(Bx * Hx, Sx / 64), 128, FA_SMEM_BYTES>>>(q, k, v, attn);
    // 5) O-projection + residual
    gemm_tc<1><<<gg, 256, GEMM_SMEM_BYTES>>>(attn, wo, bo, out, hidden, Tx, Dx, Dx);
    // 6) LN2
    ln_kernel<<<Tx, 256>>>(out, ln2w, ln2b, x2);
    // 7) gate: zero counters, then top-2 scatter
    zero_cnt_kernel<<<1, 32>>>(cnt);
    gate_kernel<<<Tx / 8, 256>>>(x2, wgate, cnt, list, wgt);
    // 8) sparse per-expert MLPs (blocks beyond cnt[e] exit immediately)
    for (int e = 0; e < Ex; e++) {
        gemm_moe<0><<<dim3(Ix / BN, Tx / BM), 256, GEMM_SMEM_BYTES>>>(
            x2, we1 + (size_t)e * Dx * Ix, be1 + (size_t)e * Ix,
            hmid, list + e * Tx, nullptr, cnt + e, Ix, Dx);
        gemm_moe<1><<<dim3(Dx / BN, Tx / BM), 256, GEMM_SMEM_BYTES>>>(
            hmid, we2 + (size_t)e * Ix * Dx, be2 + (size_t)e * Dx,
            out, list + e * Tx, wgt + e * Tx, cnt + e, Dx, Ix);
    }
}

// round 9
// speedup vs baseline: 5.7213x; 1.0431x over previous
#include <cuda_runtime.h>
#include <math.h>
#include <stdint.h>

// ---------------- problem constants ----------------
#define Bx   2
#define Sx   2048
#define Dx   2048
#define Hx   16
#define HDx  128
#define Ex   4
#define Ix   2048
#define Tx   (Bx * Sx)          // 4096 tokens

// ---------------- scratch (static device globals; no runtime alloc) ----------------
__device__ float g_x1  [(size_t)Tx * Dx];
__device__ float g_q   [(size_t)Tx * Dx];
__device__ float g_k   [(size_t)Tx * Dx];
__device__ float g_v   [(size_t)Tx * Dx];
__device__ float g_attn[(size_t)Tx * Dx];
__device__ float g_x2  [(size_t)Tx * Dx];
__device__ float g_hmid[(size_t)Tx * Ix];
__device__ int   g_cnt [Ex];
__device__ int   g_list[Ex * Tx];
__device__ float g_wgt [Ex * Tx];

__device__ __forceinline__ uint32_t f2tf32(float x) {
    uint32_t u;
    asm volatile("cvt.rna.tf32.f32 %0, %1;\n" : "=r"(u) : "f"(x));
    return u;
}

__device__ __forceinline__ void mma_tf32(float* d, const uint32_t* a, const uint32_t* b) {
    asm volatile(
        "mma.sync.aligned.m16n8k8.row.col.f32.tf32.tf32.f32 "
        "{%0,%1,%2,%3}, {%4,%5,%6,%7}, {%8,%9}, {%0,%1,%2,%3};\n"
        : "+f"(d[0]), "+f"(d[1]), "+f"(d[2]), "+f"(d[3])
        : "r"(a[0]), "r"(a[1]), "r"(a[2]), "r"(a[3]), "r"(b[0]), "r"(b[1]));
}

__device__ __forceinline__ void cp16(float* dst, const float* src) {
    uint32_t d = (uint32_t)__cvta_generic_to_shared(dst);
    asm volatile("cp.async.cg.shared.global [%0], [%1], 16;\n" :: "r"(d), "l"(src));
}

// ---------------- LayerNorm ----------------
__global__ __launch_bounds__(256) void ln_kernel(
    const float* __restrict__ x, const float* __restrict__ w,
    const float* __restrict__ b, float* __restrict__ y)
{
    __shared__ float red[8];
    int row = blockIdx.x;
    int t = threadIdx.x;
    const float* xr = x + (size_t)row * Dx;

    float v[8];
    float s = 0.f;
#pragma unroll
    for (int i = 0; i < 8; i++) { v[i] = xr[t + i * 256]; s += v[i]; }
#pragma unroll
    for (int off = 16; off >= 1; off >>= 1) s += __shfl_xor_sync(0xffffffffu, s, off);
    if ((t & 31) == 0) red[t >> 5] = s;
    __syncthreads();
    float tot = red[0] + red[1] + red[2] + red[3] + red[4] + red[5] + red[6] + red[7];
    float mu = tot * (1.0f / (float)Dx);

    float s2 = 0.f;
#pragma unroll
    for (int i = 0; i < 8; i++) { float d = v[i] - mu; s2 += d * d; }
    __syncthreads();
#pragma unroll
    for (int off = 16; off >= 1; off >>= 1) s2 += __shfl_xor_sync(0xffffffffu, s2, off);
    if ((t & 31) == 0) red[t >> 5] = s2;
    __syncthreads();
    float tot2 = red[0] + red[1] + red[2] + red[3] + red[4] + red[5] + red[6] + red[7];
    float var = tot2 * (1.0f / (float)Dx);
    float r = rsqrtf(var + 1e-5f);

    float* yr = y + (size_t)row * Dx;
#pragma unroll
    for (int i = 0; i < 8; i++) {
        int c = t + i * 256;
        yr[c] = (v[i] - mu) * r * w[c] + b[c];
    }
}

// ================= tensor-core tf32 GEMM (dense) =================
// MODE 0: C = AB + bias
// MODE 1: C = AB + bias + extra (residual)
#define BM 128
#define BN 128
#define BK 32
#define APAD 4
#define BPAD 8
#define ASZ (BM * (BK + APAD))
#define BSZ (BK * (BN + BPAD))
#define GEMM_SMEM_BYTES ((2 * ASZ + 2 * BSZ) * 4)   // 71680

template <int MODE>
__global__ __launch_bounds__(256, 2) void gemm_tc(
    const float* __restrict__ A, const float* __restrict__ B,
    const float* __restrict__ bias, float* __restrict__ C,
    const float* __restrict__ extra, int M, int N, int K)
{
    extern __shared__ float sm[];
    float* As0 = sm;
    float* Bs0 = sm + 2 * ASZ;

    const int tid  = threadIdx.x;
    const int lane = tid & 31;
    const int wid  = tid >> 5;
    const int g = lane >> 2;
    const int t = lane & 3;
    const int wm = wid >> 2;
    const int wn = wid & 3;
    const int m0 = blockIdx.y * BM;
    const int n0 = blockIdx.x * BN;

    float acc[4][4][4];
#pragma unroll
    for (int i = 0; i < 4; i++)
#pragma unroll
        for (int j = 0; j < 4; j++)
#pragma unroll
            for (int c = 0; c < 4; c++) acc[i][j][c] = 0.f;

    auto loadTile = [&](int k0, int buf) {
        float* Ad = As0 + buf * ASZ;
        float* Bd = Bs0 + buf * BSZ;
#pragma unroll
        for (int i = 0; i < 4; i++) {
            int f = tid + i * 256;
            int row = f >> 3;
            int kq  = (f & 7) * 4;
            cp16(Ad + row * (BK + APAD) + kq,
                 A + (size_t)(m0 + row) * K + k0 + kq);
        }
#pragma unroll
        for (int i = 0; i < 4; i++) {
            int f = tid + i * 256;
            int kr = f >> 5;
            int nc = (f & 31) * 4;
            cp16(Bd + kr * (BN + BPAD) + nc,
                 B + (size_t)(k0 + kr) * N + n0 + nc);
        }
        asm volatile("cp.async.commit_group;\n");
    };

    const int ntiles = K / BK;
    loadTile(0, 0);

    for (int tile = 0; tile < ntiles; tile++) {
        int buf = tile & 1;
        if (tile + 1 < ntiles) {
            loadTile((tile + 1) * BK, buf ^ 1);
            asm volatile("cp.async.wait_group 1;\n");
        } else {
            asm volatile("cp.async.wait_group 0;\n");
        }
        __syncthreads();

        const float* Ab = As0 + buf * ASZ;
        const float* Bb = Bs0 + buf * BSZ;

#pragma unroll
        for (int kk = 0; kk < BK / 8; kk++) {
            const int k = kk * 8;
            uint32_t af[4][4];
            uint32_t bf[4][2];
#pragma unroll
            for (int mi = 0; mi < 4; mi++) {
                int r = wm * 64 + mi * 16 + g;
                const float* ar0 = Ab + (size_t)r * (BK + APAD) + k;
                const float* ar1 = ar0 + 8 * (BK + APAD);
                af[mi][0] = f2tf32(ar0[t]);
                af[mi][1] = f2tf32(ar1[t]);
                af[mi][2] = f2tf32(ar0[t + 4]);
                af[mi][3] = f2tf32(ar1[t + 4]);
            }
#pragma unroll
            for (int ni = 0; ni < 4; ni++) {
                int c = wn * 32 + ni * 8 + g;
                bf[ni][0] = f2tf32(Bb[(size_t)(k + t) * (BN + BPAD) + c]);
                bf[ni][1] = f2tf32(Bb[(size_t)(k + t + 4) * (BN + BPAD) + c]);
            }
#pragma unroll
            for (int mi = 0; mi < 4; mi++)
#pragma unroll
                for (int ni = 0; ni < 4; ni++)
                    mma_tf32(acc[mi][ni], af[mi], bf[ni]);
        }
        __syncthreads();
    }

#pragma unroll
    for (int mi = 0; mi < 4; mi++) {
        int r0 = m0 + wm * 64 + mi * 16 + g;
        int r1 = r0 + 8;
#pragma unroll
        for (int ni = 0; ni < 4; ni++) {
            int c = n0 + wn * 32 + ni * 8 + t * 2;
            float2 b2 = *(const float2*)&bias[c];
            float v00 = acc[mi][ni][0] + b2.x;
            float v01 = acc[mi][ni][1] + b2.y;
            float v10 = acc[mi][ni][2] + b2.x;
            float v11 = acc[mi][ni][3] + b2.y;
            if (MODE == 1) {
                float2 e0 = *(const float2*)&extra[(size_t)r0 * N + c];
                float2 e1 = *(const float2*)&extra[(size_t)r1 * N + c];
                v00 += e0.x; v01 += e0.y;
                v10 += e1.x; v11 += e1.y;
            }
            *(float2*)&C[(size_t)r0 * N + c] = make_float2(v00, v01);
            *(float2*)&C[(size_t)r1 * N + c] = make_float2(v10, v11);
        }
    }
}

// ================= sparse MoE expert GEMMs =================
// PHASE 0 (up):   A rows gathered from X via gidx; C = gelu(AB+bias) compact into hmid
// PHASE 1 (down): A compact (hmid); C[gidx[m]] += gw[m] * (AB + bias)
template <int PHASE>
__global__ __launch_bounds__(256, 2) void gemm_moe(
    const float* __restrict__ A, const float* __restrict__ B,
    const float* __restrict__ bias, float* __restrict__ C,
    const int* __restrict__ gidx, const float* __restrict__ gw,
    const int* __restrict__ gcnt, int N, int K)
{
    const int cnt = *gcnt;
    const int m0 = blockIdx.y * BM;
    if (m0 >= cnt) return;

    extern __shared__ float sm[];
    float* As0 = sm;
    float* Bs0 = sm + 2 * ASZ;

    const int tid  = threadIdx.x;
    const int lane = tid & 31;
    const int wid  = tid >> 5;
    const int g = lane >> 2;
    const int t = lane & 3;
    const int wm = wid >> 2;
    const int wn = wid & 3;
    const int n0 = blockIdx.x * BN;

    float acc[4][4][4];
#pragma unroll
    for (int i = 0; i < 4; i++)
#pragma unroll
        for (int j = 0; j < 4; j++)
#pragma unroll
            for (int c = 0; c < 4; c++) acc[i][j][c] = 0.f;

    // per-thread A source rows: loader iteration i touches row (tid>>3) + 32*i
    int asrc[4];
#pragma unroll
    for (int u = 0; u < 4; u++) {
        int gr = m0 + (tid >> 3) + 32 * u;
        if (gr >= cnt) gr = cnt - 1;
        asrc[u] = (PHASE == 0) ? gidx[gr] : gr;
    }

    auto loadTile = [&](int k0, int buf) {
        float* Ad = As0 + buf * ASZ;
        float* Bd = Bs0 + buf * BSZ;
#pragma unroll
        for (int i = 0; i < 4; i++) {
            int row = (tid >> 3) + 32 * i;
            int kq  = (tid & 7) * 4;
            cp16(Ad + row * (BK + APAD) + kq,
                 A + (size_t)asrc[i] * K + k0 + kq);
        }
#pragma unroll
        for (int i = 0; i < 4; i++) {
            int f = tid + i * 256;
            int kr = f >> 5;
            int nc = (f & 31) * 4;
            cp16(Bd + kr * (BN + BPAD) + nc,
                 B + (size_t)(k0 + kr) * N + n0 + nc);
        }
        asm volatile("cp.async.commit_group;\n");
    };

    const int ntiles = K / BK;
    loadTile(0, 0);

    for (int tile = 0; tile < ntiles; tile++) {
        int buf = tile & 1;
        if (tile + 1 < ntiles) {
            loadTile((tile + 1) * BK, buf ^ 1);
            asm volatile("cp.async.wait_group 1;\n");
        } else {
            asm volatile("cp.async.wait_group 0;\n");
        }
        __syncthreads();

        const float* Ab = As0 + buf * ASZ;
        const float* Bb = Bs0 + buf * BSZ;

#pragma unroll
        for (int kk = 0; kk < BK / 8; kk++) {
            const int k = kk * 8;
            uint32_t af[4][4];
            uint32_t bf[4][2];
#pragma unroll
            for (int mi = 0; mi < 4; mi++) {
                int r = wm * 64 + mi * 16 + g;
                const float* ar0 = Ab + (size_t)r * (BK + APAD) + k;
                const float* ar1 = ar0 + 8 * (BK + APAD);
                af[mi][0] = f2tf32(ar0[t]);
                af[mi][1] = f2tf32(ar1[t]);
                af[mi][2] = f2tf32(ar0[t + 4]);
                af[mi][3] = f2tf32(ar1[t + 4]);
            }
#pragma unroll
            for (int ni = 0; ni < 4; ni++) {
                int c = wn * 32 + ni * 8 + g;
                bf[ni][0] = f2tf32(Bb[(size_t)(k + t) * (BN + BPAD) + c]);
                bf[ni][1] = f2tf32(Bb[(size_t)(k + t + 4) * (BN + BPAD) + c]);
            }
#pragma unroll
            for (int mi = 0; mi < 4; mi++)
#pragma unroll
                for (int ni = 0; ni < 4; ni++)
                    mma_tf32(acc[mi][ni], af[mi], bf[ni]);
        }
        __syncthreads();
    }

#pragma unroll
    for (int mi = 0; mi < 4; mi++) {
        int r0 = m0 + wm * 64 + mi * 16 + g;
        int r1 = r0 + 8;
        bool v0 = r0 < cnt, v1 = r1 < cnt;
        int d0 = 0, d1 = 0;
        float s0 = 0.f, s1 = 0.f;
        if (PHASE == 1) {
            if (v0) { d0 = gidx[r0]; s0 = gw[r0]; }
            if (v1) { d1 = gidx[r1]; s1 = gw[r1]; }
        }
#pragma unroll
        for (int ni = 0; ni < 4; ni++) {
            int c = n0 + wn * 32 + ni * 8 + t * 2;
            float2 b2 = *(const float2*)&bias[c];
            float v00 = acc[mi][ni][0] + b2.x;
            float v01 = acc[mi][ni][1] + b2.y;
            float v10 = acc[mi][ni][2] + b2.x;
            float v11 = acc[mi][ni][3] + b2.y;
            if (PHASE == 0) {
                v00 = 0.5f * v00 * (1.0f + erff(v00 * 0.70710678118654752f));
                v01 = 0.5f * v01 * (1.0f + erff(v01 * 0.70710678118654752f));
                v10 = 0.5f * v10 * (1.0f + erff(v10 * 0.70710678118654752f));
                v11 = 0.5f * v11 * (1.0f + erff(v11 * 0.70710678118654752f));
                if (v0) *(float2*)&C[(size_t)r0 * N + c] = make_float2(v00, v01);
                if (v1) *(float2*)&C[(size_t)r1 * N + c] = make_float2(v10, v11);
            } else {
                if (v0) {
                    float2 o0 = *(const float2*)&C[(size_t)d0 * N + c];
                    o0.x += s0 * v00; o0.y += s0 * v01;
                    *(float2*)&C[(size_t)d0 * N + c] = o0;
                }
                if (v1) {
                    float2 o1 = *(const float2*)&C[(size_t)d1 * N + c];
                    o1.x += s1 * v10; o1.y += s1 * v11;
                    *(float2*)&C[(size_t)d1 * N + c] = o1;
                }
            }
        }
    }
}

// ---------------- RoPE ----------------
__global__ __launch_bounds__(256) void rope_kernel(float* __restrict__ q, float* __restrict__ k)
{
    int idx = blockIdx.x * 256 + threadIdx.x;
    int d = idx & 63;
    int rest = idx >> 6;
    int h = rest & (Hx - 1);
    int tok = rest >> 4;
    int s = tok & (Sx - 1);

    float freq = expf(-(float)d * (9.21034037197618f / 64.0f));
    float ang = (float)s * freq;
    float c, sn;
    sincosf(ang, &sn, &c);

    size_t base = (size_t)tok * Dx + h * HDx;
    float q1 = q[base + d], q2 = q[base + d + 64];
    q[base + d]      = q1 * c - q2 * sn;
    q[base + d + 64] = q2 * c + q1 * sn;
    float k1 = k[base + d], k2 = k[base + d + 64];
    k[base + d]      = k1 * c - k2 * sn;
    k[base + d + 64] = k2 * c + k1 * sn;
}

// ================= tensor-core flash attention =================
#define KSTR 132
#define VSTR 136
#define PSTR 68
#define FA_SMEM_BYTES ((64 * KSTR + 64 * VSTR + 4 * 16 * PSTR) * 4)   // 86016

__global__ __launch_bounds__(128) void fattn_kernel(
    const float* __restrict__ q, const float* __restrict__ k,
    const float* __restrict__ v, float* __restrict__ o)
{
    extern __shared__ float fs[];
    float* Ks = fs;
    float* Vs = fs + 64 * KSTR;
    uint32_t* Ps = (uint32_t*)(fs + 64 * KSTR + 64 * VSTR);

    const int bh = blockIdx.x;
    const int b = bh >> 4;
    const int h = bh & (Hx - 1);
    const int qt = blockIdx.y;
    const int tid = threadIdx.x;
    const int lane = tid & 31;
    const int w = tid >> 5;
    const int g = lane >> 2;
    const int t = lane & 3;

    const float* Qg = q + ((size_t)(b * Sx + qt * 64)) * Dx + h * HDx;
    const float* Kg = k + ((size_t)b * Sx) * Dx + h * HDx;
    const float* Vg = v + ((size_t)b * Sx) * Dx + h * HDx;

    for (int i = tid; i < 64 * 32; i += 128) {
        int r = i >> 5, c4 = (i & 31) * 4;
        *(float4*)&Ks[r * KSTR + c4] = *(const float4*)(Qg + (size_t)r * Dx + c4);
    }
    __syncthreads();

    const float qscale = 0.08838834764831843f;
    uint32_t qf[16][4];
#pragma unroll
    for (int s = 0; s < 16; s++) {
        const float* r0 = &Ks[(w * 16 + g) * KSTR + s * 8];
        const float* r1 = r0 + 8 * KSTR;
        qf[s][0] = f2tf32(r0[t] * qscale);
        qf[s][1] = f2tf32(r1[t] * qscale);
        qf[s][2] = f2tf32(r0[t + 4] * qscale);
        qf[s][3] = f2tf32(r1[t + 4] * qscale);
    }
    __syncthreads();

    float acc_o[16][4];
#pragma unroll
    for (int n = 0; n < 16; n++)
#pragma unroll
        for (int c = 0; c < 4; c++) acc_o[n][c] = 0.f;

    float m0 = -1e30f, m1 = -1e30f, l0 = 0.f, l1 = 0.f;
    const int q0 = qt * 64 + w * 16;

    for (int kt = 0; kt <= qt; kt++) {
#pragma unroll
        for (int i = 0; i < 16; i++) {
            int f = tid + i * 128;
            int r = f >> 5, c4 = (f & 31) * 4;
            cp16(&Ks[r * KSTR + c4], Kg + (size_t)(kt * 64 + r) * Dx + c4);
        }
        asm volatile("cp.async.commit_group;\n");
#pragma unroll
        for (int i = 0; i < 16; i++) {
            int f = tid + i * 128;
            int r = f >> 5, c4 = (f & 31) * 4;
            cp16(&Vs[r * VSTR + c4], Vg + (size_t)(kt * 64 + r) * Dx + c4);
        }
        asm volatile("cp.async.commit_group;\n");
        asm volatile("cp.async.wait_group 1;\n");
        __syncthreads();

        float sacc[8][4];
#pragma unroll
        for (int n = 0; n < 8; n++)
#pragma unroll
            for (int c = 0; c < 4; c++) sacc[n][c] = 0.f;

#pragma unroll
        for (int s = 0; s < 16; s++) {
#pragma unroll
            for (int n = 0; n < 8; n++) {
                uint32_t bf[2];
                const float* kr = &Ks[(n * 8 + g) * KSTR + s * 8];
                bf[0] = f2tf32(kr[t]);
                bf[1] = f2tf32(kr[t + 4]);
                mma_tf32(sacc[n], qf[s], bf);
            }
        }

        if (kt == qt) {
#pragma unroll
            for (int n = 0; n < 8; n++) {
                int key = kt * 64 + n * 8 + 2 * t;
                if (key     > q0 + g)     sacc[n][0] = -1e30f;
                if (key + 1 > q0 + g)     sacc[n][1] = -1e30f;
                if (key     > q0 + g + 8) sacc[n][2] = -1e30f;
                if (key + 1 > q0 + g + 8) sacc[n][3] = -1e30f;
            }
        }

        float rm0 = -1e30f, rm1 = -1e30f;
#pragma unroll
        for (int n = 0; n < 8; n++) {
            rm0 = fmaxf(rm0, fmaxf(sacc[n][0], sacc[n][1]));
            rm1 = fmaxf(rm1, fmaxf(sacc[n][2], sacc[n][3]));
        }
        rm0 = fmaxf(rm0, __shfl_xor_sync(0xffffffffu, rm0, 1));
        rm0 = fmaxf(rm0, __shfl_xor_sync(0xffffffffu, rm0, 2));
        rm1 = fmaxf(rm1, __shfl_xor_sync(0xffffffffu, rm1, 1));
        rm1 = fmaxf(rm1, __shfl_xor_sync(0xffffffffu, rm1, 2));

        float nm0 = fmaxf(m0, rm0), nm1 = fmaxf(m1, rm1);
        float c0 = __expf(m0 - nm0), c1 = __expf(m1 - nm1);

        uint32_t* pw = Ps + (w * 16 + g) * PSTR;
        float rs0 = 0.f, rs1 = 0.f;
#pragma unroll
        for (int n = 0; n < 8; n++) {
            float p00 = __expf(sacc[n][0] - nm0);
            float p01 = __expf(sacc[n][1] - nm0);
            float p10 = __expf(sacc[n][2] - nm1);
            float p11 = __expf(sacc[n][3] - nm1);
            rs0 += p00 + p01;
            rs1 += p10 + p11;
            uint2 u0 = make_uint2(f2tf32(p00), f2tf32(p01));
            uint2 u1 = make_uint2(f2tf32(p10), f2tf32(p11));
            *(uint2*)&pw[n * 8 + 2 * t]            = u0;
            *(uint2*)&pw[8 * PSTR + n * 8 + 2 * t] = u1;
        }
        rs0 += __shfl_xor_sync(0xffffffffu, rs0, 1);
        rs0 += __shfl_xor_sync(0xffffffffu, rs0, 2);
        rs1 += __shfl_xor_sync(0xffffffffu, rs1, 1);
        rs1 += __shfl_xor_sync(0xffffffffu, rs1, 2);

        l0 = l0 * c0 + rs0;
        l1 = l1 * c1 + rs1;
        m0 = nm0; m1 = nm1;

#pragma unroll
        for (int n = 0; n < 16; n++) {
            acc_o[n][0] *= c0; acc_o[n][1] *= c0;
            acc_o[n][2] *= c1; acc_o[n][3] *= c1;
        }
        __syncwarp();

        uint32_t pf[8][4];
#pragma unroll
        for (int s = 0; s < 8; s++) {
            const uint32_t* pr0 = Ps + (w * 16 + g) * PSTR + s * 8;
            const uint32_t* pr1 = pr0 + 8 * PSTR;
            pf[s][0] = pr0[t];
            pf[s][1] = pr1[t];
            pf[s][2] = pr0[t + 4];
            pf[s][3] = pr1[t + 4];
        }

        asm volatile("cp.async.wait_group 0;\n");
        __syncthreads();

#pragma unroll
        for (int s = 0; s < 8; s++) {
#pragma unroll
            for (int n = 0; n < 16; n++) {
                uint32_t bf[2];
                bf[0] = f2tf32(Vs[(s * 8 + t) * VSTR + n * 8 + g]);
                bf[1] = f2tf32(Vs[(s * 8 + t + 4) * VSTR + n * 8 + g]);
                mma_tf32(acc_o[n], pf[s], bf);
            }
        }
        __syncthreads();
    }

    float inv0 = __fdividef(1.0f, l0);
    float inv1 = __fdividef(1.0f, l1);
    size_t tok0 = (size_t)(b * Sx + q0 + g);
    size_t tok1 = tok0 + 8;
    float* o0 = o + tok0 * Dx + h * HDx;
    float* o1 = o + tok1 * Dx + h * HDx;
#pragma unroll
    for (int n = 0; n < 16; n++) {
        int col = n * 8 + 2 * t;
        *(float2*)&o0[col] = make_float2(acc_o[n][0] * inv0, acc_o[n][1] * inv0);
        *(float2*)&o1[col] = make_float2(acc_o[n][2] * inv1, acc_o[n][3] * inv1);
    }
}

// ---------------- zero expert counters ----------------
__global__ void zero_cnt_kernel(int* cnt)
{
    if (threadIdx.x < Ex) cnt[threadIdx.x] = 0;
}

// ---------------- MoE gate: top-2 scatter into per-expert lists ----------------
__global__ __launch_bounds__(256) void gate_kernel(
    const float* __restrict__ x, const float* __restrict__ wg,
    int* __restrict__ cnt, int* __restrict__ list, float* __restrict__ wgt)
{
    int warp = threadIdx.x >> 5;
    int lane = threadIdx.x & 31;
    int t = blockIdx.x * 8 + warp;
    const float* xr = x + (size_t)t * Dx;

    float a0 = 0.f, a1 = 0.f, a2 = 0.f, a3 = 0.f;
    for (int d = lane; d < Dx; d += 32) {
        float xv = xr[d];
        float4 w4 = ((const float4*)wg)[d];
        a0 = fmaf(xv, w4.x, a0);
        a1 = fmaf(xv, w4.y, a1);
        a2 = fmaf(xv, w4.z, a2);
        a3 = fmaf(xv, w4.w, a3);
    }
#pragma unroll
    for (int off = 16; off >= 1; off >>= 1) {
        a0 += __shfl_xor_sync(0xffffffffu, a0, off);
        a1 += __shfl_xor_sync(0xffffffffu, a1, off);
        a2 += __shfl_xor_sync(0xffffffffu, a2, off);
        a3 += __shfl_xor_sync(0xffffffffu, a3, off);
    }
    if (lane == 0) {
        float lg[4] = {a0, a1, a2, a3};
        float mx = fmaxf(fmaxf(lg[0], lg[1]), fmaxf(lg[2], lg[3]));
        float e[4], sum = 0.f;
#pragma unroll
        for (int i = 0; i < 4; i++) { e[i] = expf(lg[i] - mx); sum += e[i]; }
        float p[4];
#pragma unroll
        for (int i = 0; i < 4; i++) p[i] = e[i] / sum;

        int i0 = 0;
#pragma unroll
        for (int i = 1; i < 4; i++) if (p[i] > p[i0]) i0 = i;
        int i1 = (i0 == 0) ? 1 : 0;
#pragma unroll
        for (int i = 0; i < 4; i++) if (i != i0 && p[i] > p[i1]) i1 = i;

        float hi = fmaxf(p[i0], p[i1]);
        float ea = expf(p[i0] - hi), eb = expf(p[i1] - hi);
        float inv = 1.0f / (ea + eb);
        float w0 = ea * inv, w1 = eb * inv;

        int s0 = atomicAdd(&cnt[i0], 1);
        list[i0 * Tx + s0] = t;
        wgt [i0 * Tx + s0] = w0;
        int s1 = atomicAdd(&cnt[i1], 1);
        list[i1 * Tx + s1] = t;
        wgt [i1 * Tx + s1] = w1;
    }
}

// ---------------- host launcher ----------------
extern "C" void kernel_launch(void* const* d_in, const int* in_sizes, int n_in,
                              void* d_out, int out_size)
{
    const float* hidden = (const float*)d_in[0];
    const float* wq   = (const float*)d_in[1];
    const float* bq   = (const float*)d_in[2];
    const float* wk   = (const float*)d_in[3];
    const float* bk   = (const float*)d_in[4];
    const float* wv   = (const float*)d_in[5];
    const float* bv   = (const float*)d_in[6];
    const float* wo   = (const float*)d_in[7];
    const float* bo   = (const float*)d_in[8];
    const float* ln1w = (const float*)d_in[9];
    const float* ln1b = (const float*)d_in[10];
    const float* ln2w = (const float*)d_in[11];
    const float* ln2b = (const float*)d_in[12];
    const float* wgate= (const float*)d_in[13];
    const float* we1  = (const float*)d_in[14];
    const float* be1  = (const float*)d_in[15];
    const float* we2  = (const float*)d_in[16];
    const float* be2  = (const float*)d_in[17];
    float* out = (float*)d_out;

    float *x1, *q, *k, *v, *attn, *x2, *hmid, *wgt;
    int *cnt, *list;
    cudaGetSymbolAddress((void**)&x1,   g_x1);
    cudaGetSymbolAddress((void**)&q,    g_q);
    cudaGetSymbolAddress((void**)&k,    g_k);
    cudaGetSymbolAddress((void**)&v,    g_v);
    cudaGetSymbolAddress((void**)&attn, g_attn);
    cudaGetSymbolAddress((void**)&x2,   g_x2);
    cudaGetSymbolAddress((void**)&hmid, g_hmid);
    cudaGetSymbolAddress((void**)&cnt,  g_cnt);
    cudaGetSymbolAddress((void**)&list, g_list);
    cudaGetSymbolAddress((void**)&wgt,  g_wgt);

    cudaFuncSetAttribute(gemm_tc<0>, cudaFuncAttributeMaxDynamicSharedMemorySize, GEMM_SMEM_BYTES);
    cudaFuncSetAttribute(gemm_tc<1>, cudaFuncAttributeMaxDynamicSharedMemorySize, GEMM_SMEM_BYTES);
    cudaFuncSetAttribute(gemm_moe<0>, cudaFuncAttributeMaxDynamicSharedMemorySize, GEMM_SMEM_BYTES);
    cudaFuncSetAttribute(gemm_moe<1>, cudaFuncAttributeMaxDynamicSharedMemorySize, GEMM_SMEM_BYTES);
    cudaFuncSetAttribute(fattn_kernel, cudaFuncAttributeMaxDynamicSharedMemorySize, FA_SMEM_BYTES);

    dim3 gg(Dx / BN, Tx / BM);          // (16, 32)

    // 1) LN1
    ln_kernel<<<Tx, 256>>>(hidden, ln1w, ln1b, x1);
    // 2) QKV projections
    gemm_tc<0><<<gg, 256, GEMM_SMEM_BYTES>>>(x1, wq, bq, q, nullptr, Tx, Dx, Dx);
    gemm_tc<0><<<gg, 256, GEMM_SMEM_BYTES>>>(x1, wk, bk, k, nullptr, Tx, Dx, Dx);
    gemm_tc<0><<<gg, 256, GEMM_SMEM_BYTES>>>(x1, wv, bv, v, nullptr, Tx, Dx, Dx);
    // 3) RoPE
    rope_kernel<<<(Tx * Hx * 64) / 256, 256>>>(q, k);
    // 4) flash attention
    fattn_kernel<<<dim3(Bx * Hx, Sx / 64), 128, FA_SMEM_BYTES>>>(q, k, v, attn);
    // 5) O-projection + residual
    gemm_tc<1><<<gg, 256, GEMM_SMEM_BYTES>>>(attn, wo, bo, out, hidden, Tx, Dx, Dx);
    // 6) LN2
    ln_kernel<<<Tx, 256>>>(out, ln2w, ln2b, x2);
    // 7) gate: zero counters, then top-2 scatter
    zero_cnt_kernel<<<1, 32>>>(cnt);
    gate_kernel<<<Tx / 8, 256>>>(x2, wgate, cnt, list, wgt);
    // 8) sparse per-expert MLPs (blocks beyond cnt[e] exit immediately)
    for (int e = 0; e < Ex; e++) {
        gemm_moe<0><<<dim3(Ix / BN, Tx / BM), 256, GEMM_SMEM_BYTES>>>(
            x2, we1 + (size_t)e * Dx * Ix, be1 + (size_t)e * Ix,
            hmid, list + e * Tx, nullptr, cnt + e, Ix, Dx);
        gemm_moe<1><<<dim3(Dx / BN, Tx / BM), 256, GEMM_SMEM_BYTES>>>(
            hmid, we2 + (size_t)e * Ix * Dx, be2 + (size_t)e * Dx,
            out, list + e * Tx, wgt + e * Tx, cnt + e, Dx, Ix);
    }
}

// round 11
// speedup vs baseline: 6.7249x; 1.1754x over previous
#include <cuda_runtime.h>
#include <math.h>
#include <stdint.h>

// ---------------- problem constants ----------------
#define Bx   2
#define Sx   2048
#define Dx   2048
#define Hx   16
#define HDx  128
#define Ex   4
#define Ix   2048
#define Tx   (Bx * Sx)          // 4096 tokens

// ---------------- scratch (static device globals; no runtime alloc) ----------------
__device__ float g_x1  [(size_t)Tx * Dx];
__device__ float g_q   [(size_t)Tx * Dx];
__device__ float g_k   [(size_t)Tx * Dx];
__device__ float g_v   [(size_t)Tx * Dx];
__device__ float g_attn[(size_t)Tx * Dx];
__device__ float g_x2  [(size_t)Tx * Dx];
__device__ float g_hmid[(size_t)Ex * Tx * Ix];   // per-expert compact mid activations
__device__ int   g_cnt [Ex];
__device__ int   g_list[Ex * Tx];
__device__ float g_wgt [Ex * Tx];

__device__ __forceinline__ uint32_t f2tf32(float x) {
    uint32_t u;
    asm volatile("cvt.rna.tf32.f32 %0, %1;\n" : "=r"(u) : "f"(x));
    return u;
}
__device__ __forceinline__ float rnd_tf32(float x) {
    return __uint_as_float(f2tf32(x));
}
__device__ __forceinline__ void mma_tf32(float* d, const uint32_t* a, const uint32_t* b) {
    asm volatile(
        "mma.sync.aligned.m16n8k8.row.col.f32.tf32.tf32.f32 "
        "{%0,%1,%2,%3}, {%4,%5,%6,%7}, {%8,%9}, {%0,%1,%2,%3};\n"
        : "+f"(d[0]), "+f"(d[1]), "+f"(d[2]), "+f"(d[3])
        : "r"(a[0]), "r"(a[1]), "r"(a[2]), "r"(a[3]), "r"(b[0]), "r"(b[1]));
}
__device__ __forceinline__ void cp16(float* dst, const float* src) {
    uint32_t d = (uint32_t)__cvta_generic_to_shared(dst);
    asm volatile("cp.async.cg.shared.global [%0], [%1], 16;\n" :: "r"(d), "l"(src));
}

// ---------------- LayerNorm (ROUND: tf32-round the output) ----------------
template <bool ROUND>
__global__ __launch_bounds__(256) void ln_kernel(
    const float* __restrict__ x, const float* __restrict__ w,
    const float* __restrict__ b, float* __restrict__ y)
{
    __shared__ float red[8];
    int row = blockIdx.x;
    int t = threadIdx.x;
    const float* xr = x + (size_t)row * Dx;

    float v[8];
    float s = 0.f;
#pragma unroll
    for (int i = 0; i < 8; i++) { v[i] = xr[t + i * 256]; s += v[i]; }
#pragma unroll
    for (int off = 16; off >= 1; off >>= 1) s += __shfl_xor_sync(0xffffffffu, s, off);
    if ((t & 31) == 0) red[t >> 5] = s;
    __syncthreads();
    float tot = red[0] + red[1] + red[2] + red[3] + red[4] + red[5] + red[6] + red[7];
    float mu = tot * (1.0f / (float)Dx);

    float s2 = 0.f;
#pragma unroll
    for (int i = 0; i < 8; i++) { float d = v[i] - mu; s2 += d * d; }
    __syncthreads();
#pragma unroll
    for (int off = 16; off >= 1; off >>= 1) s2 += __shfl_xor_sync(0xffffffffu, s2, off);
    if ((t & 31) == 0) red[t >> 5] = s2;
    __syncthreads();
    float tot2 = red[0] + red[1] + red[2] + red[3] + red[4] + red[5] + red[6] + red[7];
    float var = tot2 * (1.0f / (float)Dx);
    float r = rsqrtf(var + 1e-5f);

    float* yr = y + (size_t)row * Dx;
#pragma unroll
    for (int i = 0; i < 8; i++) {
        int c = t + i * 256;
        float val = (v[i] - mu) * r * w[c] + b[c];
        yr[c] = ROUND ? rnd_tf32(val) : val;
    }
}

// ================= shared tf32 mma.sync GEMM body =================
// C[M(=cnt),N] = A @ B[K,N], epilogues by MODE.
// MODE 0: C = AB + bias
// MODE 1: C = AB + bias + extra (residual [M,N])
// MODE 2: A rows gathered via gidx; C = rnd_tf32(gelu(AB+bias)), compact rows
// MODE 3: A compact; atomicAdd(C[gidx[m]], gw[m]*(AB+bias))
// CVTA: cvt.rna A fragments (needed when A not pre-rounded); B always cvt.
#define BM 128
#define BN 128
#define BK 32
#define APAD 4
#define BPAD 8
#define ASZ (BM * (BK + APAD))
#define BSZ (BK * (BN + BPAD))
#define GEMM_SMEM_BYTES ((2 * ASZ + 2 * BSZ) * 4)   // 71680

template <int MODE, bool CVTA>
__device__ __forceinline__ void gemm_body(
    float* sm, const float* A, const float* B,
    const float* bias, float* C, const float* extra,
    const int* gidx, const float* gw, int cnt,
    int N, int K, int m0, int n0)
{
    float* As0 = sm;
    float* Bs0 = sm + 2 * ASZ;

    const int tid  = threadIdx.x;
    const int lane = tid & 31;
    const int wid  = tid >> 5;
    const int g = lane >> 2;
    const int t = lane & 3;
    const int wm = wid >> 2;
    const int wn = wid & 3;

    float acc[4][4][4];
#pragma unroll
    for (int i = 0; i < 4; i++)
#pragma unroll
        for (int j = 0; j < 4; j++)
#pragma unroll
            for (int c = 0; c < 4; c++) acc[i][j][c] = 0.f;

    int asrc[4];
#pragma unroll
    for (int u = 0; u < 4; u++) {
        int gr = m0 + (tid >> 3) + 32 * u;
        if (gr >= cnt) gr = cnt - 1;
        asrc[u] = (MODE == 2) ? gidx[gr] : gr;
    }

    auto loadTile = [&](int k0, int buf) {
        float* Ad = As0 + buf * ASZ;
        float* Bd = Bs0 + buf * BSZ;
#pragma unroll
        for (int i = 0; i < 4; i++) {
            int row = (tid >> 3) + 32 * i;
            int kq  = (tid & 7) * 4;
            cp16(Ad + row * (BK + APAD) + kq,
                 A + (size_t)asrc[i] * K + k0 + kq);
        }
#pragma unroll
        for (int i = 0; i < 4; i++) {
            int f = tid + i * 256;
            int kr = f >> 5;
            int nc = (f & 31) * 4;
            cp16(Bd + kr * (BN + BPAD) + nc,
                 B + (size_t)(k0 + kr) * N + n0 + nc);
        }
        asm volatile("cp.async.commit_group;\n");
    };

    const int ntiles = K / BK;
    loadTile(0, 0);

    for (int tile = 0; tile < ntiles; tile++) {
        int buf = tile & 1;
        if (tile + 1 < ntiles) {
            loadTile((tile + 1) * BK, buf ^ 1);
            asm volatile("cp.async.wait_group 1;\n");
        } else {
            asm volatile("cp.async.wait_group 0;\n");
        }
        __syncthreads();

        const float* Ab = As0 + buf * ASZ;
        const float* Bb = Bs0 + buf * BSZ;

#pragma unroll
        for (int kk = 0; kk < BK / 8; kk++) {
            const int k = kk * 8;
            uint32_t af[4][4];
            uint32_t bf[4][2];
#pragma unroll
            for (int mi = 0; mi < 4; mi++) {
                int r = wm * 64 + mi * 16 + g;
                const float* ar0 = Ab + (size_t)r * (BK + APAD) + k;
                const float* ar1 = ar0 + 8 * (BK + APAD);
                if (CVTA) {
                    af[mi][0] = f2tf32(ar0[t]);
                    af[mi][1] = f2tf32(ar1[t]);
                    af[mi][2] = f2tf32(ar0[t + 4]);
                    af[mi][3] = f2tf32(ar1[t + 4]);
                } else {
                    af[mi][0] = __float_as_uint(ar0[t]);
                    af[mi][1] = __float_as_uint(ar1[t]);
                    af[mi][2] = __float_as_uint(ar0[t + 4]);
                    af[mi][3] = __float_as_uint(ar1[t + 4]);
                }
            }
#pragma unroll
            for (int ni = 0; ni < 4; ni++) {
                int c = wn * 32 + ni * 8 + g;
                bf[ni][0] = f2tf32(Bb[(size_t)(k + t) * (BN + BPAD) + c]);
                bf[ni][1] = f2tf32(Bb[(size_t)(k + t + 4) * (BN + BPAD) + c]);
            }
#pragma unroll
            for (int mi = 0; mi < 4; mi++)
#pragma unroll
                for (int ni = 0; ni < 4; ni++)
                    mma_tf32(acc[mi][ni], af[mi], bf[ni]);
        }
        __syncthreads();
    }

#pragma unroll
    for (int mi = 0; mi < 4; mi++) {
        int r0 = m0 + wm * 64 + mi * 16 + g;
        int r1 = r0 + 8;
        bool v0 = r0 < cnt, v1 = r1 < cnt;
        int d0 = 0, d1 = 0;
        float s0 = 0.f, s1 = 0.f;
        if (MODE == 3) {
            if (v0) { d0 = gidx[r0]; s0 = gw[r0]; }
            if (v1) { d1 = gidx[r1]; s1 = gw[r1]; }
        }
#pragma unroll
        for (int ni = 0; ni < 4; ni++) {
            int c = n0 + wn * 32 + ni * 8 + t * 2;
            float2 b2 = *(const float2*)&bias[c];
            float v00 = acc[mi][ni][0] + b2.x;
            float v01 = acc[mi][ni][1] + b2.y;
            float v10 = acc[mi][ni][2] + b2.x;
            float v11 = acc[mi][ni][3] + b2.y;
            if (MODE == 0 || MODE == 1) {
                if (MODE == 1) {
                    float2 e0 = *(const float2*)&extra[(size_t)r0 * N + c];
                    float2 e1 = *(const float2*)&extra[(size_t)r1 * N + c];
                    v00 += e0.x; v01 += e0.y;
                    v10 += e1.x; v11 += e1.y;
                }
                *(float2*)&C[(size_t)r0 * N + c] = make_float2(v00, v01);
                *(float2*)&C[(size_t)r1 * N + c] = make_float2(v10, v11);
            } else if (MODE == 2) {
                v00 = rnd_tf32(0.5f * v00 * (1.0f + erff(v00 * 0.70710678118654752f)));
                v01 = rnd_tf32(0.5f * v01 * (1.0f + erff(v01 * 0.70710678118654752f)));
                v10 = rnd_tf32(0.5f * v10 * (1.0f + erff(v10 * 0.70710678118654752f)));
                v11 = rnd_tf32(0.5f * v11 * (1.0f + erff(v11 * 0.70710678118654752f)));
                if (v0) *(float2*)&C[(size_t)r0 * N + c] = make_float2(v00, v01);
                if (v1) *(float2*)&C[(size_t)r1 * N + c] = make_float2(v10, v11);
            } else {
                if (v0) {
                    atomicAdd(&C[(size_t)d0 * N + c],     s0 * v00);
                    atomicAdd(&C[(size_t)d0 * N + c + 1], s0 * v01);
                }
                if (v1) {
                    atomicAdd(&C[(size_t)d1 * N + c],     s1 * v10);
                    atomicAdd(&C[(size_t)d1 * N + c + 1], s1 * v11);
                }
            }
        }
    }
}

// ---------------- fused QKV: blockIdx.z selects projection ----------------
__global__ __launch_bounds__(256, 2) void gemm_qkv(
    const float* __restrict__ A,
    const float* __restrict__ Bq, const float* __restrict__ Bk, const float* __restrict__ Bv,
    const float* __restrict__ bq, const float* __restrict__ bk, const float* __restrict__ bv,
    float* __restrict__ Cq, float* __restrict__ Ck, float* __restrict__ Cv)
{
    extern __shared__ float sm[];
    int z = blockIdx.z;
    const float* B = (z == 0) ? Bq : (z == 1) ? Bk : Bv;
    const float* bb = (z == 0) ? bq : (z == 1) ? bk : bv;
    float* C = (z == 0) ? Cq : (z == 1) ? Ck : Cv;
    gemm_body<0, false>(sm, A, B, bb, C, nullptr, nullptr, nullptr,
                        Tx, Dx, Dx, blockIdx.y * BM, blockIdx.x * BN);
}

// ---------------- O-projection + residual ----------------
__global__ __launch_bounds__(256, 2) void gemm_o(
    const float* __restrict__ A, const float* __restrict__ B,
    const float* __restrict__ bias, float* __restrict__ C,
    const float* __restrict__ extra)
{
    extern __shared__ float sm[];
    gemm_body<1, false>(sm, A, B, bias, C, extra, nullptr, nullptr,
                        Tx, Dx, Dx, blockIdx.y * BM, blockIdx.x * BN);
}

// ---------------- fused MoE up: blockIdx.z = expert ----------------
__global__ __launch_bounds__(256, 2) void moe_up(
    const float* __restrict__ x, const float* __restrict__ we1,
    const float* __restrict__ be1, float* __restrict__ hmid,
    const int* __restrict__ list, const int* __restrict__ cnt)
{
    extern __shared__ float sm[];
    int z = blockIdx.z;
    int c = cnt[z];
    int m0 = blockIdx.y * BM;
    if (m0 >= c) return;
    gemm_body<2, true>(sm,
        x, we1 + (size_t)z * Dx * Ix, be1 + (size_t)z * Ix,
        hmid + (size_t)z * Tx * Ix,
        nullptr, list + z * Tx, nullptr, c,
        Ix, Dx, m0, blockIdx.x * BN);
}

// ---------------- fused MoE down: blockIdx.z = expert, atomic scatter ----------------
__global__ __launch_bounds__(256, 2) void moe_dn(
    const float* __restrict__ hmid, const float* __restrict__ we2,
    const float* __restrict__ be2, float* __restrict__ out,
    const int* __restrict__ list, const float* __restrict__ wgt,
    const int* __restrict__ cnt)
{
    extern __shared__ float sm[];
    int z = blockIdx.z;
    int c = cnt[z];
    int m0 = blockIdx.y * BM;
    if (m0 >= c) return;
    gemm_body<3, false>(sm,
        hmid + (size_t)z * Tx * Ix, we2 + (size_t)z * Ix * Dx,
        be2 + (size_t)z * Dx, out,
        nullptr, list + z * Tx, wgt + z * Tx, c,
        Dx, Ix, m0, blockIdx.x * BN);
}

// ---------------- RoPE ----------------
__global__ __launch_bounds__(256) void rope_kernel(float* __restrict__ q, float* __restrict__ k)
{
    int idx = blockIdx.x * 256 + threadIdx.x;
    int d = idx & 63;
    int rest = idx >> 6;
    int h = rest & (Hx - 1);
    int tok = rest >> 4;
    int s = tok & (Sx - 1);

    float freq = expf(-(float)d * (9.21034037197618f / 64.0f));
    float ang = (float)s * freq;
    float c, sn;
    sincosf(ang, &sn, &c);

    size_t base = (size_t)tok * Dx + h * HDx;
    float q1 = q[base + d], q2 = q[base + d + 64];
    q[base + d]      = q1 * c - q2 * sn;
    q[base + d + 64] = q2 * c + q1 * sn;
    float k1 = k[base + d], k2 = k[base + d + 64];
    k[base + d]      = k1 * c - k2 * sn;
    k[base + d + 64] = k2 * c + k1 * sn;
}

// ================= tensor-core flash attention =================
#define KSTR 132
#define VSTR 136
#define PSTR 68
#define FA_SMEM_BYTES ((64 * KSTR + 64 * VSTR + 4 * 16 * PSTR) * 4)   // 86016

__global__ __launch_bounds__(128) void fattn_kernel(
    const float* __restrict__ q, const float* __restrict__ k,
    const float* __restrict__ v, float* __restrict__ o)
{
    extern __shared__ float fs[];
    float* Ks = fs;
    float* Vs = fs + 64 * KSTR;
    uint32_t* Ps = (uint32_t*)(fs + 64 * KSTR + 64 * VSTR);

    const int bh = blockIdx.x;
    const int b = bh >> 4;
    const int h = bh & (Hx - 1);
    const int qt = blockIdx.y;
    const int tid = threadIdx.x;
    const int lane = tid & 31;
    const int w = tid >> 5;
    const int g = lane >> 2;
    const int t = lane & 3;

    const float* Qg = q + ((size_t)(b * Sx + qt * 64)) * Dx + h * HDx;
    const float* Kg = k + ((size_t)b * Sx) * Dx + h * HDx;
    const float* Vg = v + ((size_t)b * Sx) * Dx + h * HDx;

    for (int i = tid; i < 64 * 32; i += 128) {
        int r = i >> 5, c4 = (i & 31) * 4;
        *(float4*)&Ks[r * KSTR + c4] = *(const float4*)(Qg + (size_t)r * Dx + c4);
    }
    __syncthreads();

    const float qscale = 0.08838834764831843f;
    uint32_t qf[16][4];
#pragma unroll
    for (int s = 0; s < 16; s++) {
        const float* r0 = &Ks[(w * 16 + g) * KSTR + s * 8];
        const float* r1 = r0 + 8 * KSTR;
        qf[s][0] = f2tf32(r0[t] * qscale);
        qf[s][1] = f2tf32(r1[t] * qscale);
        qf[s][2] = f2tf32(r0[t + 4] * qscale);
        qf[s][3] = f2tf32(r1[t + 4] * qscale);
    }
    __syncthreads();

    float acc_o[16][4];
#pragma unroll
    for (int n = 0; n < 16; n++)
#pragma unroll
        for (int c = 0; c < 4; c++) acc_o[n][c] = 0.f;

    float m0 = -1e30f, m1 = -1e30f, l0 = 0.f, l1 = 0.f;
    const int q0 = qt * 64 + w * 16;

    for (int kt = 0; kt <= qt; kt++) {
#pragma unroll
        for (int i = 0; i < 16; i++) {
            int f = tid + i * 128;
            int r = f >> 5, c4 = (f & 31) * 4;
            cp16(&Ks[r * KSTR + c4], Kg + (size_t)(kt * 64 + r) * Dx + c4);
        }
        asm volatile("cp.async.commit_group;\n");
#pragma unroll
        for (int i = 0; i < 16; i++) {
            int f = tid + i * 128;
            int r = f >> 5, c4 = (f & 31) * 4;
            cp16(&Vs[r * VSTR + c4], Vg + (size_t)(kt * 64 + r) * Dx + c4);
        }
        asm volatile("cp.async.commit_group;\n");
        asm volatile("cp.async.wait_group 1;\n");
        __syncthreads();

        float sacc[8][4];
#pragma unroll
        for (int n = 0; n < 8; n++)
#pragma unroll
            for (int c = 0; c < 4; c++) sacc[n][c] = 0.f;

#pragma unroll
        for (int s = 0; s < 16; s++) {
#pragma unroll
            for (int n = 0; n < 8; n++) {
                uint32_t bf[2];
                const float* kr = &Ks[(n * 8 + g) * KSTR + s * 8];
                bf[0] = f2tf32(kr[t]);
                bf[1] = f2tf32(kr[t + 4]);
                mma_tf32(sacc[n], qf[s], bf);
            }
        }

        if (kt == qt) {
#pragma unroll
            for (int n = 0; n < 8; n++) {
                int key = kt * 64 + n * 8 + 2 * t;
                if (key     > q0 + g)     sacc[n][0] = -1e30f;
                if (key + 1 > q0 + g)     sacc[n][1] = -1e30f;
                if (key     > q0 + g + 8) sacc[n][2] = -1e30f;
                if (key + 1 > q0 + g + 8) sacc[n][3] = -1e30f;
            }
        }

        float rm0 = -1e30f, rm1 = -1e30f;
#pragma unroll
        for (int n = 0; n < 8; n++) {
            rm0 = fmaxf(rm0, fmaxf(sacc[n][0], sacc[n][1]));
            rm1 = fmaxf(rm1, fmaxf(sacc[n][2], sacc[n][3]));
        }
        rm0 = fmaxf(rm0, __shfl_xor_sync(0xffffffffu, rm0, 1));
        rm0 = fmaxf(rm0, __shfl_xor_sync(0xffffffffu, rm0, 2));
        rm1 = fmaxf(rm1, __shfl_xor_sync(0xffffffffu, rm1, 1));
        rm1 = fmaxf(rm1, __shfl_xor_sync(0xffffffffu, rm1, 2));

        float nm0 = fmaxf(m0, rm0), nm1 = fmaxf(m1, rm1);
        float c0 = __expf(m0 - nm0), c1 = __expf(m1 - nm1);

        uint32_t* pw = Ps + (w * 16 + g) * PSTR;
        float rs0 = 0.f, rs1 = 0.f;
#pragma unroll
        for (int n = 0; n < 8; n++) {
            float p00 = __expf(sacc[n][0] - nm0);
            float p01 = __expf(sacc[n][1] - nm0);
            float p10 = __expf(sacc[n][2] - nm1);
            float p11 = __expf(sacc[n][3] - nm1);
            rs0 += p00 + p01;
            rs1 += p10 + p11;
            uint2 u0 = make_uint2(f2tf32(p00), f2tf32(p01));
            uint2 u1 = make_uint2(f2tf32(p10), f2tf32(p11));
            *(uint2*)&pw[n * 8 + 2 * t]            = u0;
            *(uint2*)&pw[8 * PSTR + n * 8 + 2 * t] = u1;
        }
        rs0 += __shfl_xor_sync(0xffffffffu, rs0, 1);
        rs0 += __shfl_xor_sync(0xffffffffu, rs0, 2);
        rs1 += __shfl_xor_sync(0xffffffffu, rs1, 1);
        rs1 += __shfl_xor_sync(0xffffffffu, rs1, 2);

        l0 = l0 * c0 + rs0;
        l1 = l1 * c1 + rs1;
        m0 = nm0; m1 = nm1;

#pragma unroll
        for (int n = 0; n < 16; n++) {
            acc_o[n][0] *= c0; acc_o[n][1] *= c0;
            acc_o[n][2] *= c1; acc_o[n][3] *= c1;
        }
        __syncwarp();

        uint32_t pf[8][4];
#pragma unroll
        for (int s = 0; s < 8; s++) {
            const uint32_t* pr0 = Ps + (w * 16 + g) * PSTR + s * 8;
            const uint32_t* pr1 = pr0 + 8 * PSTR;
            pf[s][0] = pr0[t];
            pf[s][1] = pr1[t];
            pf[s][2] = pr0[t + 4];
            pf[s][3] = pr1[t + 4];
        }

        asm volatile("cp.async.wait_group 0;\n");
        __syncthreads();

#pragma unroll
        for (int s = 0; s < 8; s++) {
#pragma unroll
            for (int n = 0; n < 16; n++) {
                uint32_t bf[2];
                bf[0] = f2tf32(Vs[(s * 8 + t) * VSTR + n * 8 + g]);
                bf[1] = f2tf32(Vs[(s * 8 + t + 4) * VSTR + n * 8 + g]);
                mma_tf32(acc_o[n], pf[s], bf);
            }
        }
        __syncthreads();
    }

    float inv0 = __fdividef(1.0f, l0);
    float inv1 = __fdividef(1.0f, l1);
    size_t tok0 = (size_t)(b * Sx + q0 + g);
    size_t tok1 = tok0 + 8;
    float* o0 = o + tok0 * Dx + h * HDx;
    float* o1 = o + tok1 * Dx + h * HDx;
    // tf32-round output: feeds O-projection's raw-bit A path
#pragma unroll
    for (int n = 0; n < 16; n++) {
        int col = n * 8 + 2 * t;
        *(float2*)&o0[col] = make_float2(rnd_tf32(acc_o[n][0] * inv0), rnd_tf32(acc_o[n][1] * inv0));
        *(float2*)&o1[col] = make_float2(rnd_tf32(acc_o[n][2] * inv1), rnd_tf32(acc_o[n][3] * inv1));
    }
}

// ---------------- zero expert counters ----------------
__global__ void zero_cnt_kernel(int* cnt)
{
    if (threadIdx.x < Ex) cnt[threadIdx.x] = 0;
}

// ---------------- MoE gate: top-2 scatter into per-expert lists ----------------
__global__ __launch_bounds__(256) void gate_kernel(
    const float* __restrict__ x, const float* __restrict__ wg,
    int* __restrict__ cnt, int* __restrict__ list, float* __restrict__ wgt)
{
    int warp = threadIdx.x >> 5;
    int lane = threadIdx.x & 31;
    int t = blockIdx.x * 8 + warp;
    const float* xr = x + (size_t)t * Dx;

    float a0 = 0.f, a1 = 0.f, a2 = 0.f, a3 = 0.f;
    for (int d = lane; d < Dx; d += 32) {
        float xv = xr[d];
        float4 w4 = ((const float4*)wg)[d];
        a0 = fmaf(xv, w4.x, a0);
        a1 = fmaf(xv, w4.y, a1);
        a2 = fmaf(xv, w4.z, a2);
        a3 = fmaf(xv, w4.w, a3);
    }
#pragma unroll
    for (int off = 16; off >= 1; off >>= 1) {
        a0 += __shfl_xor_sync(0xffffffffu, a0, off);
        a1 += __shfl_xor_sync(0xffffffffu, a1, off);
        a2 += __shfl_xor_sync(0xffffffffu, a2, off);
        a3 += __shfl_xor_sync(0xffffffffu, a3, off);
    }
    if (lane == 0) {
        float lg[4] = {a0, a1, a2, a3};
        float mx = fmaxf(fmaxf(lg[0], lg[1]), fmaxf(lg[2], lg[3]));
        float e[4], sum = 0.f;
#pragma unroll
        for (int i = 0; i < 4; i++) { e[i] = expf(lg[i] - mx); sum += e[i]; }
        float p[4];
#pragma unroll
        for (int i = 0; i < 4; i++) p[i] = e[i] / sum;

        int i0 = 0;
#pragma unroll
        for (int i = 1; i < 4; i++) if (p[i] > p[i0]) i0 = i;
        int i1 = (i0 == 0) ? 1 : 0;
#pragma unroll
        for (int i = 0; i < 4; i++) if (i != i0 && p[i] > p[i1]) i1 = i;

        float hi = fmaxf(p[i0], p[i1]);
        float ea = expf(p[i0] - hi), eb = expf(p[i1] - hi);
        float inv = 1.0f / (ea + eb);
        float w0 = ea * inv, w1 = eb * inv;

        int s0 = atomicAdd(&cnt[i0], 1);
        list[i0 * Tx + s0] = t;
        wgt [i0 * Tx + s0] = w0;
        int s1 = atomicAdd(&cnt[i1], 1);
        list[i1 * Tx + s1] = t;
        wgt [i1 * Tx + s1] = w1;
    }
}

// ---------------- host launcher ----------------
extern "C" void kernel_launch(void* const* d_in, const int* in_sizes, int n_in,
                              void* d_out, int out_size)
{
    const float* hidden = (const float*)d_in[0];
    const float* wq   = (const float*)d_in[1];
    const float* bq   = (const float*)d_in[2];
    const float* wk   = (const float*)d_in[3];
    const float* bk   = (const float*)d_in[4];
    const float* wv   = (const float*)d_in[5];
    const float* bv   = (const float*)d_in[6];
    const float* wo   = (const float*)d_in[7];
    const float* bo   = (const float*)d_in[8];
    const float* ln1w = (const float*)d_in[9];
    const float* ln1b = (const float*)d_in[10];
    const float* ln2w = (const float*)d_in[11];
    const float* ln2b = (const float*)d_in[12];
    const float* wgate= (const float*)d_in[13];
    const float* we1  = (const float*)d_in[14];
    const float* be1  = (const float*)d_in[15];
    const float* we2  = (const float*)d_in[16];
    const float* be2  = (const float*)d_in[17];
    float* out = (float*)d_out;

    float *x1, *q, *k, *v, *attn, *x2, *hmid, *wgt;
    int *cnt, *list;
    cudaGetSymbolAddress((void**)&x1,   g_x1);
    cudaGetSymbolAddress((void**)&q,    g_q);
    cudaGetSymbolAddress((void**)&k,    g_k);
    cudaGetSymbolAddress((void**)&v,    g_v);
    cudaGetSymbolAddress((void**)&attn, g_attn);
    cudaGetSymbolAddress((void**)&x2,   g_x2);
    cudaGetSymbolAddress((void**)&hmid, g_hmid);
    cudaGetSymbolAddress((void**)&cnt,  g_cnt);
    cudaGetSymbolAddress((void**)&list, g_list);
    cudaGetSymbolAddress((void**)&wgt,  g_wgt);

    cudaFuncSetAttribute(gemm_qkv, cudaFuncAttributeMaxDynamicSharedMemorySize, GEMM_SMEM_BYTES);
    cudaFuncSetAttribute(gemm_o,   cudaFuncAttributeMaxDynamicSharedMemorySize, GEMM_SMEM_BYTES);
    cudaFuncSetAttribute(moe_up,   cudaFuncAttributeMaxDynamicSharedMemorySize, GEMM_SMEM_BYTES);
    cudaFuncSetAttribute(moe_dn,   cudaFuncAttributeMaxDynamicSharedMemorySize, GEMM_SMEM_BYTES);
    cudaFuncSetAttribute(fattn_kernel, cudaFuncAttributeMaxDynamicSharedMemorySize, FA_SMEM_BYTES);

    // 1) LN1 (tf32-rounded: QKV GEMM feeds A raw)
    ln_kernel<true><<<Tx, 256>>>(hidden, ln1w, ln1b, x1);
    // 2) fused QKV projections
    gemm_qkv<<<dim3(Dx / BN, Tx / BM, 3), 256, GEMM_SMEM_BYTES>>>(
        x1, wq, wk, wv, bq, bk, bv, q, k, v);
    // 3) RoPE
    rope_kernel<<<(Tx * Hx * 64) / 256, 256>>>(q, k);
    // 4) flash attention (tf32-rounded output)
    fattn_kernel<<<dim3(Bx * Hx, Sx / 64), 128, FA_SMEM_BYTES>>>(q, k, v, attn);
    // 5) O-projection + residual
    gemm_o<<<dim3(Dx / BN, Tx / BM), 256, GEMM_SMEM_BYTES>>>(attn, wo, bo, out, hidden);
    // 6) LN2 (NOT rounded: gate must see full precision to keep routing stable)
    ln_kernel<false><<<Tx, 256>>>(out, ln2w, ln2b, x2);
    // 7) gate: zero counters, then top-2 scatter
    zero_cnt_kernel<<<1, 32>>>(cnt);
    gate_kernel<<<Tx / 8, 256>>>(x2, wgate, cnt, list, wgt);
    // 8) fused sparse MoE: all experts in one up launch + one atomic down launch
    moe_up<<<dim3(Ix / BN, Tx / BM, Ex), 256, GEMM_SMEM_BYTES>>>(
        x2, we1, be1, hmid, list, cnt);
    moe_dn<<<dim3(Dx / BN, Tx / BM, Ex), 256, GEMM_SMEM_BYTES>>>(
        hmid, we2, be2, out, list, wgt, cnt);
}

// round 12
// speedup vs baseline: 6.9808x; 1.0381x over previous
#include <cuda_runtime.h>
#include <math.h>
#include <stdint.h>

// ---------------- problem constants ----------------
#define Bx   2
#define Sx   2048
#define Dx   2048
#define Hx   16
#define HDx  128
#define Ex   4
#define Ix   2048
#define Tx   (Bx * Sx)          // 4096 tokens

// ---------------- scratch (static device globals; no runtime alloc) ----------------
__device__ float g_x1  [(size_t)Tx * Dx];        // LN1 out; later reused as x2r
__device__ float g_q   [(size_t)Tx * Dx];
__device__ float g_k   [(size_t)Tx * Dx];
__device__ float g_v   [(size_t)Tx * Dx];
__device__ float g_attn[(size_t)Tx * Dx];
__device__ float g_x2  [(size_t)Tx * Dx];
__device__ float g_hmid[(size_t)Ex * Tx * Ix];   // per-expert compact mid activations
__device__ int   g_cnt [Ex];
__device__ int   g_list[Ex * Tx];
__device__ float g_wgt [Ex * Tx];
__device__ float g_wr  [(size_t)12 * Dx * Dx];   // tf32-pre-rounded weights

__device__ __forceinline__ uint32_t f2tf32(float x) {
    uint32_t u;
    asm volatile("cvt.rna.tf32.f32 %0, %1;\n" : "=r"(u) : "f"(x));
    return u;
}
__device__ __forceinline__ float rnd_tf32(float x) {
    return __uint_as_float(f2tf32(x));
}
__device__ __forceinline__ void mma_tf32(float* d, const uint32_t* a, const uint32_t* b) {
    asm volatile(
        "mma.sync.aligned.m16n8k8.row.col.f32.tf32.tf32.f32 "
        "{%0,%1,%2,%3}, {%4,%5,%6,%7}, {%8,%9}, {%0,%1,%2,%3};\n"
        : "+f"(d[0]), "+f"(d[1]), "+f"(d[2]), "+f"(d[3])
        : "r"(a[0]), "r"(a[1]), "r"(a[2]), "r"(a[3]), "r"(b[0]), "r"(b[1]));
}
__device__ __forceinline__ void cp16(float* dst, const float* src) {
    uint32_t d = (uint32_t)__cvta_generic_to_shared(dst);
    asm volatile("cp.async.cg.shared.global [%0], [%1], 16;\n" :: "r"(d), "l"(src));
}

// ---------------- weight pre-round: 12 matrices -> g_wr (tf32 rna) ----------------
__global__ __launch_bounds__(256) void round_w_kernel(
    const float* __restrict__ wq, const float* __restrict__ wk,
    const float* __restrict__ wv, const float* __restrict__ wo,
    const float* __restrict__ we1, const float* __restrict__ we2,
    float* __restrict__ wr)
{
    int z = blockIdx.z;
    const float* src;
    if      (z == 0) src = wq;
    else if (z == 1) src = wk;
    else if (z == 2) src = wv;
    else if (z == 3) src = wo;
    else if (z < 8)  src = we1 + (size_t)(z - 4) * Dx * Ix;
    else             src = we2 + (size_t)(z - 8) * Ix * Dx;
    float* dst = wr + (size_t)z * Dx * Dx;

    size_t i = ((size_t)blockIdx.x * 256 + threadIdx.x) * 4;
    float4 vv = *(const float4*)(src + i);
    vv.x = rnd_tf32(vv.x); vv.y = rnd_tf32(vv.y);
    vv.z = rnd_tf32(vv.z); vv.w = rnd_tf32(vv.w);
    *(float4*)(dst + i) = vv;
}

// ---------------- LayerNorm ----------------
// ROUND: tf32-round y. DUAL: additionally write rounded copy to y2 (y stays full).
template <bool ROUND, bool DUAL>
__global__ __launch_bounds__(256) void ln_kernel(
    const float* __restrict__ x, const float* __restrict__ w,
    const float* __restrict__ b, float* __restrict__ y, float* __restrict__ y2)
{
    __shared__ float red[8];
    int row = blockIdx.x;
    int t = threadIdx.x;
    const float* xr = x + (size_t)row * Dx;

    float v[8];
    float s = 0.f;
#pragma unroll
    for (int i = 0; i < 8; i++) { v[i] = xr[t + i * 256]; s += v[i]; }
#pragma unroll
    for (int off = 16; off >= 1; off >>= 1) s += __shfl_xor_sync(0xffffffffu, s, off);
    if ((t & 31) == 0) red[t >> 5] = s;
    __syncthreads();
    float tot = red[0] + red[1] + red[2] + red[3] + red[4] + red[5] + red[6] + red[7];
    float mu = tot * (1.0f / (float)Dx);

    float s2 = 0.f;
#pragma unroll
    for (int i = 0; i < 8; i++) { float d = v[i] - mu; s2 += d * d; }
    __syncthreads();
#pragma unroll
    for (int off = 16; off >= 1; off >>= 1) s2 += __shfl_xor_sync(0xffffffffu, s2, off);
    if ((t & 31) == 0) red[t >> 5] = s2;
    __syncthreads();
    float tot2 = red[0] + red[1] + red[2] + red[3] + red[4] + red[5] + red[6] + red[7];
    float var = tot2 * (1.0f / (float)Dx);
    float r = rsqrtf(var + 1e-5f);

    float* yr = y + (size_t)row * Dx;
    float* yr2 = DUAL ? (y2 + (size_t)row * Dx) : nullptr;
#pragma unroll
    for (int i = 0; i < 8; i++) {
        int c = t + i * 256;
        float val = (v[i] - mu) * r * w[c] + b[c];
        yr[c] = ROUND ? rnd_tf32(val) : val;
        if (DUAL) yr2[c] = rnd_tf32(val);
    }
}

// ================= shared tf32 mma.sync GEMM body (cvt-free inner loop) =================
// All A/B inputs are pre-rounded to tf32 in gmem; fragments feed raw bits.
// MODE 0: C = AB + bias
// MODE 1: C = AB + bias + extra (residual [M,N])
// MODE 2: A rows gathered via gidx; C = rnd_tf32(gelu(AB+bias)), compact rows
// MODE 3: A compact; atomicAdd(C[gidx[m]], gw[m]*(AB+bias))
#define BM 128
#define BN 128
#define BK 32
#define APAD 4
#define BPAD 8
#define ASZ (BM * (BK + APAD))
#define BSZ (BK * (BN + BPAD))
#define GEMM_SMEM_BYTES ((2 * ASZ + 2 * BSZ) * 4)   // 71680

template <int MODE>
__device__ __forceinline__ void gemm_body(
    float* sm, const float* A, const float* B,
    const float* bias, float* C, const float* extra,
    const int* gidx, const float* gw, int cnt,
    int N, int K, int m0, int n0)
{
    float* As0 = sm;
    float* Bs0 = sm + 2 * ASZ;

    const int tid  = threadIdx.x;
    const int lane = tid & 31;
    const int wid  = tid >> 5;
    const int g = lane >> 2;
    const int t = lane & 3;
    const int wm = wid >> 2;
    const int wn = wid & 3;

    float acc[4][4][4];
#pragma unroll
    for (int i = 0; i < 4; i++)
#pragma unroll
        for (int j = 0; j < 4; j++)
#pragma unroll
            for (int c = 0; c < 4; c++) acc[i][j][c] = 0.f;

    int asrc[4];
#pragma unroll
    for (int u = 0; u < 4; u++) {
        int gr = m0 + (tid >> 3) + 32 * u;
        if (gr >= cnt) gr = cnt - 1;
        asrc[u] = (MODE == 2) ? gidx[gr] : gr;
    }

    auto loadTile = [&](int k0, int buf) {
        float* Ad = As0 + buf * ASZ;
        float* Bd = Bs0 + buf * BSZ;
#pragma unroll
        for (int i = 0; i < 4; i++) {
            int row = (tid >> 3) + 32 * i;
            int kq  = (tid & 7) * 4;
            cp16(Ad + row * (BK + APAD) + kq,
                 A + (size_t)asrc[i] * K + k0 + kq);
        }
#pragma unroll
        for (int i = 0; i < 4; i++) {
            int f = tid + i * 256;
            int kr = f >> 5;
            int nc = (f & 31) * 4;
            cp16(Bd + kr * (BN + BPAD) + nc,
                 B + (size_t)(k0 + kr) * N + n0 + nc);
        }
        asm volatile("cp.async.commit_group;\n");
    };

    const int ntiles = K / BK;
    loadTile(0, 0);

    for (int tile = 0; tile < ntiles; tile++) {
        int buf = tile & 1;
        if (tile + 1 < ntiles) {
            loadTile((tile + 1) * BK, buf ^ 1);
            asm volatile("cp.async.wait_group 1;\n");
        } else {
            asm volatile("cp.async.wait_group 0;\n");
        }
        __syncthreads();

        const float* Ab = As0 + buf * ASZ;
        const float* Bb = Bs0 + buf * BSZ;

#pragma unroll
        for (int kk = 0; kk < BK / 8; kk++) {
            const int k = kk * 8;
            uint32_t af[4][4];
            uint32_t bf[4][2];
#pragma unroll
            for (int mi = 0; mi < 4; mi++) {
                int r = wm * 64 + mi * 16 + g;
                const float* ar0 = Ab + (size_t)r * (BK + APAD) + k;
                const float* ar1 = ar0 + 8 * (BK + APAD);
                af[mi][0] = __float_as_uint(ar0[t]);
                af[mi][1] = __float_as_uint(ar1[t]);
                af[mi][2] = __float_as_uint(ar0[t + 4]);
                af[mi][3] = __float_as_uint(ar1[t + 4]);
            }
#pragma unroll
            for (int ni = 0; ni < 4; ni++) {
                int c = wn * 32 + ni * 8 + g;
                bf[ni][0] = __float_as_uint(Bb[(size_t)(k + t) * (BN + BPAD) + c]);
                bf[ni][1] = __float_as_uint(Bb[(size_t)(k + t + 4) * (BN + BPAD) + c]);
            }
#pragma unroll
            for (int mi = 0; mi < 4; mi++)
#pragma unroll
                for (int ni = 0; ni < 4; ni++)
                    mma_tf32(acc[mi][ni], af[mi], bf[ni]);
        }
        __syncthreads();
    }

#pragma unroll
    for (int mi = 0; mi < 4; mi++) {
        int r0 = m0 + wm * 64 + mi * 16 + g;
        int r1 = r0 + 8;
        bool v0 = r0 < cnt, v1 = r1 < cnt;
        int d0 = 0, d1 = 0;
        float s0 = 0.f, s1 = 0.f;
        if (MODE == 3) {
            if (v0) { d0 = gidx[r0]; s0 = gw[r0]; }
            if (v1) { d1 = gidx[r1]; s1 = gw[r1]; }
        }
#pragma unroll
        for (int ni = 0; ni < 4; ni++) {
            int c = n0 + wn * 32 + ni * 8 + t * 2;
            float2 b2 = *(const float2*)&bias[c];
            float v00 = acc[mi][ni][0] + b2.x;
            float v01 = acc[mi][ni][1] + b2.y;
            float v10 = acc[mi][ni][2] + b2.x;
            float v11 = acc[mi][ni][3] + b2.y;
            if (MODE == 0 || MODE == 1) {
                if (MODE == 1) {
                    float2 e0 = *(const float2*)&extra[(size_t)r0 * N + c];
                    float2 e1 = *(const float2*)&extra[(size_t)r1 * N + c];
                    v00 += e0.x; v01 += e0.y;
                    v10 += e1.x; v11 += e1.y;
                }
                *(float2*)&C[(size_t)r0 * N + c] = make_float2(v00, v01);
                *(float2*)&C[(size_t)r1 * N + c] = make_float2(v10, v11);
            } else if (MODE == 2) {
                v00 = rnd_tf32(0.5f * v00 * (1.0f + erff(v00 * 0.70710678118654752f)));
                v01 = rnd_tf32(0.5f * v01 * (1.0f + erff(v01 * 0.70710678118654752f)));
                v10 = rnd_tf32(0.5f * v10 * (1.0f + erff(v10 * 0.70710678118654752f)));
                v11 = rnd_tf32(0.5f * v11 * (1.0f + erff(v11 * 0.70710678118654752f)));
                if (v0) *(float2*)&C[(size_t)r0 * N + c] = make_float2(v00, v01);
                if (v1) *(float2*)&C[(size_t)r1 * N + c] = make_float2(v10, v11);
            } else {
                if (v0) {
                    atomicAdd(&C[(size_t)d0 * N + c],     s0 * v00);
                    atomicAdd(&C[(size_t)d0 * N + c + 1], s0 * v01);
                }
                if (v1) {
                    atomicAdd(&C[(size_t)d1 * N + c],     s1 * v10);
                    atomicAdd(&C[(size_t)d1 * N + c + 1], s1 * v11);
                }
            }
        }
    }
}

// ---------------- fused QKV: blockIdx.z selects projection ----------------
__global__ __launch_bounds__(256, 2) void gemm_qkv(
    const float* __restrict__ A, const float* __restrict__ wr,
    const float* __restrict__ bq, const float* __restrict__ bk, const float* __restrict__ bv,
    float* __restrict__ Cq, float* __restrict__ Ck, float* __restrict__ Cv)
{
    extern __shared__ float sm[];
    int z = blockIdx.z;
    const float* B = wr + (size_t)z * Dx * Dx;
    const float* bb = (z == 0) ? bq : (z == 1) ? bk : bv;
    float* C = (z == 0) ? Cq : (z == 1) ? Ck : Cv;
    gemm_body<0>(sm, A, B, bb, C, nullptr, nullptr, nullptr,
                 Tx, Dx, Dx, blockIdx.y * BM, blockIdx.x * BN);
}

// ---------------- O-projection + residual ----------------
__global__ __launch_bounds__(256, 2) void gemm_o(
    const float* __restrict__ A, const float* __restrict__ B,
    const float* __restrict__ bias, float* __restrict__ C,
    const float* __restrict__ extra)
{
    extern __shared__ float sm[];
    gemm_body<1>(sm, A, B, bias, C, extra, nullptr, nullptr,
                 Tx, Dx, Dx, blockIdx.y * BM, blockIdx.x * BN);
}

// ---------------- fused MoE up: blockIdx.z = expert ----------------
__global__ __launch_bounds__(256, 2) void moe_up(
    const float* __restrict__ x2r, const float* __restrict__ wr,
    const float* __restrict__ be1, float* __restrict__ hmid,
    const int* __restrict__ list, const int* __restrict__ cnt)
{
    extern __shared__ float sm[];
    int z = blockIdx.z;
    int c = cnt[z];
    int m0 = blockIdx.y * BM;
    if (m0 >= c) return;
    gemm_body<2>(sm,
        x2r, wr + (size_t)(4 + z) * Dx * Dx, be1 + (size_t)z * Ix,
        hmid + (size_t)z * Tx * Ix,
        nullptr, list + z * Tx, nullptr, c,
        Ix, Dx, m0, blockIdx.x * BN);
}

// ---------------- fused MoE down: blockIdx.z = expert, atomic scatter ----------------
__global__ __launch_bounds__(256, 2) void moe_dn(
    const float* __restrict__ hmid, const float* __restrict__ wr,
    const float* __restrict__ be2, float* __restrict__ out,
    const int* __restrict__ list, const float* __restrict__ wgt,
    const int* __restrict__ cnt)
{
    extern __shared__ float sm[];
    int z = blockIdx.z;
    int c = cnt[z];
    int m0 = blockIdx.y * BM;
    if (m0 >= c) return;
    gemm_body<3>(sm,
        hmid + (size_t)z * Tx * Ix, wr + (size_t)(8 + z) * Dx * Dx,
        be2 + (size_t)z * Dx, out,
        nullptr, list + z * Tx, wgt + z * Tx, c,
        Dx, Ix, m0, blockIdx.x * BN);
}

// ---------------- RoPE ----------------
__global__ __launch_bounds__(256) void rope_kernel(float* __restrict__ q, float* __restrict__ k)
{
    int idx = blockIdx.x * 256 + threadIdx.x;
    int d = idx & 63;
    int rest = idx >> 6;
    int h = rest & (Hx - 1);
    int tok = rest >> 4;
    int s = tok & (Sx - 1);

    float freq = expf(-(float)d * (9.21034037197618f / 64.0f));
    float ang = (float)s * freq;
    float c, sn;
    sincosf(ang, &sn, &c);

    size_t base = (size_t)tok * Dx + h * HDx;
    float q1 = q[base + d], q2 = q[base + d + 64];
    q[base + d]      = q1 * c - q2 * sn;
    q[base + d + 64] = q2 * c + q1 * sn;
    float k1 = k[base + d], k2 = k[base + d + 64];
    k[base + d]      = k1 * c - k2 * sn;
    k[base + d + 64] = k2 * c + k1 * sn;
}

// ================= tensor-core flash attention =================
#define KSTR 132
#define VSTR 136
#define PSTR 68
#define FA_SMEM_BYTES ((64 * KSTR + 64 * VSTR + 4 * 16 * PSTR) * 4)   // 86016

__global__ __launch_bounds__(128) void fattn_kernel(
    const float* __restrict__ q, const float* __restrict__ k,
    const float* __restrict__ v, float* __restrict__ o)
{
    extern __shared__ float fs[];
    float* Ks = fs;
    float* Vs = fs + 64 * KSTR;
    uint32_t* Ps = (uint32_t*)(fs + 64 * KSTR + 64 * VSTR);

    const int bh = blockIdx.x;
    const int b = bh >> 4;
    const int h = bh & (Hx - 1);
    const int qt = gridDim.y - 1 - blockIdx.y;   // longest tiles scheduled first
    const int tid = threadIdx.x;
    const int lane = tid & 31;
    const int w = tid >> 5;
    const int g = lane >> 2;
    const int t = lane & 3;

    const float* Qg = q + ((size_t)(b * Sx + qt * 64)) * Dx + h * HDx;
    const float* Kg = k + ((size_t)b * Sx) * Dx + h * HDx;
    const float* Vg = v + ((size_t)b * Sx) * Dx + h * HDx;

    for (int i = tid; i < 64 * 32; i += 128) {
        int r = i >> 5, c4 = (i & 31) * 4;
        *(float4*)&Ks[r * KSTR + c4] = *(const float4*)(Qg + (size_t)r * Dx + c4);
    }
    __syncthreads();

    const float qscale = 0.08838834764831843f;
    uint32_t qf[16][4];
#pragma unroll
    for (int s = 0; s < 16; s++) {
        const float* r0 = &Ks[(w * 16 + g) * KSTR + s * 8];
        const float* r1 = r0 + 8 * KSTR;
        qf[s][0] = f2tf32(r0[t] * qscale);
        qf[s][1] = f2tf32(r1[t] * qscale);
        qf[s][2] = f2tf32(r0[t + 4] * qscale);
        qf[s][3] = f2tf32(r1[t + 4] * qscale);
    }
    __syncthreads();

    float acc_o[16][4];
#pragma unroll
    for (int n = 0; n < 16; n++)
#pragma unroll
        for (int c = 0; c < 4; c++) acc_o[n][c] = 0.f;

    float m0 = -1e30f, m1 = -1e30f, l0 = 0.f, l1 = 0.f;
    const int q0 = qt * 64 + w * 16;

    for (int kt = 0; kt <= qt; kt++) {
#pragma unroll
        for (int i = 0; i < 16; i++) {
            int f = tid + i * 128;
            int r = f >> 5, c4 = (f & 31) * 4;
            cp16(&Ks[r * KSTR + c4], Kg + (size_t)(kt * 64 + r) * Dx + c4);
        }
        asm volatile("cp.async.commit_group;\n");
#pragma unroll
        for (int i = 0; i < 16; i++) {
            int f = tid + i * 128;
            int r = f >> 5, c4 = (f & 31) * 4;
            cp16(&Vs[r * VSTR + c4], Vg + (size_t)(kt * 64 + r) * Dx + c4);
        }
        asm volatile("cp.async.commit_group;\n");
        asm volatile("cp.async.wait_group 1;\n");
        __syncthreads();

        float sacc[8][4];
#pragma unroll
        for (int n = 0; n < 8; n++)
#pragma unroll
            for (int c = 0; c < 4; c++) sacc[n][c] = 0.f;

#pragma unroll
        for (int s = 0; s < 16; s++) {
#pragma unroll
            for (int n = 0; n < 8; n++) {
                uint32_t bf[2];
                const float* kr = &Ks[(n * 8 + g) * KSTR + s * 8];
                bf[0] = f2tf32(kr[t]);
                bf[1] = f2tf32(kr[t + 4]);
                mma_tf32(sacc[n], qf[s], bf);
            }
        }

        if (kt == qt) {
#pragma unroll
            for (int n = 0; n < 8; n++) {
                int key = kt * 64 + n * 8 + 2 * t;
                if (key     > q0 + g)     sacc[n][0] = -1e30f;
                if (key + 1 > q0 + g)     sacc[n][1] = -1e30f;
                if (key     > q0 + g + 8) sacc[n][2] = -1e30f;
                if (key + 1 > q0 + g + 8) sacc[n][3] = -1e30f;
            }
        }

        float rm0 = -1e30f, rm1 = -1e30f;
#pragma unroll
        for (int n = 0; n < 8; n++) {
            rm0 = fmaxf(rm0, fmaxf(sacc[n][0], sacc[n][1]));
            rm1 = fmaxf(rm1, fmaxf(sacc[n][2], sacc[n][3]));
        }
        rm0 = fmaxf(rm0, __shfl_xor_sync(0xffffffffu, rm0, 1));
        rm0 = fmaxf(rm0, __shfl_xor_sync(0xffffffffu, rm0, 2));
        rm1 = fmaxf(rm1, __shfl_xor_sync(0xffffffffu, rm1, 1));
        rm1 = fmaxf(rm1, __shfl_xor_sync(0xffffffffu, rm1, 2));

        float nm0 = fmaxf(m0, rm0), nm1 = fmaxf(m1, rm1);
        float c0 = __expf(m0 - nm0), c1 = __expf(m1 - nm1);

        uint32_t* pw = Ps + (w * 16 + g) * PSTR;
        float rs0 = 0.f, rs1 = 0.f;
#pragma unroll
        for (int n = 0; n < 8; n++) {
            float p00 = __expf(sacc[n][0] - nm0);
            float p01 = __expf(sacc[n][1] - nm0);
            float p10 = __expf(sacc[n][2] - nm1);
            float p11 = __expf(sacc[n][3] - nm1);
            rs0 += p00 + p01;
            rs1 += p10 + p11;
            uint2 u0 = make_uint2(f2tf32(p00), f2tf32(p01));
            uint2 u1 = make_uint2(f2tf32(p10), f2tf32(p11));
            *(uint2*)&pw[n * 8 + 2 * t]            = u0;
            *(uint2*)&pw[8 * PSTR + n * 8 + 2 * t] = u1;
        }
        rs0 += __shfl_xor_sync(0xffffffffu, rs0, 1);
        rs0 += __shfl_xor_sync(0xffffffffu, rs0, 2);
        rs1 += __shfl_xor_sync(0xffffffffu, rs1, 1);
        rs1 += __shfl_xor_sync(0xffffffffu, rs1, 2);

        l0 = l0 * c0 + rs0;
        l1 = l1 * c1 + rs1;
        m0 = nm0; m1 = nm1;

#pragma unroll
        for (int n = 0; n < 16; n++) {
            acc_o[n][0] *= c0; acc_o[n][1] *= c0;
            acc_o[n][2] *= c1; acc_o[n][3] *= c1;
        }
        __syncwarp();

        uint32_t pf[8][4];
#pragma unroll
        for (int s = 0; s < 8; s++) {
            const uint32_t* pr0 = Ps + (w * 16 + g) * PSTR + s * 8;
            const uint32_t* pr1 = pr0 + 8 * PSTR;
            pf[s][0] = pr0[t];
            pf[s][1] = pr1[t];
            pf[s][2] = pr0[t + 4];
            pf[s][3] = pr1[t + 4];
        }

        asm volatile("cp.async.wait_group 0;\n");
        __syncthreads();

#pragma unroll
        for (int s = 0; s < 8; s++) {
#pragma unroll
            for (int n = 0; n < 16; n++) {
                uint32_t bf[2];
                bf[0] = f2tf32(Vs[(s * 8 + t) * VSTR + n * 8 + g]);
                bf[1] = f2tf32(Vs[(s * 8 + t + 4) * VSTR + n * 8 + g]);
                mma_tf32(acc_o[n], pf[s], bf);
            }
        }
        __syncthreads();
    }

    float inv0 = __fdividef(1.0f, l0);
    float inv1 = __fdividef(1.0f, l1);
    size_t tok0 = (size_t)(b * Sx + q0 + g);
    size_t tok1 = tok0 + 8;
    float* o0 = o + tok0 * Dx + h * HDx;
    float* o1 = o + tok1 * Dx + h * HDx;
    // tf32-round output: feeds O-projection's raw-bit A path
#pragma unroll
    for (int n = 0; n < 16; n++) {
        int col = n * 8 + 2 * t;
        *(float2*)&o0[col] = make_float2(rnd_tf32(acc_o[n][0] * inv0), rnd_tf32(acc_o[n][1] * inv0));
        *(float2*)&o1[col] = make_float2(rnd_tf32(acc_o[n][2] * inv1), rnd_tf32(acc_o[n][3] * inv1));
    }
}

// ---------------- zero expert counters ----------------
__global__ void zero_cnt_kernel(int* cnt)
{
    if (threadIdx.x < Ex) cnt[threadIdx.x] = 0;
}

// ---------------- MoE gate: top-2 scatter into per-expert lists ----------------
__global__ __launch_bounds__(256) void gate_kernel(
    const float* __restrict__ x, const float* __restrict__ wg,
    int* __restrict__ cnt, int* __restrict__ list, float* __restrict__ wgt)
{
    int warp = threadIdx.x >> 5;
    int lane = threadIdx.x & 31;
    int t = blockIdx.x * 8 + warp;
    const float* xr = x + (size_t)t * Dx;

    float a0 = 0.f, a1 = 0.f, a2 = 0.f, a3 = 0.f;
    for (int d = lane; d < Dx; d += 32) {
        float xv = xr[d];
        float4 w4 = ((const float4*)wg)[d];
        a0 = fmaf(xv, w4.x, a0);
        a1 = fmaf(xv, w4.y, a1);
        a2 = fmaf(xv, w4.z, a2);
        a3 = fmaf(xv, w4.w, a3);
    }
#pragma unroll
    for (int off = 16; off >= 1; off >>= 1) {
        a0 += __shfl_xor_sync(0xffffffffu, a0, off);
        a1 += __shfl_xor_sync(0xffffffffu, a1, off);
        a2 += __shfl_xor_sync(0xffffffffu, a2, off);
        a3 += __shfl_xor_sync(0xffffffffu, a3, off);
    }
    if (lane == 0) {
        float lg[4] = {a0, a1, a2, a3};
        float mx = fmaxf(fmaxf(lg[0], lg[1]), fmaxf(lg[2], lg[3]));
        float e[4], sum = 0.f;
#pragma unroll
        for (int i = 0; i < 4; i++) { e[i] = expf(lg[i] - mx); sum += e[i]; }
        float p[4];
#pragma unroll
        for (int i = 0; i < 4; i++) p[i] = e[i] / sum;

        int i0 = 0;
#pragma unroll
        for (int i = 1; i < 4; i++) if (p[i] > p[i0]) i0 = i;
        int i1 = (i0 == 0) ? 1 : 0;
#pragma unroll
        for (int i = 0; i < 4; i++) if (i != i0 && p[i] > p[i1]) i1 = i;

        float hi = fmaxf(p[i0], p[i1]);
        float ea = expf(p[i0] - hi), eb = expf(p[i1] - hi);
        float inv = 1.0f / (ea + eb);
        float w0 = ea * inv, w1 = eb * inv;

        int s0 = atomicAdd(&cnt[i0], 1);
        list[i0 * Tx + s0] = t;
        wgt [i0 * Tx + s0] = w0;
        int s1 = atomicAdd(&cnt[i1], 1);
        list[i1 * Tx + s1] = t;
        wgt [i1 * Tx + s1] = w1;
    }
}

// ---------------- host launcher ----------------
extern "C" void kernel_launch(void* const* d_in, const int* in_sizes, int n_in,
                              void* d_out, int out_size)
{
    const float* hidden = (const float*)d_in[0];
    const float* wq   = (const float*)d_in[1];
    const float* bq   = (const float*)d_in[2];
    const float* wk   = (const float*)d_in[3];
    const float* bk   = (const float*)d_in[4];
    const float* wv   = (const float*)d_in[5];
    const float* bv   = (const float*)d_in[6];
    const float* wo   = (const float*)d_in[7];
    const float* bo   = (const float*)d_in[8];
    const float* ln1w = (const float*)d_in[9];
    const float* ln1b = (const float*)d_in[10];
    const float* ln2w = (const float*)d_in[11];
    const float* ln2b = (const float*)d_in[12];
    const float* wgate= (const float*)d_in[13];
    const float* we1  = (const float*)d_in[14];
    const float* be1  = (const float*)d_in[15];
    const float* we2  = (const float*)d_in[16];
    const float* be2  = (const float*)d_in[17];
    float* out = (float*)d_out;

    float *x1, *q, *k, *v, *attn, *x2, *hmid, *wgt, *wr;
    int *cnt, *list;
    cudaGetSymbolAddress((void**)&x1,   g_x1);
    cudaGetSymbolAddress((void**)&q,    g_q);
    cudaGetSymbolAddress((void**)&k,    g_k);
    cudaGetSymbolAddress((void**)&v,    g_v);
    cudaGetSymbolAddress((void**)&attn, g_attn);
    cudaGetSymbolAddress((void**)&x2,   g_x2);
    cudaGetSymbolAddress((void**)&hmid, g_hmid);
    cudaGetSymbolAddress((void**)&cnt,  g_cnt);
    cudaGetSymbolAddress((void**)&list, g_list);
    cudaGetSymbolAddress((void**)&wgt,  g_wgt);
    cudaGetSymbolAddress((void**)&wr,   g_wr);

    cudaFuncSetAttribute(gemm_qkv, cudaFuncAttributeMaxDynamicSharedMemorySize, GEMM_SMEM_BYTES);
    cudaFuncSetAttribute(gemm_o,   cudaFuncAttributeMaxDynamicSharedMemorySize, GEMM_SMEM_BYTES);
    cudaFuncSetAttribute(moe_up,   cudaFuncAttributeMaxDynamicSharedMemorySize, GEMM_SMEM_BYTES);
    cudaFuncSetAttribute(moe_dn,   cudaFuncAttributeMaxDynamicSharedMemorySize, GEMM_SMEM_BYTES);
    cudaFuncSetAttribute(fattn_kernel, cudaFuncAttributeMaxDynamicSharedMemorySize, FA_SMEM_BYTES);

    // 0) pre-round all weights to tf32 (one-time per launch, bit-identical to per-fragment cvt)
    round_w_kernel<<<dim3((Dx * Dx) / 1024, 1, 12), 256>>>(wq, wk, wv, wo, we1, we2, wr);
    // 1) LN1 (tf32-rounded)
    ln_kernel<true, false><<<Tx, 256>>>(hidden, ln1w, ln1b, x1, nullptr);
    // 2) fused QKV projections (cvt-free inner loops)
    gemm_qkv<<<dim3(Dx / BN, Tx / BM, 3), 256, GEMM_SMEM_BYTES>>>(
        x1, wr, bq, bk, bv, q, k, v);
    // 3) RoPE
    rope_kernel<<<(Tx * Hx * 64) / 256, 256>>>(q, k);
    // 4) flash attention (descending-qt schedule, tf32-rounded output)
    fattn_kernel<<<dim3(Bx * Hx, Sx / 64), 128, FA_SMEM_BYTES>>>(q, k, v, attn);
    // 5) O-projection + residual
    gemm_o<<<dim3(Dx / BN, Tx / BM), 256, GEMM_SMEM_BYTES>>>(attn, wr + (size_t)3 * Dx * Dx, bo, out, hidden);
    // 6) LN2 dual: x2 full precision (gate), x2r=g_x1 rounded (moe_up A)
    ln_kernel<false, true><<<Tx, 256>>>(out, ln2w, ln2b, x2, x1);
    // 7) gate on full-precision x2
    zero_cnt_kernel<<<1, 32>>>(cnt);
    gate_kernel<<<Tx / 8, 256>>>(x2, wgate, cnt, list, wgt);
    // 8) fused sparse MoE
    moe_up<<<dim3(Ix / BN, Tx / BM, Ex), 256, GEMM_SMEM_BYTES>>>(
        x1, wr, be1, hmid, list, cnt);
    moe_dn<<<dim3(Dx / BN, Tx / BM, Ex), 256, GEMM_SMEM_BYTES>>>(
        hmid, wr, be2, out, list, wgt, cnt);
}

// round 13
// speedup vs baseline: 7.0791x; 1.0141x over previous
#include <cuda_runtime.h>
#include <math.h>
#include <stdint.h>

// ---------------- problem constants ----------------
#define Bx   2
#define Sx   2048
#define Dx   2048
#define Hx   16
#define HDx  128
#define Ex   4
#define Ix   2048
#define Tx   (Bx * Sx)          // 4096 tokens

// ---------------- scratch (static device globals; no runtime alloc) ----------------
__device__ float g_x1  [(size_t)Tx * Dx];        // LN1 out; later reused as x2r
__device__ float g_q   [(size_t)Tx * Dx];
__device__ float g_k   [(size_t)Tx * Dx];
__device__ float g_v   [(size_t)Tx * Dx];
__device__ float g_attn[(size_t)Tx * Dx];
__device__ float g_x2  [(size_t)Tx * Dx];
__device__ float g_hmid[(size_t)Ex * Tx * Ix];   // per-expert compact mid activations
__device__ int   g_cnt [Ex];
__device__ int   g_list[Ex * Tx];
__device__ float g_wgt [Ex * Tx];
__device__ float g_wr  [(size_t)12 * Dx * Dx];   // tf32-pre-rounded weights

__device__ __forceinline__ uint32_t f2tf32(float x) {
    uint32_t u;
    asm volatile("cvt.rna.tf32.f32 %0, %1;\n" : "=r"(u) : "f"(x));
    return u;
}
__device__ __forceinline__ float rnd_tf32(float x) {
    return __uint_as_float(f2tf32(x));
}
__device__ __forceinline__ void mma_tf32(float* d, const uint32_t* a, const uint32_t* b) {
    asm volatile(
        "mma.sync.aligned.m16n8k8.row.col.f32.tf32.tf32.f32 "
        "{%0,%1,%2,%3}, {%4,%5,%6,%7}, {%8,%9}, {%0,%1,%2,%3};\n"
        : "+f"(d[0]), "+f"(d[1]), "+f"(d[2]), "+f"(d[3])
        : "r"(a[0]), "r"(a[1]), "r"(a[2]), "r"(a[3]), "r"(b[0]), "r"(b[1]));
}
__device__ __forceinline__ void cp16(float* dst, const float* src) {
    uint32_t d = (uint32_t)__cvta_generic_to_shared(dst);
    asm volatile("cp.async.cg.shared.global [%0], [%1], 16;\n" :: "r"(d), "l"(src));
}

// ---------------- weight pre-round: 12 matrices -> g_wr (tf32 rna) ----------------
__global__ __launch_bounds__(256) void round_w_kernel(
    const float* __restrict__ wq, const float* __restrict__ wk,
    const float* __restrict__ wv, const float* __restrict__ wo,
    const float* __restrict__ we1, const float* __restrict__ we2,
    float* __restrict__ wr)
{
    int z = blockIdx.z;
    const float* src;
    if      (z == 0) src = wq;
    else if (z == 1) src = wk;
    else if (z == 2) src = wv;
    else if (z == 3) src = wo;
    else if (z < 8)  src = we1 + (size_t)(z - 4) * Dx * Ix;
    else             src = we2 + (size_t)(z - 8) * Ix * Dx;
    float* dst = wr + (size_t)z * Dx * Dx;

    size_t i = ((size_t)blockIdx.x * 256 + threadIdx.x) * 4;
    float4 vv = *(const float4*)(src + i);
    vv.x = rnd_tf32(vv.x); vv.y = rnd_tf32(vv.y);
    vv.z = rnd_tf32(vv.z); vv.w = rnd_tf32(vv.w);
    *(float4*)(dst + i) = vv;
}

// ---------------- LayerNorm ----------------
// ROUND: tf32-round y. DUAL: additionally write rounded copy to y2 (y stays full).
template <bool ROUND, bool DUAL>
__global__ __launch_bounds__(256) void ln_kernel(
    const float* __restrict__ x, const float* __restrict__ w,
    const float* __restrict__ b, float* __restrict__ y, float* __restrict__ y2)
{
    __shared__ float red[8];
    int row = blockIdx.x;
    int t = threadIdx.x;
    const float* xr = x + (size_t)row * Dx;

    float v[8];
    float s = 0.f;
#pragma unroll
    for (int i = 0; i < 8; i++) { v[i] = xr[t + i * 256]; s += v[i]; }
#pragma unroll
    for (int off = 16; off >= 1; off >>= 1) s += __shfl_xor_sync(0xffffffffu, s, off);
    if ((t & 31) == 0) red[t >> 5] = s;
    __syncthreads();
    float tot = red[0] + red[1] + red[2] + red[3] + red[4] + red[5] + red[6] + red[7];
    float mu = tot * (1.0f / (float)Dx);

    float s2 = 0.f;
#pragma unroll
    for (int i = 0; i < 8; i++) { float d = v[i] - mu; s2 += d * d; }
    __syncthreads();
#pragma unroll
    for (int off = 16; off >= 1; off >>= 1) s2 += __shfl_xor_sync(0xffffffffu, s2, off);
    if ((t & 31) == 0) red[t >> 5] = s2;
    __syncthreads();
    float tot2 = red[0] + red[1] + red[2] + red[3] + red[4] + red[5] + red[6] + red[7];
    float var = tot2 * (1.0f / (float)Dx);
    float r = rsqrtf(var + 1e-5f);

    float* yr = y + (size_t)row * Dx;
    float* yr2 = DUAL ? (y2 + (size_t)row * Dx) : nullptr;
#pragma unroll
    for (int i = 0; i < 8; i++) {
        int c = t + i * 256;
        float val = (v[i] - mu) * r * w[c] + b[c];
        yr[c] = ROUND ? rnd_tf32(val) : val;
        if (DUAL) yr2[c] = rnd_tf32(val);
    }
}

// ================= shared tf32 mma.sync GEMM body (cvt-free inner loop) =================
// All A/B inputs are pre-rounded to tf32 in gmem; fragments feed raw bits.
// MODE 0: C = AB + bias
// MODE 1: C = AB + bias + extra (residual [M,N])
// MODE 2: A rows gathered via gidx; C = rnd_tf32(gelu(AB+bias)), compact rows
// MODE 3: A compact; atomicAdd(C[gidx[m]], gw[m]*(AB+bias))
#define BM 128
#define BN 128
#define BK 32
#define APAD 4
#define BPAD 8
#define ASZ (BM * (BK + APAD))
#define BSZ (BK * (BN + BPAD))
#define GEMM_SMEM_BYTES ((2 * ASZ + 2 * BSZ) * 4)   // 71680

template <int MODE>
__device__ __forceinline__ void gemm_body(
    float* sm, const float* A, const float* B,
    const float* bias, float* C, const float* extra,
    const int* gidx, const float* gw, int cnt,
    int N, int K, int m0, int n0)
{
    float* As0 = sm;
    float* Bs0 = sm + 2 * ASZ;

    const int tid  = threadIdx.x;
    const int lane = tid & 31;
    const int wid  = tid >> 5;
    const int g = lane >> 2;
    const int t = lane & 3;
    const int wm = wid >> 2;
    const int wn = wid & 3;

    float acc[4][4][4];
#pragma unroll
    for (int i = 0; i < 4; i++)
#pragma unroll
        for (int j = 0; j < 4; j++)
#pragma unroll
            for (int c = 0; c < 4; c++) acc[i][j][c] = 0.f;

    int asrc[4];
#pragma unroll
    for (int u = 0; u < 4; u++) {
        int gr = m0 + (tid >> 3) + 32 * u;
        if (gr >= cnt) gr = cnt - 1;
        asrc[u] = (MODE == 2) ? gidx[gr] : gr;
    }

    auto loadTile = [&](int k0, int buf) {
        float* Ad = As0 + buf * ASZ;
        float* Bd = Bs0 + buf * BSZ;
#pragma unroll
        for (int i = 0; i < 4; i++) {
            int row = (tid >> 3) + 32 * i;
            int kq  = (tid & 7) * 4;
            cp16(Ad + row * (BK + APAD) + kq,
                 A + (size_t)asrc[i] * K + k0 + kq);
        }
#pragma unroll
        for (int i = 0; i < 4; i++) {
            int f = tid + i * 256;
            int kr = f >> 5;
            int nc = (f & 31) * 4;
            cp16(Bd + kr * (BN + BPAD) + nc,
                 B + (size_t)(k0 + kr) * N + n0 + nc);
        }
        asm volatile("cp.async.commit_group;\n");
    };

    const int ntiles = K / BK;
    loadTile(0, 0);

    for (int tile = 0; tile < ntiles; tile++) {
        int buf = tile & 1;
        if (tile + 1 < ntiles) {
            loadTile((tile + 1) * BK, buf ^ 1);
            asm volatile("cp.async.wait_group 1;\n");
        } else {
            asm volatile("cp.async.wait_group 0;\n");
        }
        __syncthreads();

        const float* Ab = As0 + buf * ASZ;
        const float* Bb = Bs0 + buf * BSZ;

#pragma unroll
        for (int kk = 0; kk < BK / 8; kk++) {
            const int k = kk * 8;
            uint32_t af[4][4];
            uint32_t bf[4][2];
#pragma unroll
            for (int mi = 0; mi < 4; mi++) {
                int r = wm * 64 + mi * 16 + g;
                const float* ar0 = Ab + (size_t)r * (BK + APAD) + k;
                const float* ar1 = ar0 + 8 * (BK + APAD);
                af[mi][0] = __float_as_uint(ar0[t]);
                af[mi][1] = __float_as_uint(ar1[t]);
                af[mi][2] = __float_as_uint(ar0[t + 4]);
                af[mi][3] = __float_as_uint(ar1[t + 4]);
            }
#pragma unroll
            for (int ni = 0; ni < 4; ni++) {
                int c = wn * 32 + ni * 8 + g;
                bf[ni][0] = __float_as_uint(Bb[(size_t)(k + t) * (BN + BPAD) + c]);
                bf[ni][1] = __float_as_uint(Bb[(size_t)(k + t + 4) * (BN + BPAD) + c]);
            }
#pragma unroll
            for (int mi = 0; mi < 4; mi++)
#pragma unroll
                for (int ni = 0; ni < 4; ni++)
                    mma_tf32(acc[mi][ni], af[mi], bf[ni]);
        }
        __syncthreads();
    }

#pragma unroll
    for (int mi = 0; mi < 4; mi++) {
        int r0 = m0 + wm * 64 + mi * 16 + g;
        int r1 = r0 + 8;
        bool v0 = r0 < cnt, v1 = r1 < cnt;
        int d0 = 0, d1 = 0;
        float s0 = 0.f, s1 = 0.f;
        if (MODE == 3) {
            if (v0) { d0 = gidx[r0]; s0 = gw[r0]; }
            if (v1) { d1 = gidx[r1]; s1 = gw[r1]; }
        }
#pragma unroll
        for (int ni = 0; ni < 4; ni++) {
            int c = n0 + wn * 32 + ni * 8 + t * 2;
            float2 b2 = *(const float2*)&bias[c];
            float v00 = acc[mi][ni][0] + b2.x;
            float v01 = acc[mi][ni][1] + b2.y;
            float v10 = acc[mi][ni][2] + b2.x;
            float v11 = acc[mi][ni][3] + b2.y;
            if (MODE == 0 || MODE == 1) {
                if (MODE == 1) {
                    float2 e0 = *(const float2*)&extra[(size_t)r0 * N + c];
                    float2 e1 = *(const float2*)&extra[(size_t)r1 * N + c];
                    v00 += e0.x; v01 += e0.y;
                    v10 += e1.x; v11 += e1.y;
                }
                *(float2*)&C[(size_t)r0 * N + c] = make_float2(v00, v01);
                *(float2*)&C[(size_t)r1 * N + c] = make_float2(v10, v11);
            } else if (MODE == 2) {
                v00 = rnd_tf32(0.5f * v00 * (1.0f + erff(v00 * 0.70710678118654752f)));
                v01 = rnd_tf32(0.5f * v01 * (1.0f + erff(v01 * 0.70710678118654752f)));
                v10 = rnd_tf32(0.5f * v10 * (1.0f + erff(v10 * 0.70710678118654752f)));
                v11 = rnd_tf32(0.5f * v11 * (1.0f + erff(v11 * 0.70710678118654752f)));
                if (v0) *(float2*)&C[(size_t)r0 * N + c] = make_float2(v00, v01);
                if (v1) *(float2*)&C[(size_t)r1 * N + c] = make_float2(v10, v11);
            } else {
                if (v0) {
                    atomicAdd(&C[(size_t)d0 * N + c],     s0 * v00);
                    atomicAdd(&C[(size_t)d0 * N + c + 1], s0 * v01);
                }
                if (v1) {
                    atomicAdd(&C[(size_t)d1 * N + c],     s1 * v10);
                    atomicAdd(&C[(size_t)d1 * N + c + 1], s1 * v11);
                }
            }
        }
    }
}

// ---------------- fused QKV: blockIdx.z selects projection ----------------
__global__ __launch_bounds__(256, 2) void gemm_qkv(
    const float* __restrict__ A, const float* __restrict__ wr,
    const float* __restrict__ bq, const float* __restrict__ bk, const float* __restrict__ bv,
    float* __restrict__ Cq, float* __restrict__ Ck, float* __restrict__ Cv)
{
    extern __shared__ float sm[];
    int z = blockIdx.z;
    const float* B = wr + (size_t)z * Dx * Dx;
    const float* bb = (z == 0) ? bq : (z == 1) ? bk : bv;
    float* C = (z == 0) ? Cq : (z == 1) ? Ck : Cv;
    gemm_body<0>(sm, A, B, bb, C, nullptr, nullptr, nullptr,
                 Tx, Dx, Dx, blockIdx.y * BM, blockIdx.x * BN);
}

// ---------------- O-projection + residual ----------------
__global__ __launch_bounds__(256, 2) void gemm_o(
    const float* __restrict__ A, const float* __restrict__ B,
    const float* __restrict__ bias, float* __restrict__ C,
    const float* __restrict__ extra)
{
    extern __shared__ float sm[];
    gemm_body<1>(sm, A, B, bias, C, extra, nullptr, nullptr,
                 Tx, Dx, Dx, blockIdx.y * BM, blockIdx.x * BN);
}

// ---------------- fused MoE up: blockIdx.z = expert ----------------
__global__ __launch_bounds__(256, 2) void moe_up(
    const float* __restrict__ x2r, const float* __restrict__ wr,
    const float* __restrict__ be1, float* __restrict__ hmid,
    const int* __restrict__ list, const int* __restrict__ cnt)
{
    extern __shared__ float sm[];
    int z = blockIdx.z;
    int c = cnt[z];
    int m0 = blockIdx.y * BM;
    if (m0 >= c) return;
    gemm_body<2>(sm,
        x2r, wr + (size_t)(4 + z) * Dx * Dx, be1 + (size_t)z * Ix,
        hmid + (size_t)z * Tx * Ix,
        nullptr, list + z * Tx, nullptr, c,
        Ix, Dx, m0, blockIdx.x * BN);
}

// ---------------- fused MoE down: blockIdx.z = expert, atomic scatter ----------------
__global__ __launch_bounds__(256, 2) void moe_dn(
    const float* __restrict__ hmid, const float* __restrict__ wr,
    const float* __restrict__ be2, float* __restrict__ out,
    const int* __restrict__ list, const float* __restrict__ wgt,
    const int* __restrict__ cnt)
{
    extern __shared__ float sm[];
    int z = blockIdx.z;
    int c = cnt[z];
    int m0 = blockIdx.y * BM;
    if (m0 >= c) return;
    gemm_body<3>(sm,
        hmid + (size_t)z * Tx * Ix, wr + (size_t)(8 + z) * Dx * Dx,
        be2 + (size_t)z * Dx, out,
        nullptr, list + z * Tx, wgt + z * Tx, c,
        Dx, Ix, m0, blockIdx.x * BN);
}

// ---------------- RoPE (+ tf32-round K and V at the writer) ----------------
__global__ __launch_bounds__(256) void rope_kernel(
    float* __restrict__ q, float* __restrict__ k, float* __restrict__ v)
{
    int idx = blockIdx.x * 256 + threadIdx.x;
    int d = idx & 63;
    int rest = idx >> 6;
    int h = rest & (Hx - 1);
    int tok = rest >> 4;
    int s = tok & (Sx - 1);

    float freq = expf(-(float)d * (9.21034037197618f / 64.0f));
    float ang = (float)s * freq;
    float c, sn;
    sincosf(ang, &sn, &c);

    size_t base = (size_t)tok * Dx + h * HDx;
    float q1 = q[base + d], q2 = q[base + d + 64];
    q[base + d]      = q1 * c - q2 * sn;        // q stays full precision (fattn scales+cvts)
    q[base + d + 64] = q2 * c + q1 * sn;
    float k1 = k[base + d], k2 = k[base + d + 64];
    k[base + d]      = rnd_tf32(k1 * c - k2 * sn);   // pre-rounded: fattn feeds raw bits
    k[base + d + 64] = rnd_tf32(k2 * c + k1 * sn);
    v[base + d]      = rnd_tf32(v[base + d]);
    v[base + d + 64] = rnd_tf32(v[base + d + 64]);
}

// ================= tensor-core flash attention (cvt-free K/V fragments) =================
#define KSTR 132
#define VSTR 136
#define PSTR 68
#define FA_SMEM_BYTES ((64 * KSTR + 64 * VSTR + 4 * 16 * PSTR) * 4)   // 86016

__global__ __launch_bounds__(128) void fattn_kernel(
    const float* __restrict__ q, const float* __restrict__ k,
    const float* __restrict__ v, float* __restrict__ o)
{
    extern __shared__ float fs[];
    float* Ks = fs;
    float* Vs = fs + 64 * KSTR;
    uint32_t* Ps = (uint32_t*)(fs + 64 * KSTR + 64 * VSTR);

    const int bh = blockIdx.x;
    const int b = bh >> 4;
    const int h = bh & (Hx - 1);
    const int qt = gridDim.y - 1 - blockIdx.y;   // longest tiles scheduled first
    const int tid = threadIdx.x;
    const int lane = tid & 31;
    const int w = tid >> 5;
    const int g = lane >> 2;
    const int t = lane & 3;

    const float* Qg = q + ((size_t)(b * Sx + qt * 64)) * Dx + h * HDx;
    const float* Kg = k + ((size_t)b * Sx) * Dx + h * HDx;
    const float* Vg = v + ((size_t)b * Sx) * Dx + h * HDx;

    for (int i = tid; i < 64 * 32; i += 128) {
        int r = i >> 5, c4 = (i & 31) * 4;
        *(float4*)&Ks[r * KSTR + c4] = *(const float4*)(Qg + (size_t)r * Dx + c4);
    }
    __syncthreads();

    const float qscale = 0.08838834764831843f;
    uint32_t qf[16][4];
#pragma unroll
    for (int s = 0; s < 16; s++) {
        const float* r0 = &Ks[(w * 16 + g) * KSTR + s * 8];
        const float* r1 = r0 + 8 * KSTR;
        qf[s][0] = f2tf32(r0[t] * qscale);
        qf[s][1] = f2tf32(r1[t] * qscale);
        qf[s][2] = f2tf32(r0[t + 4] * qscale);
        qf[s][3] = f2tf32(r1[t + 4] * qscale);
    }
    __syncthreads();

    float acc_o[16][4];
#pragma unroll
    for (int n = 0; n < 16; n++)
#pragma unroll
        for (int c = 0; c < 4; c++) acc_o[n][c] = 0.f;

    float m0 = -1e30f, m1 = -1e30f, l0 = 0.f, l1 = 0.f;
    const int q0 = qt * 64 + w * 16;

    for (int kt = 0; kt <= qt; kt++) {
#pragma unroll
        for (int i = 0; i < 16; i++) {
            int f = tid + i * 128;
            int r = f >> 5, c4 = (f & 31) * 4;
            cp16(&Ks[r * KSTR + c4], Kg + (size_t)(kt * 64 + r) * Dx + c4);
        }
        asm volatile("cp.async.commit_group;\n");
#pragma unroll
        for (int i = 0; i < 16; i++) {
            int f = tid + i * 128;
            int r = f >> 5, c4 = (f & 31) * 4;
            cp16(&Vs[r * VSTR + c4], Vg + (size_t)(kt * 64 + r) * Dx + c4);
        }
        asm volatile("cp.async.commit_group;\n");
        asm volatile("cp.async.wait_group 1;\n");
        __syncthreads();

        float sacc[8][4];
#pragma unroll
        for (int n = 0; n < 8; n++)
#pragma unroll
            for (int c = 0; c < 4; c++) sacc[n][c] = 0.f;

#pragma unroll
        for (int s = 0; s < 16; s++) {
#pragma unroll
            for (int n = 0; n < 8; n++) {
                uint32_t bf[2];
                const float* kr = &Ks[(n * 8 + g) * KSTR + s * 8];
                bf[0] = __float_as_uint(kr[t]);
                bf[1] = __float_as_uint(kr[t + 4]);
                mma_tf32(sacc[n], qf[s], bf);
            }
        }

        if (kt == qt) {
#pragma unroll
            for (int n = 0; n < 8; n++) {
                int key = kt * 64 + n * 8 + 2 * t;
                if (key     > q0 + g)     sacc[n][0] = -1e30f;
                if (key + 1 > q0 + g)     sacc[n][1] = -1e30f;
                if (key     > q0 + g + 8) sacc[n][2] = -1e30f;
                if (key + 1 > q0 + g + 8) sacc[n][3] = -1e30f;
            }
        }

        float rm0 = -1e30f, rm1 = -1e30f;
#pragma unroll
        for (int n = 0; n < 8; n++) {
            rm0 = fmaxf(rm0, fmaxf(sacc[n][0], sacc[n][1]));
            rm1 = fmaxf(rm1, fmaxf(sacc[n][2], sacc[n][3]));
        }
        rm0 = fmaxf(rm0, __shfl_xor_sync(0xffffffffu, rm0, 1));
        rm0 = fmaxf(rm0, __shfl_xor_sync(0xffffffffu, rm0, 2));
        rm1 = fmaxf(rm1, __shfl_xor_sync(0xffffffffu, rm1, 1));
        rm1 = fmaxf(rm1, __shfl_xor_sync(0xffffffffu, rm1, 2));

        float nm0 = fmaxf(m0, rm0), nm1 = fmaxf(m1, rm1);
        float c0 = __expf(m0 - nm0), c1 = __expf(m1 - nm1);

        uint32_t* pw = Ps + (w * 16 + g) * PSTR;
        float rs0 = 0.f, rs1 = 0.f;
#pragma unroll
        for (int n = 0; n < 8; n++) {
            float p00 = __expf(sacc[n][0] - nm0);
            float p01 = __expf(sacc[n][1] - nm0);
            float p10 = __expf(sacc[n][2] - nm1);
            float p11 = __expf(sacc[n][3] - nm1);
            rs0 += p00 + p01;
            rs1 += p10 + p11;
            uint2 u0 = make_uint2(f2tf32(p00), f2tf32(p01));
            uint2 u1 = make_uint2(f2tf32(p10), f2tf32(p11));
            *(uint2*)&pw[n * 8 + 2 * t]            = u0;
            *(uint2*)&pw[8 * PSTR + n * 8 + 2 * t] = u1;
        }
        rs0 += __shfl_xor_sync(0xffffffffu, rs0, 1);
        rs0 += __shfl_xor_sync(0xffffffffu, rs0, 2);
        rs1 += __shfl_xor_sync(0xffffffffu, rs1, 1);
        rs1 += __shfl_xor_sync(0xffffffffu, rs1, 2);

        l0 = l0 * c0 + rs0;
        l1 = l1 * c1 + rs1;
        m0 = nm0; m1 = nm1;

#pragma unroll
        for (int n = 0; n < 16; n++) {
            acc_o[n][0] *= c0; acc_o[n][1] *= c0;
            acc_o[n][2] *= c1; acc_o[n][3] *= c1;
        }
        __syncwarp();

        uint32_t pf[8][4];
#pragma unroll
        for (int s = 0; s < 8; s++) {
            const uint32_t* pr0 = Ps + (w * 16 + g) * PSTR + s * 8;
            const uint32_t* pr1 = pr0 + 8 * PSTR;
            pf[s][0] = pr0[t];
            pf[s][1] = pr1[t];
            pf[s][2] = pr0[t + 4];
            pf[s][3] = pr1[t + 4];
        }

        asm volatile("cp.async.wait_group 0;\n");
        __syncthreads();

#pragma unroll
        for (int s = 0; s < 8; s++) {
#pragma unroll
            for (int n = 0; n < 16; n++) {
                uint32_t bf[2];
                bf[0] = __float_as_uint(Vs[(s * 8 + t) * VSTR + n * 8 + g]);
                bf[1] = __float_as_uint(Vs[(s * 8 + t + 4) * VSTR + n * 8 + g]);
                mma_tf32(acc_o[n], pf[s], bf);
            }
        }
        __syncthreads();
    }

    float inv0 = __fdividef(1.0f, l0);
    float inv1 = __fdividef(1.0f, l1);
    size_t tok0 = (size_t)(b * Sx + q0 + g);
    size_t tok1 = tok0 + 8;
    float* o0 = o + tok0 * Dx + h * HDx;
    float* o1 = o + tok1 * Dx + h * HDx;
    // tf32-round output: feeds O-projection's raw-bit A path
#pragma unroll
    for (int n = 0; n < 16; n++) {
        int col = n * 8 + 2 * t;
        *(float2*)&o0[col] = make_float2(rnd_tf32(acc_o[n][0] * inv0), rnd_tf32(acc_o[n][1] * inv0));
        *(float2*)&o1[col] = make_float2(rnd_tf32(acc_o[n][2] * inv1), rnd_tf32(acc_o[n][3] * inv1));
    }
}

// ---------------- zero expert counters ----------------
__global__ void zero_cnt_kernel(int* cnt)
{
    if (threadIdx.x < Ex) cnt[threadIdx.x] = 0;
}

// ---------------- MoE gate: top-2 scatter into per-expert lists ----------------
__global__ __launch_bounds__(256) void gate_kernel(
    const float* __restrict__ x, const float* __restrict__ wg,
    int* __restrict__ cnt, int* __restrict__ list, float* __restrict__ wgt)
{
    int warp = threadIdx.x >> 5;
    int lane = threadIdx.x & 31;
    int t = blockIdx.x * 8 + warp;
    const float* xr = x + (size_t)t * Dx;

    float a0 = 0.f, a1 = 0.f, a2 = 0.f, a3 = 0.f;
    for (int d = lane; d < Dx; d += 32) {
        float xv = xr[d];
        float4 w4 = ((const float4*)wg)[d];
        a0 = fmaf(xv, w4.x, a0);
        a1 = fmaf(xv, w4.y, a1);
        a2 = fmaf(xv, w4.z, a2);
        a3 = fmaf(xv, w4.w, a3);
    }
#pragma unroll
    for (int off = 16; off >= 1; off >>= 1) {
        a0 += __shfl_xor_sync(0xffffffffu, a0, off);
        a1 += __shfl_xor_sync(0xffffffffu, a1, off);
        a2 += __shfl_xor_sync(0xffffffffu, a2, off);
        a3 += __shfl_xor_sync(0xffffffffu, a3, off);
    }
    if (lane == 0) {
        float lg[4] = {a0, a1, a2, a3};
        float mx = fmaxf(fmaxf(lg[0], lg[1]), fmaxf(lg[2], lg[3]));
        float e[4], sum = 0.f;
#pragma unroll
        for (int i = 0; i < 4; i++) { e[i] = expf(lg[i] - mx); sum += e[i]; }
        float p[4];
#pragma unroll
        for (int i = 0; i < 4; i++) p[i] = e[i] / sum;

        int i0 = 0;
#pragma unroll
        for (int i = 1; i < 4; i++) if (p[i] > p[i0]) i0 = i;
        int i1 = (i0 == 0) ? 1 : 0;
#pragma unroll
        for (int i = 0; i < 4; i++) if (i != i0 && p[i] > p[i1]) i1 = i;

        float hi = fmaxf(p[i0], p[i1]);
        float ea = expf(p[i0] - hi), eb = expf(p[i1] - hi);
        float inv = 1.0f / (ea + eb);
        float w0 = ea * inv, w1 = eb * inv;

        int s0 = atomicAdd(&cnt[i0], 1);
        list[i0 * Tx + s0] = t;
        wgt [i0 * Tx + s0] = w0;
        int s1 = atomicAdd(&cnt[i1], 1);
        list[i1 * Tx + s1] = t;
        wgt [i1 * Tx + s1] = w1;
    }
}

// ---------------- host launcher ----------------
extern "C" void kernel_launch(void* const* d_in, const int* in_sizes, int n_in,
                              void* d_out, int out_size)
{
    const float* hidden = (const float*)d_in[0];
    const float* wq   = (const float*)d_in[1];
    const float* bq   = (const float*)d_in[2];
    const float* wk   = (const float*)d_in[3];
    const float* bk   = (const float*)d_in[4];
    const float* wv   = (const float*)d_in[5];
    const float* bv   = (const float*)d_in[6];
    const float* wo   = (const float*)d_in[7];
    const float* bo   = (const float*)d_in[8];
    const float* ln1w = (const float*)d_in[9];
    const float* ln1b = (const float*)d_in[10];
    const float* ln2w = (const float*)d_in[11];
    const float* ln2b = (const float*)d_in[12];
    const float* wgate= (const float*)d_in[13];
    const float* we1  = (const float*)d_in[14];
    const float* be1  = (const float*)d_in[15];
    const float* we2  = (const float*)d_in[16];
    const float* be2  = (const float*)d_in[17];
    float* out = (float*)d_out;

    float *x1, *q, *k, *v, *attn, *x2, *hmid, *wgt, *wr;
    int *cnt, *list;
    cudaGetSymbolAddress((void**)&x1,   g_x1);
    cudaGetSymbolAddress((void**)&q,    g_q);
    cudaGetSymbolAddress((void**)&k,    g_k);
    cudaGetSymbolAddress((void**)&v,    g_v);
    cudaGetSymbolAddress((void**)&attn, g_attn);
    cudaGetSymbolAddress((void**)&x2,   g_x2);
    cudaGetSymbolAddress((void**)&hmid, g_hmid);
    cudaGetSymbolAddress((void**)&cnt,  g_cnt);
    cudaGetSymbolAddress((void**)&list, g_list);
    cudaGetSymbolAddress((void**)&wgt,  g_wgt);
    cudaGetSymbolAddress((void**)&wr,   g_wr);

    cudaFuncSetAttribute(gemm_qkv, cudaFuncAttributeMaxDynamicSharedMemorySize, GEMM_SMEM_BYTES);
    cudaFuncSetAttribute(gemm_o,   cudaFuncAttributeMaxDynamicSharedMemorySize, GEMM_SMEM_BYTES);
    cudaFuncSetAttribute(moe_up,   cudaFuncAttributeMaxDynamicSharedMemorySize, GEMM_SMEM_BYTES);
    cudaFuncSetAttribute(moe_dn,   cudaFuncAttributeMaxDynamicSharedMemorySize, GEMM_SMEM_BYTES);
    cudaFuncSetAttribute(fattn_kernel, cudaFuncAttributeMaxDynamicSharedMemorySize, FA_SMEM_BYTES);

    // 0) pre-round all weights to tf32 (one-time per launch)
    round_w_kernel<<<dim3((Dx * Dx) / 1024, 1, 12), 256>>>(wq, wk, wv, wo, we1, we2, wr);
    // 1) LN1 (tf32-rounded)
    ln_kernel<true, false><<<Tx, 256>>>(hidden, ln1w, ln1b, x1, nullptr);
    // 2) fused QKV projections (cvt-free inner loops)
    gemm_qkv<<<dim3(Dx / BN, Tx / BM, 3), 256, GEMM_SMEM_BYTES>>>(
        x1, wr, bq, bk, bv, q, k, v);
    // 3) RoPE + pre-round K/V for fattn's raw-bit fragments
    rope_kernel<<<(Tx * Hx * 64) / 256, 256>>>(q, k, v);
    // 4) flash attention (cvt-free K/V, descending-qt schedule)
    fattn_kernel<<<dim3(Bx * Hx, Sx / 64), 128, FA_SMEM_BYTES>>>(q, k, v, attn);
    // 5) O-projection + residual
    gemm_o<<<dim3(Dx / BN, Tx / BM), 256, GEMM_SMEM_BYTES>>>(attn, wr + (size_t)3 * Dx * Dx, bo, out, hidden);
    // 6) LN2 dual: x2 full precision (gate), x2r=g_x1 rounded (moe_up A)
    ln_kernel<false, true><<<Tx, 256>>>(out, ln2w, ln2b, x2, x1);
    // 7) gate on full-precision x2
    zero_cnt_kernel<<<1, 32>>>(cnt);
    gate_kernel<<<Tx / 8, 256>>>(x2, wgate, cnt, list, wgt);
    // 8) fused sparse MoE
    moe_up<<<dim3(Ix / BN, Tx / BM, Ex), 256, GEMM_SMEM_BYTES>>>(
        x1, wr, be1, hmid, list, cnt);
    moe_dn<<<dim3(Dx / BN, Tx / BM, Ex), 256, GEMM_SMEM_BYTES>>>(
        hmid, wr, be2, out, list, wgt, cnt);
}